// round 4
// baseline (speedup 1.0000x reference)
#include <cuda_runtime.h>
#include <math.h>

#define B_SZ 2
#define SEQ  1024
#define DM   1024
#define DI   2048
#define DS   16
#define DFF  4096
#define MTOK (B_SZ*SEQ)

// ---------------- scratch (device globals; allocation-free) ----------------
__device__ float g_xn   [MTOK*DM];        // 8 MB
__device__ float g_xg   [MTOK*2*DI];      // 32 MB  (x_proj | gate)
__device__ float g_xc   [MTOK*DI];        // 16 MB
__device__ float g_delta[MTOK*DI];        // 16 MB
__device__ float g_Bm   [67108864];       // 256 MB  MTOK*DI*DS
__device__ float g_Cm   [67108864];       // 256 MB
__device__ float g_y    [MTOK*DI];        // 16 MB
__device__ float g_x2   [MTOK*DM];        // 8 MB
__device__ float g_xn2  [MTOK*DM];        // 8 MB
__device__ float g_h1   [MTOK*DFF];       // 32 MB

// ---------------- LayerNorm: one block per row of 1024 ----------------
__global__ __launch_bounds__(256)
void ln_kernel(const float* __restrict__ in, const float* __restrict__ g,
               const float* __restrict__ bcoef, float* __restrict__ out)
{
    int row = blockIdx.x;
    int tid = threadIdx.x;                        // 256 threads, 4 floats each
    float4 v = ((const float4*)(in + (size_t)row*DM))[tid];

    __shared__ float red1[8];
    __shared__ float red2[8];

    float s = v.x + v.y + v.z + v.w;
    #pragma unroll
    for (int o = 16; o > 0; o >>= 1) s += __shfl_xor_sync(0xffffffffu, s, o);
    if ((tid & 31) == 0) red1[tid >> 5] = s;
    __syncthreads();
    float tot = 0.f;
    #pragma unroll
    for (int i = 0; i < 8; i++) tot += red1[i];
    float mean = tot * (1.0f / DM);

    float dx = v.x - mean, dy = v.y - mean, dz = v.z - mean, dw = v.w - mean;
    float sq = dx*dx + dy*dy + dz*dz + dw*dw;
    #pragma unroll
    for (int o = 16; o > 0; o >>= 1) sq += __shfl_xor_sync(0xffffffffu, sq, o);
    if ((tid & 31) == 0) red2[tid >> 5] = sq;
    __syncthreads();
    float tot2 = 0.f;
    #pragma unroll
    for (int i = 0; i < 8; i++) tot2 += red2[i];
    float rstd = rsqrtf(tot2 * (1.0f / DM) + 1e-5f);

    float4 gg = ((const float4*)g)[tid];
    float4 bb = ((const float4*)bcoef)[tid];
    float4 o4;
    o4.x = dx * rstd * gg.x + bb.x;
    o4.y = dy * rstd * gg.y + bb.y;
    o4.z = dz * rstd * gg.z + bb.z;
    o4.w = dw * rstd * gg.w + bb.w;
    ((float4*)(out + (size_t)row*DM))[tid] = o4;
}

// ---------------- SGEMM: C[M,N] = A[M,K] @ W[K,N], fused epilogue ----------------
// EPI: 0 = +bias ; 1 = delta = sigmoid(+bias)*0.099+0.001 ; 2 = gelu(+bias, exact) ;
//      3 = +bias + add[r*N+c]
template<int EPI>
__global__ __launch_bounds__(256)
void sgemm(int M, int N, int K,
           const float* __restrict__ A, const float* __restrict__ Bw,
           const float* __restrict__ bias, const float* __restrict__ add,
           float* __restrict__ C)
{
    const int BM = 128, BN = 128, BK = 8, TM = 8, TN = 8;
    __shared__ float As[BK][BM];
    __shared__ float Bs[BK][BN];

    int tid  = threadIdx.x;
    int crow = blockIdx.y * BM;
    int ccol = blockIdx.x * BN;

    int arow = tid >> 1;              // 0..127
    int acol = (tid & 1) * 4;         // 0 or 4
    int brow = tid >> 5;              // 0..7
    int bcol = (tid & 31) * 4;        // 0..124

    const float* Ab = A  + (size_t)crow * K;
    const float* Bb = Bw + ccol;

    float acc[TM][TN] = {};
    float ra[TM], rb[TN];
    int ty = tid >> 4, tx = tid & 15;

    for (int k0 = 0; k0 < K; k0 += BK) {
        float4 av = *(const float4*)(Ab + (size_t)arow * K + k0 + acol);
        As[acol + 0][arow] = av.x;
        As[acol + 1][arow] = av.y;
        As[acol + 2][arow] = av.z;
        As[acol + 3][arow] = av.w;
        float4 bv = *(const float4*)(Bb + (size_t)(k0 + brow) * N + bcol);
        *(float4*)(&Bs[brow][bcol]) = bv;
        __syncthreads();

        #pragma unroll
        for (int k = 0; k < BK; ++k) {
            #pragma unroll
            for (int i = 0; i < TM; i += 4) *(float4*)(ra + i) = *(const float4*)(&As[k][ty*TM + i]);
            #pragma unroll
            for (int j = 0; j < TN; j += 4) *(float4*)(rb + j) = *(const float4*)(&Bs[k][tx*TN + j]);
            #pragma unroll
            for (int i = 0; i < TM; i++)
                #pragma unroll
                for (int j = 0; j < TN; j++)
                    acc[i][j] += ra[i] * rb[j];
        }
        __syncthreads();
    }

    #pragma unroll
    for (int i = 0; i < TM; i++) {
        int r = crow + ty*TM + i;
        #pragma unroll
        for (int j = 0; j < TN; j += 4) {
            int c = ccol + tx*TN + j;
            float4 o;
            float vv[4];
            #pragma unroll
            for (int q = 0; q < 4; q++) {
                float v = acc[i][j+q] + bias[c+q];
                if (EPI == 1) v = 1.0f/(1.0f + expf(-v)) * 0.099f + 0.001f;
                if (EPI == 2) v = 0.5f * v * (1.0f + erff(v * 0.70710678118654752f));
                if (EPI == 3) v += add[(size_t)r * N + c + q];
                vv[q] = v;
            }
            o.x = vv[0]; o.y = vv[1]; o.z = vv[2]; o.w = vv[3];
            *(float4*)(&C[(size_t)r * N + c]) = o;
        }
    }
}

// ---------------- causal depthwise conv (taps=4) ----------------
__global__ __launch_bounds__(256)
void conv_kernel(const float* __restrict__ xg, const float* __restrict__ cw,
                 const float* __restrict__ cb, float* __restrict__ xc)
{
    int idx   = blockIdx.x * blockDim.x + threadIdx.x;   // over MTOK*DI
    int d     = idx & (DI - 1);
    int token = idx >> 11;
    int t     = token & (SEQ - 1);
    float acc = cb[d];
    #pragma unroll
    for (int k = 0; k < 4; k++) {
        int ts = t - 3 + k;
        if (ts >= 0) acc += xg[(size_t)(token - 3 + k) * (2*DI) + d] * cw[d*4 + k];
    }
    xc[idx] = acc;
}

// ---------------- selective scan: one thread per (b,d,n) ----------------
__global__ __launch_bounds__(256)
void scan_kernel(const float* __restrict__ xg, const float* __restrict__ delta,
                 const float* __restrict__ Bm, const float* __restrict__ Cm,
                 const float* __restrict__ A_log, const float* __restrict__ Dp,
                 float* __restrict__ y)
{
    int tid = blockIdx.x * blockDim.x + threadIdx.x;     // 65536
    int n = tid & (DS - 1);
    int d = (tid >> 4) & (DI - 1);
    int b = tid >> 15;

    float Aneg = -expf(A_log[d*DS + n]);
    float Dval = Dp[d];
    float h = 0.f;
    int base_tok = b * SEQ;

    for (int t = 0; t < SEQ; ++t) {
        int token = base_tok + t;
        float dv = delta[(size_t)token * DI + d];
        float xp = xg[(size_t)token * (2*DI) + d];
        float bm = Bm[(size_t)token * (DI*DS) + d*DS + n];
        float cm = Cm[(size_t)token * (DI*DS) + d*DS + n];
        float a  = __expf(dv * Aneg);
        h = a * h + (dv * bm) * xp;
        float yv = cm * h;
        yv += __shfl_xor_sync(0xffffffffu, yv, 1);
        yv += __shfl_xor_sync(0xffffffffu, yv, 2);
        yv += __shfl_xor_sync(0xffffffffu, yv, 4);
        yv += __shfl_xor_sync(0xffffffffu, yv, 8);
        if (n == 0) {
            float g  = xg[(size_t)token * (2*DI) + DI + d];
            float sg = g / (1.0f + __expf(-g));               // silu(gate)
            y[(size_t)token * DI + d] = (yv + Dval * xp) * sg;
        }
    }
}

// ---------------- host launcher ----------------
extern "C" void kernel_launch(void* const* d_in, const int* in_sizes, int n_in,
                              void* d_out, int out_size)
{
    const float* x      = (const float*)d_in[0];
    const float* ln1_g  = (const float*)d_in[1];
    const float* ln1_b  = (const float*)d_in[2];
    const float* W_in   = (const float*)d_in[3];
    const float* b_in   = (const float*)d_in[4];
    const float* conv_w = (const float*)d_in[5];
    const float* conv_b = (const float*)d_in[6];
    const float* A_log  = (const float*)d_in[7];
    const float* W_B    = (const float*)d_in[8];
    const float* b_B    = (const float*)d_in[9];
    const float* W_C    = (const float*)d_in[10];
    const float* b_C    = (const float*)d_in[11];
    const float* Dp     = (const float*)d_in[12];
    const float* W_dt   = (const float*)d_in[13];
    const float* b_dt   = (const float*)d_in[14];
    const float* W_out  = (const float*)d_in[15];
    const float* b_out  = (const float*)d_in[16];
    const float* ln2_g  = (const float*)d_in[17];
    const float* ln2_b  = (const float*)d_in[18];
    const float* W1     = (const float*)d_in[19];
    const float* b1     = (const float*)d_in[20];
    const float* W2     = (const float*)d_in[21];
    const float* b2     = (const float*)d_in[22];
    float* out = (float*)d_out;

    float *xn, *xg, *xc, *delta, *Bm, *Cm, *y, *x2, *xn2, *h1;
    cudaGetSymbolAddress((void**)&xn,    g_xn);
    cudaGetSymbolAddress((void**)&xg,    g_xg);
    cudaGetSymbolAddress((void**)&xc,    g_xc);
    cudaGetSymbolAddress((void**)&delta, g_delta);
    cudaGetSymbolAddress((void**)&Bm,    g_Bm);
    cudaGetSymbolAddress((void**)&Cm,    g_Cm);
    cudaGetSymbolAddress((void**)&y,     g_y);
    cudaGetSymbolAddress((void**)&x2,    g_x2);
    cudaGetSymbolAddress((void**)&xn2,   g_xn2);
    cudaGetSymbolAddress((void**)&h1,    g_h1);

    // 1) LN1
    ln_kernel<<<MTOK, 256>>>(x, ln1_g, ln1_b, xn);
    // 2) xg = xn @ W_in + b_in              [2048, 4096]
    sgemm<0><<<dim3((2*DI)/128, MTOK/128), 256>>>(MTOK, 2*DI, DM, xn, W_in, b_in, nullptr, xg);
    // 3) causal depthwise conv on x_proj    [2048, 2048]
    conv_kernel<<<(MTOK*DI)/256, 256>>>(xg, conv_w, conv_b, xc);
    // 4) delta = sigmoid(xc @ W_dt + b_dt)*0.099 + 0.001
    sgemm<1><<<dim3(DI/128, MTOK/128), 256>>>(MTOK, DI, DI, xc, W_dt, b_dt, nullptr, delta);
    // 5) Bm, Cm                             [2048, 32768] each
    sgemm<0><<<dim3((DI*DS)/128, MTOK/128), 256>>>(MTOK, DI*DS, DI, xc, W_B, b_B, nullptr, Bm);
    sgemm<0><<<dim3((DI*DS)/128, MTOK/128), 256>>>(MTOK, DI*DS, DI, xc, W_C, b_C, nullptr, Cm);
    // 6) selective scan + Dp*x_proj + silu(gate) fused
    scan_kernel<<<256, 256>>>(xg, delta, Bm, Cm, A_log, Dp, y);
    // 7) x2 = residual + y @ W_out + b_out
    sgemm<3><<<dim3(DM/128, MTOK/128), 256>>>(MTOK, DM, DI, y, W_out, b_out, x, x2);
    // 8) LN2
    ln_kernel<<<MTOK, 256>>>(x2, ln2_g, ln2_b, xn2);
    // 9) h1 = gelu(xn2 @ W1 + b1)
    sgemm<2><<<dim3(DFF/128, MTOK/128), 256>>>(MTOK, DFF, DM, xn2, W1, b1, nullptr, h1);
    // 10) out = x2 + h1 @ W2 + b2
    sgemm<3><<<dim3(DM/128, MTOK/128), 256>>>(MTOK, DM, DFF, h1, W2, b2, x2, out);
}

// round 6
// speedup vs baseline: 1.6355x; 1.6355x over previous
#include <cuda_runtime.h>
#include <cuda_bf16.h>
#include <math.h>

#define B_SZ 2
#define SEQ  1024
#define DM   1024
#define DI   2048
#define DS   16
#define DFF  4096
#define MTOK (B_SZ*SEQ)

// ---- GEMM tiling ----
#define BM 128
#define BN 128
#define BK 32
#define NSTAGE 3
#define PITCH 40                      // bf16 per smem row (80 bytes)
#define SPLIT_B (128*PITCH*2)         // 10240 B: one split tile (128 rows x 80B)
#define AB_B    (2*SPLIT_B)           // 20480 B: hi+lo for one operand
#define STAGE_B (2*AB_B)              // 40960 B: A(hi,lo) + B(hi,lo)
#define SMEM_B  (NSTAGE*STAGE_B)      // 122880 B

// ---- fp32 scratch ----
__device__ float g_xg   [MTOK*2*DI];
__device__ float g_delta[MTOK*DI];
__device__ float g_Bm   [67108864];
__device__ float g_Cm   [67108864];
__device__ float g_x2   [MTOK*DM];
// ---- bf16 activation pairs (GEMM A operands) ----
__device__ __nv_bfloat16 g_xn_h [MTOK*DM],  g_xn_l [MTOK*DM];
__device__ __nv_bfloat16 g_xc_h [MTOK*DI],  g_xc_l [MTOK*DI];
__device__ __nv_bfloat16 g_y_h  [MTOK*DI],  g_y_l  [MTOK*DI];
__device__ __nv_bfloat16 g_xn2_h[MTOK*DM],  g_xn2_l[MTOK*DM];
__device__ __nv_bfloat16 g_h1_h [MTOK*DFF], g_h1_l [MTOK*DFF];
// ---- bf16 transposed weight pairs [N,K] ----
__device__ __nv_bfloat16 g_Win_h [2*DI*DM],  g_Win_l [2*DI*DM];
__device__ __nv_bfloat16 g_Wdt_h [DI*DI],    g_Wdt_l [DI*DI];
__device__ __nv_bfloat16 g_WB_h  [DI*DI*DS], g_WB_l  [DI*DI*DS];
__device__ __nv_bfloat16 g_WC_h  [DI*DI*DS], g_WC_l  [DI*DI*DS];
__device__ __nv_bfloat16 g_Wout_h[DM*DI],    g_Wout_l[DM*DI];
__device__ __nv_bfloat16 g_W1_h  [DFF*DM],   g_W1_l  [DFF*DM];
__device__ __nv_bfloat16 g_W2_h  [DM*DFF],   g_W2_l  [DM*DFF];

// ---------------- helpers ----------------
__device__ __forceinline__ unsigned s2u(const void* p) {
    unsigned a;
    asm("{ .reg .u64 t; cvta.to.shared.u64 t, %1; cvt.u32.u64 %0, t; }" : "=r"(a) : "l"(p));
    return a;
}
__device__ __forceinline__ void cp16(unsigned d, const void* s) {
    asm volatile("cp.async.cg.shared.global [%0], [%1], 16;" :: "r"(d), "l"(s));
}
#define CP_COMMIT() asm volatile("cp.async.commit_group;" ::: "memory")
#define CP_WAIT1()  asm volatile("cp.async.wait_group 1;" ::: "memory")
#define LDSM4(r, addr) \
    asm volatile("ldmatrix.sync.aligned.m8n8.x4.shared.b16 {%0,%1,%2,%3}, [%4];" \
        : "=r"((r)[0]),"=r"((r)[1]),"=r"((r)[2]),"=r"((r)[3]) : "r"(addr))
#define MMA4(d, a, b0v, b1v) \
    asm volatile("mma.sync.aligned.m16n8k16.row.col.f32.bf16.bf16.f32 " \
        "{%0,%1,%2,%3},{%4,%5,%6,%7},{%8,%9},{%0,%1,%2,%3};" \
        : "+f"((d)[0]),"+f"((d)[1]),"+f"((d)[2]),"+f"((d)[3]) \
        : "r"((a)[0]),"r"((a)[1]),"r"((a)[2]),"r"((a)[3]),"r"(b0v),"r"(b1v))

__device__ __forceinline__ void split_bf16(float v, __nv_bfloat16& h, __nv_bfloat16& l) {
    h = __float2bfloat16(v);
    l = __float2bfloat16(v - __bfloat162float(h));
}

// ---------------- split HMMA GEMM ----------------
// C[M,N] = A[M,K] @ W[K,N]; A = Ah+Al bf16 [M,K]; W = Bh+Bl bf16 [N,K] (pre-transposed).
// EPI: 0 bias ; 1 sigmoid-delta ; 2 gelu ; 3 bias+residual.  OBF: emit bf16 hi/lo pairs.
template<int EPI, bool OBF>
__device__ __forceinline__ void epi2(int r, int c, float v0, float v1, int N,
    const float* __restrict__ bias, const float* __restrict__ add,
    float* __restrict__ outf, __nv_bfloat16* __restrict__ oh, __nv_bfloat16* __restrict__ ol)
{
    size_t go = (size_t)r*N + c;
    float2 bb = *(const float2*)&bias[c];
    v0 += bb.x; v1 += bb.y;
    if (EPI == 3) { float2 aa = *(const float2*)&add[go]; v0 += aa.x; v1 += aa.y; }
    if (EPI == 1) {
        v0 = 1.0f/(1.0f + expf(-v0))*0.099f + 0.001f;
        v1 = 1.0f/(1.0f + expf(-v1))*0.099f + 0.001f;
    }
    if (EPI == 2) {
        v0 = 0.5f*v0*(1.0f + erff(v0*0.70710678118654752f));
        v1 = 0.5f*v1*(1.0f + erff(v1*0.70710678118654752f));
    }
    if (OBF) {
        __nv_bfloat16 h0,l0,h1,l1;
        split_bf16(v0,h0,l0); split_bf16(v1,h1,l1);
        *(__nv_bfloat162*)&oh[go] = __nv_bfloat162{h0,h1};
        *(__nv_bfloat162*)&ol[go] = __nv_bfloat162{l0,l1};
    } else {
        float2 o; o.x = v0; o.y = v1;
        *(float2*)&outf[go] = o;
    }
}

template<int EPI, bool OBF>
__global__ __launch_bounds__(256, 1)
void hgemm(const __nv_bfloat16* __restrict__ Ah, const __nv_bfloat16* __restrict__ Al,
           const __nv_bfloat16* __restrict__ Bh, const __nv_bfloat16* __restrict__ Bl,
           int K, int N,
           const float* __restrict__ bias, const float* __restrict__ add,
           float* __restrict__ outf,
           __nv_bfloat16* __restrict__ oh, __nv_bfloat16* __restrict__ ol)
{
    extern __shared__ char sm[];
    unsigned sbase = s2u(sm);
    int tid = threadIdx.x, lane = tid & 31, wid = tid >> 5;
    int wm = wid & 3, wn = wid >> 2;           // 4 x 2 warp grid; warp tile 32 x 64
    int crow = blockIdx.x * BM, ccol = blockIdx.y * BN;

    // loader mapping: each thread owns one row of one split for A and B (4 chunks each)
    int lrow = tid & 127, lsp = tid >> 7;
    const __nv_bfloat16* Asrc = (lsp ? Al : Ah) + (size_t)(crow + lrow)*K;
    const __nv_bfloat16* Bsrc = (lsp ? Bl : Bh) + (size_t)(ccol + lrow)*K;
    unsigned adst = sbase + lsp*SPLIT_B + lrow*80;
    unsigned bdst = sbase + AB_B + lsp*SPLIT_B + lrow*80;

    float acc[2][8][4];
    #pragma unroll
    for (int i = 0; i < 2; i++)
        #pragma unroll
        for (int j = 0; j < 8; j++)
            #pragma unroll
            for (int q = 0; q < 4; q++) acc[i][j][q] = 0.f;

    const int nk = K / BK;

    // prologue: stages 0..NSTAGE-2
    #pragma unroll
    for (int st = 0; st < NSTAGE-1; st++) {
        const __nv_bfloat16* as = Asrc + st*BK;
        const __nv_bfloat16* bs = Bsrc + st*BK;
        unsigned ao = adst + st*STAGE_B, bo = bdst + st*STAGE_B;
        #pragma unroll
        for (int c = 0; c < 4; c++) {
            cp16(ao + c*16, as + c*8);
            cp16(bo + c*16, bs + c*8);
        }
        CP_COMMIT();
    }

    int rrow = lane & 15, rhalf = lane >> 4;

    for (int i = 0; i < nk; i++) {
        CP_WAIT1();
        __syncthreads();
        int st = i % NSTAGE;
        unsigned aST = sbase + st*STAGE_B;
        unsigned bST = aST + AB_B;

        #pragma unroll
        for (int ks = 0; ks < 2; ks++) {
            int koff = ks*16;
            unsigned ah[2][4], al_[2][4], bh[8][2], bl_[8][2];
            #pragma unroll
            for (int mt = 0; mt < 2; mt++) {
                unsigned base = aST + (unsigned)(wm*32 + mt*16 + rrow)*80
                              + (unsigned)(koff + rhalf*8)*2;
                LDSM4(ah[mt], base);
                LDSM4(al_[mt], base + SPLIT_B);
            }
            #pragma unroll
            for (int p = 0; p < 4; p++) {
                unsigned base = bST + (unsigned)(wn*64 + p*16 + rrow)*80
                              + (unsigned)(koff + rhalf*8)*2;
                unsigned t[4];
                LDSM4(t, base);
                bh[2*p][0] = t[0]; bh[2*p+1][0] = t[1];
                bh[2*p][1] = t[2]; bh[2*p+1][1] = t[3];
                LDSM4(t, base + SPLIT_B);
                bl_[2*p][0] = t[0]; bl_[2*p+1][0] = t[1];
                bl_[2*p][1] = t[2]; bl_[2*p+1][1] = t[3];
            }
            #pragma unroll
            for (int mt = 0; mt < 2; mt++)
                #pragma unroll
                for (int nt = 0; nt < 8; nt++) {
                    MMA4(acc[mt][nt], ah[mt],  bh[nt][0],  bh[nt][1]);
                    MMA4(acc[mt][nt], ah[mt],  bl_[nt][0], bl_[nt][1]);
                    MMA4(acc[mt][nt], al_[mt], bh[nt][0],  bh[nt][1]);
                }
        }
        __syncthreads();

        int j = i + NSTAGE - 1;
        if (j < nk) {
            int sl = j % NSTAGE;
            const __nv_bfloat16* as = Asrc + j*BK;
            const __nv_bfloat16* bs = Bsrc + j*BK;
            unsigned ao = adst + sl*STAGE_B, bo = bdst + sl*STAGE_B;
            #pragma unroll
            for (int c = 0; c < 4; c++) {
                cp16(ao + c*16, as + c*8);
                cp16(bo + c*16, bs + c*8);
            }
        }
        CP_COMMIT();
    }

    // epilogue: fragment layout m16n8k16 C: (r0, c..c+1) regs 0-1, (r0+8, c..c+1) regs 2-3
    #pragma unroll
    for (int mt = 0; mt < 2; mt++) {
        int r0 = crow + wm*32 + mt*16 + (lane >> 2);
        #pragma unroll
        for (int nt = 0; nt < 8; nt++) {
            int c = ccol + wn*64 + nt*8 + 2*(lane & 3);
            epi2<EPI,OBF>(r0,     c, acc[mt][nt][0], acc[mt][nt][1], N, bias, add, outf, oh, ol);
            epi2<EPI,OBF>(r0 + 8, c, acc[mt][nt][2], acc[mt][nt][3], N, bias, add, outf, oh, ol);
        }
    }
}

// ---------------- weight transpose + split: W[K,N] fp32 -> hi/lo [N,K] bf16 ----------------
__global__ __launch_bounds__(256)
void wtrans(const float* __restrict__ W, __nv_bfloat16* __restrict__ hi,
            __nv_bfloat16* __restrict__ lo, int K, int N)
{
    __shared__ float t[32][33];
    int n0 = blockIdx.x*32, k0 = blockIdx.y*32;
    int tx = threadIdx.x, ty = threadIdx.y;
    #pragma unroll
    for (int i = 0; i < 4; i++)
        t[ty + i*8][tx] = W[(size_t)(k0 + ty + i*8)*N + n0 + tx];
    __syncthreads();
    #pragma unroll
    for (int i = 0; i < 4; i++) {
        int nl = ty + i*8;
        __nv_bfloat16 h, l; split_bf16(t[tx][nl], h, l);
        size_t o = (size_t)(n0 + nl)*K + k0 + tx;
        hi[o] = h; lo[o] = l;
    }
}

// ---------------- LayerNorm -> bf16 pair ----------------
__global__ __launch_bounds__(256)
void ln_kernel(const float* __restrict__ in, const float* __restrict__ g,
               const float* __restrict__ bcoef,
               __nv_bfloat16* __restrict__ oh, __nv_bfloat16* __restrict__ ol)
{
    int row = blockIdx.x, tid = threadIdx.x;
    float4 v = ((const float4*)(in + (size_t)row*DM))[tid];
    __shared__ float red1[8], red2[8];
    float s = v.x + v.y + v.z + v.w;
    #pragma unroll
    for (int o = 16; o > 0; o >>= 1) s += __shfl_xor_sync(0xffffffffu, s, o);
    if ((tid & 31) == 0) red1[tid >> 5] = s;
    __syncthreads();
    float tot = 0.f;
    #pragma unroll
    for (int i = 0; i < 8; i++) tot += red1[i];
    float mean = tot * (1.0f/DM);
    float dx = v.x-mean, dy = v.y-mean, dz = v.z-mean, dw = v.w-mean;
    float sq = dx*dx + dy*dy + dz*dz + dw*dw;
    #pragma unroll
    for (int o = 16; o > 0; o >>= 1) sq += __shfl_xor_sync(0xffffffffu, sq, o);
    if ((tid & 31) == 0) red2[tid >> 5] = sq;
    __syncthreads();
    float tot2 = 0.f;
    #pragma unroll
    for (int i = 0; i < 8; i++) tot2 += red2[i];
    float rstd = rsqrtf(tot2*(1.0f/DM) + 1e-5f);
    float4 gg = ((const float4*)g)[tid];
    float4 bb = ((const float4*)bcoef)[tid];
    float o0 = dx*rstd*gg.x+bb.x, o1 = dy*rstd*gg.y+bb.y;
    float o2 = dz*rstd*gg.z+bb.z, o3 = dw*rstd*gg.w+bb.w;
    __nv_bfloat16 h0,l0,h1,l1,h2,l2,h3,l3;
    split_bf16(o0,h0,l0); split_bf16(o1,h1,l1); split_bf16(o2,h2,l2); split_bf16(o3,h3,l3);
    __nv_bfloat162* ph = (__nv_bfloat162*)(oh + (size_t)row*DM);
    __nv_bfloat162* pl = (__nv_bfloat162*)(ol + (size_t)row*DM);
    ph[tid*2] = __nv_bfloat162{h0,h1}; ph[tid*2+1] = __nv_bfloat162{h2,h3};
    pl[tid*2] = __nv_bfloat162{l0,l1}; pl[tid*2+1] = __nv_bfloat162{l2,l3};
}

// ---------------- causal depthwise conv -> bf16 pair ----------------
__global__ __launch_bounds__(256)
void conv_kernel(const float* __restrict__ xg, const float* __restrict__ cw,
                 const float* __restrict__ cb,
                 __nv_bfloat16* __restrict__ oh, __nv_bfloat16* __restrict__ ol)
{
    int idx = blockIdx.x*blockDim.x + threadIdx.x;
    int d = idx & (DI-1);
    int token = idx >> 11;
    int t = token & (SEQ-1);
    float acc = cb[d];
    #pragma unroll
    for (int k = 0; k < 4; k++) {
        int ts = t - 3 + k;
        if (ts >= 0) acc += xg[(size_t)(token-3+k)*(2*DI) + d] * cw[d*4+k];
    }
    __nv_bfloat16 h, l; split_bf16(acc, h, l);
    oh[idx] = h; ol[idx] = l;
}

// ---------------- selective scan -> bf16 pair ----------------
__global__ __launch_bounds__(256)
void scan_kernel(const float* __restrict__ xg, const float* __restrict__ delta,
                 const float* __restrict__ Bm, const float* __restrict__ Cm,
                 const float* __restrict__ A_log, const float* __restrict__ Dp,
                 __nv_bfloat16* __restrict__ yh, __nv_bfloat16* __restrict__ yl)
{
    int tid = blockIdx.x*blockDim.x + threadIdx.x;
    int n = tid & (DS-1);
    int d = (tid >> 4) & (DI-1);
    int b = tid >> 15;
    float Aneg = -expf(A_log[d*DS + n]);
    float Dval = Dp[d];
    float h = 0.f;
    int base_tok = b*SEQ;
    for (int t = 0; t < SEQ; ++t) {
        int token = base_tok + t;
        float dv = delta[(size_t)token*DI + d];
        float xp = xg[(size_t)token*(2*DI) + d];
        float bm = Bm[(size_t)token*(DI*DS) + d*DS + n];
        float cm = Cm[(size_t)token*(DI*DS) + d*DS + n];
        float a = __expf(dv*Aneg);
        h = a*h + (dv*bm)*xp;
        float yv = cm*h;
        yv += __shfl_xor_sync(0xffffffffu, yv, 1);
        yv += __shfl_xor_sync(0xffffffffu, yv, 2);
        yv += __shfl_xor_sync(0xffffffffu, yv, 4);
        yv += __shfl_xor_sync(0xffffffffu, yv, 8);
        if (n == 0) {
            float g = xg[(size_t)token*(2*DI) + DI + d];
            float sg = g / (1.0f + __expf(-g));
            float val = (yv + Dval*xp)*sg;
            __nv_bfloat16 hh, ll; split_bf16(val, hh, ll);
            yh[(size_t)token*DI + d] = hh;
            yl[(size_t)token*DI + d] = ll;
        }
    }
}

// ---------------- host ----------------
template<int EPI, bool OBF>
static void launch_hgemm(const __nv_bfloat16* Ah, const __nv_bfloat16* Al,
                         const __nv_bfloat16* Bh, const __nv_bfloat16* Bl,
                         int K, int N, const float* bias, const float* add,
                         float* outf, __nv_bfloat16* oh, __nv_bfloat16* ol)
{
    cudaFuncSetAttribute(hgemm<EPI,OBF>, cudaFuncAttributeMaxDynamicSharedMemorySize, SMEM_B);
    hgemm<EPI,OBF><<<dim3(MTOK/BM, N/BN), 256, SMEM_B>>>(Ah, Al, Bh, Bl, K, N,
                                                          bias, add, outf, oh, ol);
}

extern "C" void kernel_launch(void* const* d_in, const int* in_sizes, int n_in,
                              void* d_out, int out_size)
{
    const float* x      = (const float*)d_in[0];
    const float* ln1_g  = (const float*)d_in[1];
    const float* ln1_b  = (const float*)d_in[2];
    const float* W_in   = (const float*)d_in[3];
    const float* b_in   = (const float*)d_in[4];
    const float* conv_w = (const float*)d_in[5];
    const float* conv_b = (const float*)d_in[6];
    const float* A_log  = (const float*)d_in[7];
    const float* W_B    = (const float*)d_in[8];
    const float* b_B    = (const float*)d_in[9];
    const float* W_C    = (const float*)d_in[10];
    const float* b_C    = (const float*)d_in[11];
    const float* Dp     = (const float*)d_in[12];
    const float* W_dt   = (const float*)d_in[13];
    const float* b_dt   = (const float*)d_in[14];
    const float* W_out  = (const float*)d_in[15];
    const float* b_out  = (const float*)d_in[16];
    const float* ln2_g  = (const float*)d_in[17];
    const float* ln2_b  = (const float*)d_in[18];
    const float* W1     = (const float*)d_in[19];
    const float* b1     = (const float*)d_in[20];
    const float* W2     = (const float*)d_in[21];
    const float* b2     = (const float*)d_in[22];
    float* out = (float*)d_out;

    float *xg, *delta, *Bm, *Cm, *x2;
    cudaGetSymbolAddress((void**)&xg, g_xg);
    cudaGetSymbolAddress((void**)&delta, g_delta);
    cudaGetSymbolAddress((void**)&Bm, g_Bm);
    cudaGetSymbolAddress((void**)&Cm, g_Cm);
    cudaGetSymbolAddress((void**)&x2, g_x2);
    __nv_bfloat16 *xnh,*xnl,*xch,*xcl,*yh,*yl,*xn2h,*xn2l,*h1h,*h1l;
    cudaGetSymbolAddress((void**)&xnh, g_xn_h);   cudaGetSymbolAddress((void**)&xnl, g_xn_l);
    cudaGetSymbolAddress((void**)&xch, g_xc_h);   cudaGetSymbolAddress((void**)&xcl, g_xc_l);
    cudaGetSymbolAddress((void**)&yh,  g_y_h);    cudaGetSymbolAddress((void**)&yl,  g_y_l);
    cudaGetSymbolAddress((void**)&xn2h,g_xn2_h);  cudaGetSymbolAddress((void**)&xn2l,g_xn2_l);
    cudaGetSymbolAddress((void**)&h1h, g_h1_h);   cudaGetSymbolAddress((void**)&h1l, g_h1_l);
    __nv_bfloat16 *Winh,*Winl,*Wdth,*Wdtl,*WBh,*WBl,*WCh,*WCl,*Wouth,*Woutl,*W1h,*W1l,*W2h,*W2l;
    cudaGetSymbolAddress((void**)&Winh, g_Win_h); cudaGetSymbolAddress((void**)&Winl, g_Win_l);
    cudaGetSymbolAddress((void**)&Wdth, g_Wdt_h); cudaGetSymbolAddress((void**)&Wdtl, g_Wdt_l);
    cudaGetSymbolAddress((void**)&WBh,  g_WB_h);  cudaGetSymbolAddress((void**)&WBl,  g_WB_l);
    cudaGetSymbolAddress((void**)&WCh,  g_WC_h);  cudaGetSymbolAddress((void**)&WCl,  g_WC_l);
    cudaGetSymbolAddress((void**)&Wouth,g_Wout_h);cudaGetSymbolAddress((void**)&Woutl,g_Wout_l);
    cudaGetSymbolAddress((void**)&W1h,  g_W1_h);  cudaGetSymbolAddress((void**)&W1l,  g_W1_l);
    cudaGetSymbolAddress((void**)&W2h,  g_W2_h);  cudaGetSymbolAddress((void**)&W2l,  g_W2_l);

    dim3 tb(32, 8);
    wtrans<<<dim3((2*DI)/32, DM/32),  tb>>>(W_in,  Winh,  Winl,  DM,  2*DI);
    wtrans<<<dim3(DI/32, DI/32),      tb>>>(W_dt,  Wdth,  Wdtl,  DI,  DI);
    wtrans<<<dim3((DI*DS)/32, DI/32), tb>>>(W_B,   WBh,   WBl,   DI,  DI*DS);
    wtrans<<<dim3((DI*DS)/32, DI/32), tb>>>(W_C,   WCh,   WCl,   DI,  DI*DS);
    wtrans<<<dim3(DM/32, DI/32),      tb>>>(W_out, Wouth, Woutl, DI,  DM);
    wtrans<<<dim3(DFF/32, DM/32),     tb>>>(W1,    W1h,   W1l,   DM,  DFF);
    wtrans<<<dim3(DM/32, DFF/32),     tb>>>(W2,    W2h,   W2l,   DFF, DM);

    // 1) LN1 -> xn pairs
    ln_kernel<<<MTOK, 256>>>(x, ln1_g, ln1_b, xnh, xnl);
    // 2) xg = xn @ W_in + b_in (fp32)
    launch_hgemm<0,false>(xnh, xnl, Winh, Winl, DM, 2*DI, b_in, nullptr, xg, nullptr, nullptr);
    // 3) conv -> xc pairs
    conv_kernel<<<(MTOK*DI)/256, 256>>>(xg, conv_w, conv_b, xch, xcl);
    // 4) delta = sigmoid(xc @ W_dt + b_dt)*0.099 + 0.001
    launch_hgemm<1,false>(xch, xcl, Wdth, Wdtl, DI, DI, b_dt, nullptr, delta, nullptr, nullptr);
    // 5) Bm, Cm
    launch_hgemm<0,false>(xch, xcl, WBh, WBl, DI, DI*DS, b_B, nullptr, Bm, nullptr, nullptr);
    launch_hgemm<0,false>(xch, xcl, WCh, WCl, DI, DI*DS, b_C, nullptr, Cm, nullptr, nullptr);
    // 6) scan -> y pairs
    scan_kernel<<<256, 256>>>(xg, delta, Bm, Cm, A_log, Dp, yh, yl);
    // 7) x2 = x + y @ W_out + b_out
    launch_hgemm<3,false>(yh, yl, Wouth, Woutl, DI, DM, b_out, x, x2, nullptr, nullptr);
    // 8) LN2 -> xn2 pairs
    ln_kernel<<<MTOK, 256>>>(x2, ln2_g, ln2_b, xn2h, xn2l);
    // 9) h1 = gelu(xn2 @ W1 + b1) -> bf16 pairs
    launch_hgemm<2,true>(xn2h, xn2l, W1h, W1l, DM, DFF, b1, nullptr, nullptr, h1h, h1l);
    // 10) out = x2 + h1 @ W2 + b2
    launch_hgemm<3,false>(h1h, h1l, W2h, W2l, DFF, DM, b2, x2, out, nullptr, nullptr);
}

// round 7
// speedup vs baseline: 1.7339x; 1.0602x over previous
#include <cuda_runtime.h>
#include <cuda_bf16.h>
#include <math.h>

#define B_SZ 2
#define SEQ  1024
#define DM   1024
#define DI   2048
#define DS   16
#define DFF  4096
#define MTOK (B_SZ*SEQ)

// ---- GEMM tiling: CTA 128x256, warp 64x64 (2x4 warps), BK=32, 3-stage cp.async ----
#define BM 128
#define BN 256
#define BK 32
#define NSTAGE 3
#define ROWB 80                        // bytes per smem row (40 bf16; conflict-free ldmatrix)
#define A_SPLIT (BM*ROWB)              // 10240
#define A_BOTH  (2*A_SPLIT)            // 20480
#define B_SPLIT (BN*ROWB)              // 20480
#define B_BOTH  (2*B_SPLIT)            // 40960
#define STAGE_B (A_BOTH + B_BOTH)      // 61440
#define SMEM_B  (NSTAGE*STAGE_B)       // 184320

// ---- fp32 scratch ----
__device__ float g_xg   [MTOK*2*DI];
__device__ float g_delta[MTOK*DI];
__device__ float g_Bm   [67108864];
__device__ float g_Cm   [67108864];
__device__ float g_x2   [MTOK*DM];
// ---- bf16 activation pairs ----
__device__ __nv_bfloat16 g_xn_h [MTOK*DM],  g_xn_l [MTOK*DM];
__device__ __nv_bfloat16 g_xc_h [MTOK*DI],  g_xc_l [MTOK*DI];
__device__ __nv_bfloat16 g_y_h  [MTOK*DI],  g_y_l  [MTOK*DI];
__device__ __nv_bfloat16 g_xn2_h[MTOK*DM],  g_xn2_l[MTOK*DM];
__device__ __nv_bfloat16 g_h1_h [MTOK*DFF], g_h1_l [MTOK*DFF];
// ---- bf16 transposed weight pairs [N,K] ----
__device__ __nv_bfloat16 g_Win_h [2*DI*DM],  g_Win_l [2*DI*DM];
__device__ __nv_bfloat16 g_Wdt_h [DI*DI],    g_Wdt_l [DI*DI];
__device__ __nv_bfloat16 g_WB_h  [DI*DI*DS], g_WB_l  [DI*DI*DS];
__device__ __nv_bfloat16 g_WC_h  [DI*DI*DS], g_WC_l  [DI*DI*DS];
__device__ __nv_bfloat16 g_Wout_h[DM*DI],    g_Wout_l[DM*DI];
__device__ __nv_bfloat16 g_W1_h  [DFF*DM],   g_W1_l  [DFF*DM];
__device__ __nv_bfloat16 g_W2_h  [DM*DFF],   g_W2_l  [DM*DFF];

// ---------------- helpers ----------------
__device__ __forceinline__ unsigned s2u(const void* p) {
    unsigned a;
    asm("{ .reg .u64 t; cvta.to.shared.u64 t, %1; cvt.u32.u64 %0, t; }" : "=r"(a) : "l"(p));
    return a;
}
__device__ __forceinline__ void cp16(unsigned d, const void* s) {
    asm volatile("cp.async.cg.shared.global [%0], [%1], 16;" :: "r"(d), "l"(s));
}
#define CP_COMMIT() asm volatile("cp.async.commit_group;" ::: "memory")
#define CP_WAIT1()  asm volatile("cp.async.wait_group 1;" ::: "memory")
#define LDSM4(r, addr) \
    asm volatile("ldmatrix.sync.aligned.m8n8.x4.shared.b16 {%0,%1,%2,%3}, [%4];" \
        : "=r"((r)[0]),"=r"((r)[1]),"=r"((r)[2]),"=r"((r)[3]) : "r"(addr))
#define MMA4(d, a, b0v, b1v) \
    asm volatile("mma.sync.aligned.m16n8k16.row.col.f32.bf16.bf16.f32 " \
        "{%0,%1,%2,%3},{%4,%5,%6,%7},{%8,%9},{%0,%1,%2,%3};" \
        : "+f"((d)[0]),"+f"((d)[1]),"+f"((d)[2]),"+f"((d)[3]) \
        : "r"((a)[0]),"r"((a)[1]),"r"((a)[2]),"r"((a)[3]),"r"(b0v),"r"(b1v))

__device__ __forceinline__ void split_bf16(float v, __nv_bfloat16& h, __nv_bfloat16& l) {
    h = __float2bfloat16(v);
    l = __float2bfloat16(v - __bfloat162float(h));
}

// ---------------- epilogue helper ----------------
template<int EPI, bool OBF>
__device__ __forceinline__ void epi2(int r, int c, float v0, float v1, int N,
    const float* __restrict__ bias, const float* __restrict__ add,
    float* __restrict__ outf, __nv_bfloat16* __restrict__ oh, __nv_bfloat16* __restrict__ ol)
{
    size_t go = (size_t)r*N + c;
    float2 bb = *(const float2*)&bias[c];
    v0 += bb.x; v1 += bb.y;
    if (EPI == 3) { float2 aa = *(const float2*)&add[go]; v0 += aa.x; v1 += aa.y; }
    if (EPI == 1) {
        v0 = 1.0f/(1.0f + expf(-v0))*0.099f + 0.001f;
        v1 = 1.0f/(1.0f + expf(-v1))*0.099f + 0.001f;
    }
    if (EPI == 2) {
        v0 = 0.5f*v0*(1.0f + erff(v0*0.70710678118654752f));
        v1 = 0.5f*v1*(1.0f + erff(v1*0.70710678118654752f));
    }
    if (OBF) {
        __nv_bfloat16 h0,l0,h1,l1;
        split_bf16(v0,h0,l0); split_bf16(v1,h1,l1);
        *(__nv_bfloat162*)&oh[go] = __nv_bfloat162{h0,h1};
        *(__nv_bfloat162*)&ol[go] = __nv_bfloat162{l0,l1};
    } else {
        float2 o; o.x = v0; o.y = v1;
        *(float2*)&outf[go] = o;
    }
}

// ---------------- split HMMA GEMM (3-term bf16) ----------------
template<int EPI, bool OBF>
__global__ __launch_bounds__(256, 1)
void hgemm(const __nv_bfloat16* __restrict__ Ah, const __nv_bfloat16* __restrict__ Al,
           const __nv_bfloat16* __restrict__ Bh, const __nv_bfloat16* __restrict__ Bl,
           int K, int N,
           const float* __restrict__ bias, const float* __restrict__ add,
           float* __restrict__ outf,
           __nv_bfloat16* __restrict__ oh, __nv_bfloat16* __restrict__ ol)
{
    extern __shared__ char sm[];
    unsigned sbase = s2u(sm);
    int tid = threadIdx.x, lane = tid & 31, wid = tid >> 5;
    int wm = wid & 1, wn = wid >> 1;            // 2 x 4 warp grid; warp tile 64 x 64
    int crow = blockIdx.x * BM, ccol = blockIdx.y * BN;

    // loader mapping
    int arow = tid & 127, asp = tid >> 7;                     // 1 A row-split per thread
    const __nv_bfloat16* Asrc = (asp ? Al : Ah) + (size_t)(crow + arow)*K;
    unsigned adst = sbase + asp*A_SPLIT + arow*ROWB;
    int brow0 = tid, brow1 = tid + 256;                       // 2 B row-splits per thread
    const __nv_bfloat16* Bsrc0 = ((brow0 >> 8) ? Bl : Bh) + (size_t)(ccol + (brow0 & 255))*K;
    const __nv_bfloat16* Bsrc1 = ((brow1 >> 8) ? Bl : Bh) + (size_t)(ccol + (brow1 & 255))*K;
    unsigned bdst0 = sbase + A_BOTH + (brow0 >> 8)*B_SPLIT + (brow0 & 255)*ROWB;
    unsigned bdst1 = sbase + A_BOTH + (brow1 >> 8)*B_SPLIT + (brow1 & 255)*ROWB;

    float acc[4][8][4];
    #pragma unroll
    for (int i = 0; i < 4; i++)
        #pragma unroll
        for (int j = 0; j < 8; j++)
            #pragma unroll
            for (int q = 0; q < 4; q++) acc[i][j][q] = 0.f;

    const int nk = K / BK;

    #pragma unroll
    for (int st = 0; st < NSTAGE-1; st++) {
        unsigned so = st*STAGE_B;
        #pragma unroll
        for (int c = 0; c < 4; c++) {
            cp16(adst + so + c*16,  Asrc  + st*BK + c*8);
            cp16(bdst0 + so + c*16, Bsrc0 + st*BK + c*8);
            cp16(bdst1 + so + c*16, Bsrc1 + st*BK + c*8);
        }
        CP_COMMIT();
    }

    int rrow = lane & 15, rhalf = lane >> 4;

    for (int i = 0; i < nk; i++) {
        CP_WAIT1();
        __syncthreads();

        // issue next stage immediately (overlaps with MMA block below)
        int j = i + NSTAGE - 1;
        if (j < nk) {
            unsigned so = (j % NSTAGE)*STAGE_B;
            #pragma unroll
            for (int c = 0; c < 4; c++) {
                cp16(adst + so + c*16,  Asrc  + j*BK + c*8);
                cp16(bdst0 + so + c*16, Bsrc0 + j*BK + c*8);
                cp16(bdst1 + so + c*16, Bsrc1 + j*BK + c*8);
            }
        }
        CP_COMMIT();

        unsigned aST = sbase + (i % NSTAGE)*STAGE_B;
        unsigned bST = aST + A_BOTH;

        #pragma unroll
        for (int ks = 0; ks < 2; ks++) {
            int koff = ks*16;
            unsigned ah[4][4], al_[4][4];
            #pragma unroll
            for (int mt = 0; mt < 4; mt++) {
                unsigned base = aST + (unsigned)(wm*64 + mt*16 + rrow)*ROWB
                              + (unsigned)(koff + rhalf*8)*2;
                LDSM4(ah[mt], base);
                LDSM4(al_[mt], base + A_SPLIT);
            }
            #pragma unroll
            for (int p = 0; p < 4; p++) {
                unsigned base = bST + (unsigned)(wn*64 + p*16 + rrow)*ROWB
                              + (unsigned)(koff + rhalf*8)*2;
                unsigned th[4], tl[4];
                LDSM4(th, base);
                LDSM4(tl, base + B_SPLIT);
                #pragma unroll
                for (int mt = 0; mt < 4; mt++) {
                    MMA4(acc[mt][2*p],   ah[mt],  th[0], th[2]);
                    MMA4(acc[mt][2*p+1], ah[mt],  th[1], th[3]);
                    MMA4(acc[mt][2*p],   ah[mt],  tl[0], tl[2]);
                    MMA4(acc[mt][2*p+1], ah[mt],  tl[1], tl[3]);
                    MMA4(acc[mt][2*p],   al_[mt], th[0], th[2]);
                    MMA4(acc[mt][2*p+1], al_[mt], th[1], th[3]);
                }
            }
        }
        __syncthreads();
    }

    // epilogue
    #pragma unroll
    for (int mt = 0; mt < 4; mt++) {
        int r0 = crow + wm*64 + mt*16 + (lane >> 2);
        #pragma unroll
        for (int nt = 0; nt < 8; nt++) {
            int c = ccol + wn*64 + nt*8 + 2*(lane & 3);
            epi2<EPI,OBF>(r0,     c, acc[mt][nt][0], acc[mt][nt][1], N, bias, add, outf, oh, ol);
            epi2<EPI,OBF>(r0 + 8, c, acc[mt][nt][2], acc[mt][nt][3], N, bias, add, outf, oh, ol);
        }
    }
}

// ---------------- weight transpose + split ----------------
__global__ __launch_bounds__(256)
void wtrans(const float* __restrict__ W, __nv_bfloat16* __restrict__ hi,
            __nv_bfloat16* __restrict__ lo, int K, int N)
{
    __shared__ float t[32][33];
    int n0 = blockIdx.x*32, k0 = blockIdx.y*32;
    int tx = threadIdx.x, ty = threadIdx.y;
    #pragma unroll
    for (int i = 0; i < 4; i++)
        t[ty + i*8][tx] = W[(size_t)(k0 + ty + i*8)*N + n0 + tx];
    __syncthreads();
    #pragma unroll
    for (int i = 0; i < 4; i++) {
        int nl = ty + i*8;
        __nv_bfloat16 h, l; split_bf16(t[tx][nl], h, l);
        size_t o = (size_t)(n0 + nl)*K + k0 + tx;
        hi[o] = h; lo[o] = l;
    }
}

// ---------------- LayerNorm -> bf16 pair ----------------
__global__ __launch_bounds__(256)
void ln_kernel(const float* __restrict__ in, const float* __restrict__ g,
               const float* __restrict__ bcoef,
               __nv_bfloat16* __restrict__ oh, __nv_bfloat16* __restrict__ ol)
{
    int row = blockIdx.x, tid = threadIdx.x;
    float4 v = ((const float4*)(in + (size_t)row*DM))[tid];
    __shared__ float red1[8], red2[8];
    float s = v.x + v.y + v.z + v.w;
    #pragma unroll
    for (int o = 16; o > 0; o >>= 1) s += __shfl_xor_sync(0xffffffffu, s, o);
    if ((tid & 31) == 0) red1[tid >> 5] = s;
    __syncthreads();
    float tot = 0.f;
    #pragma unroll
    for (int i = 0; i < 8; i++) tot += red1[i];
    float mean = tot * (1.0f/DM);
    float dx = v.x-mean, dy = v.y-mean, dz = v.z-mean, dw = v.w-mean;
    float sq = dx*dx + dy*dy + dz*dz + dw*dw;
    #pragma unroll
    for (int o = 16; o > 0; o >>= 1) sq += __shfl_xor_sync(0xffffffffu, sq, o);
    if ((tid & 31) == 0) red2[tid >> 5] = sq;
    __syncthreads();
    float tot2 = 0.f;
    #pragma unroll
    for (int i = 0; i < 8; i++) tot2 += red2[i];
    float rstd = rsqrtf(tot2*(1.0f/DM) + 1e-5f);
    float4 gg = ((const float4*)g)[tid];
    float4 bb = ((const float4*)bcoef)[tid];
    float o0 = dx*rstd*gg.x+bb.x, o1 = dy*rstd*gg.y+bb.y;
    float o2 = dz*rstd*gg.z+bb.z, o3 = dw*rstd*gg.w+bb.w;
    __nv_bfloat16 h0,l0,h1,l1,h2,l2,h3,l3;
    split_bf16(o0,h0,l0); split_bf16(o1,h1,l1); split_bf16(o2,h2,l2); split_bf16(o3,h3,l3);
    __nv_bfloat162* ph = (__nv_bfloat162*)(oh + (size_t)row*DM);
    __nv_bfloat162* pl = (__nv_bfloat162*)(ol + (size_t)row*DM);
    ph[tid*2] = __nv_bfloat162{h0,h1}; ph[tid*2+1] = __nv_bfloat162{h2,h3};
    pl[tid*2] = __nv_bfloat162{l0,l1}; pl[tid*2+1] = __nv_bfloat162{l2,l3};
}

// ---------------- causal depthwise conv -> bf16 pair ----------------
__global__ __launch_bounds__(256)
void conv_kernel(const float* __restrict__ xg, const float* __restrict__ cw,
                 const float* __restrict__ cb,
                 __nv_bfloat16* __restrict__ oh, __nv_bfloat16* __restrict__ ol)
{
    int idx = blockIdx.x*blockDim.x + threadIdx.x;
    int d = idx & (DI-1);
    int token = idx >> 11;
    int t = token & (SEQ-1);
    float acc = cb[d];
    #pragma unroll
    for (int k = 0; k < 4; k++) {
        int ts = t - 3 + k;
        if (ts >= 0) acc += xg[(size_t)(token-3+k)*(2*DI) + d] * cw[d*4+k];
    }
    __nv_bfloat16 h, l; split_bf16(acc, h, l);
    oh[idx] = h; ol[idx] = l;
}

// ---------------- selective scan -> bf16 pair ----------------
__global__ __launch_bounds__(256)
void scan_kernel(const float* __restrict__ xg, const float* __restrict__ delta,
                 const float* __restrict__ Bm, const float* __restrict__ Cm,
                 const float* __restrict__ A_log, const float* __restrict__ Dp,
                 __nv_bfloat16* __restrict__ yh, __nv_bfloat16* __restrict__ yl)
{
    int tid = blockIdx.x*blockDim.x + threadIdx.x;
    int n = tid & (DS-1);
    int d = (tid >> 4) & (DI-1);
    int b = tid >> 15;
    float Aneg = -expf(A_log[d*DS + n]);
    float Dval = Dp[d];
    float h = 0.f;
    int base_tok = b*SEQ;
    for (int t = 0; t < SEQ; ++t) {
        int token = base_tok + t;
        float dv = delta[(size_t)token*DI + d];
        float xp = xg[(size_t)token*(2*DI) + d];
        float bm = Bm[(size_t)token*(DI*DS) + d*DS + n];
        float cm = Cm[(size_t)token*(DI*DS) + d*DS + n];
        float a = __expf(dv*Aneg);
        h = a*h + (dv*bm)*xp;
        float yv = cm*h;
        yv += __shfl_xor_sync(0xffffffffu, yv, 1);
        yv += __shfl_xor_sync(0xffffffffu, yv, 2);
        yv += __shfl_xor_sync(0xffffffffu, yv, 4);
        yv += __shfl_xor_sync(0xffffffffu, yv, 8);
        if (n == 0) {
            float g = xg[(size_t)token*(2*DI) + DI + d];
            float sg = g / (1.0f + __expf(-g));
            float val = (yv + Dval*xp)*sg;
            __nv_bfloat16 hh, ll; split_bf16(val, hh, ll);
            yh[(size_t)token*DI + d] = hh;
            yl[(size_t)token*DI + d] = ll;
        }
    }
}

// ---------------- host ----------------
template<int EPI, bool OBF>
static void launch_hgemm(const __nv_bfloat16* Ah, const __nv_bfloat16* Al,
                         const __nv_bfloat16* Bh, const __nv_bfloat16* Bl,
                         int K, int N, const float* bias, const float* add,
                         float* outf, __nv_bfloat16* oh, __nv_bfloat16* ol)
{
    cudaFuncSetAttribute(hgemm<EPI,OBF>, cudaFuncAttributeMaxDynamicSharedMemorySize, SMEM_B);
    hgemm<EPI,OBF><<<dim3(MTOK/BM, N/BN), 256, SMEM_B>>>(Ah, Al, Bh, Bl, K, N,
                                                          bias, add, outf, oh, ol);
}

extern "C" void kernel_launch(void* const* d_in, const int* in_sizes, int n_in,
                              void* d_out, int out_size)
{
    const float* x      = (const float*)d_in[0];
    const float* ln1_g  = (const float*)d_in[1];
    const float* ln1_b  = (const float*)d_in[2];
    const float* W_in   = (const float*)d_in[3];
    const float* b_in   = (const float*)d_in[4];
    const float* conv_w = (const float*)d_in[5];
    const float* conv_b = (const float*)d_in[6];
    const float* A_log  = (const float*)d_in[7];
    const float* W_B    = (const float*)d_in[8];
    const float* b_B    = (const float*)d_in[9];
    const float* W_C    = (const float*)d_in[10];
    const float* b_C    = (const float*)d_in[11];
    const float* Dp     = (const float*)d_in[12];
    const float* W_dt   = (const float*)d_in[13];
    const float* b_dt   = (const float*)d_in[14];
    const float* W_out  = (const float*)d_in[15];
    const float* b_out  = (const float*)d_in[16];
    const float* ln2_g  = (const float*)d_in[17];
    const float* ln2_b  = (const float*)d_in[18];
    const float* W1     = (const float*)d_in[19];
    const float* b1     = (const float*)d_in[20];
    const float* W2     = (const float*)d_in[21];
    const float* b2     = (const float*)d_in[22];
    float* out = (float*)d_out;

    float *xg, *delta, *Bm, *Cm, *x2;
    cudaGetSymbolAddress((void**)&xg, g_xg);
    cudaGetSymbolAddress((void**)&delta, g_delta);
    cudaGetSymbolAddress((void**)&Bm, g_Bm);
    cudaGetSymbolAddress((void**)&Cm, g_Cm);
    cudaGetSymbolAddress((void**)&x2, g_x2);
    __nv_bfloat16 *xnh,*xnl,*xch,*xcl,*yh,*yl,*xn2h,*xn2l,*h1h,*h1l;
    cudaGetSymbolAddress((void**)&xnh, g_xn_h);   cudaGetSymbolAddress((void**)&xnl, g_xn_l);
    cudaGetSymbolAddress((void**)&xch, g_xc_h);   cudaGetSymbolAddress((void**)&xcl, g_xc_l);
    cudaGetSymbolAddress((void**)&yh,  g_y_h);    cudaGetSymbolAddress((void**)&yl,  g_y_l);
    cudaGetSymbolAddress((void**)&xn2h,g_xn2_h);  cudaGetSymbolAddress((void**)&xn2l,g_xn2_l);
    cudaGetSymbolAddress((void**)&h1h, g_h1_h);   cudaGetSymbolAddress((void**)&h1l, g_h1_l);
    __nv_bfloat16 *Winh,*Winl,*Wdth,*Wdtl,*WBh,*WBl,*WCh,*WCl,*Wouth,*Woutl,*W1h,*W1l,*W2h,*W2l;
    cudaGetSymbolAddress((void**)&Winh, g_Win_h); cudaGetSymbolAddress((void**)&Winl, g_Win_l);
    cudaGetSymbolAddress((void**)&Wdth, g_Wdt_h); cudaGetSymbolAddress((void**)&Wdtl, g_Wdt_l);
    cudaGetSymbolAddress((void**)&WBh,  g_WB_h);  cudaGetSymbolAddress((void**)&WBl,  g_WB_l);
    cudaGetSymbolAddress((void**)&WCh,  g_WC_h);  cudaGetSymbolAddress((void**)&WCl,  g_WC_l);
    cudaGetSymbolAddress((void**)&Wouth,g_Wout_h);cudaGetSymbolAddress((void**)&Woutl,g_Wout_l);
    cudaGetSymbolAddress((void**)&W1h,  g_W1_h);  cudaGetSymbolAddress((void**)&W1l,  g_W1_l);
    cudaGetSymbolAddress((void**)&W2h,  g_W2_h);  cudaGetSymbolAddress((void**)&W2l,  g_W2_l);

    dim3 tb(32, 8);
    wtrans<<<dim3((2*DI)/32, DM/32),  tb>>>(W_in,  Winh,  Winl,  DM,  2*DI);
    wtrans<<<dim3(DI/32, DI/32),      tb>>>(W_dt,  Wdth,  Wdtl,  DI,  DI);
    wtrans<<<dim3((DI*DS)/32, DI/32), tb>>>(W_B,   WBh,   WBl,   DI,  DI*DS);
    wtrans<<<dim3((DI*DS)/32, DI/32), tb>>>(W_C,   WCh,   WCl,   DI,  DI*DS);
    wtrans<<<dim3(DM/32, DI/32),      tb>>>(W_out, Wouth, Woutl, DI,  DM);
    wtrans<<<dim3(DFF/32, DM/32),     tb>>>(W1,    W1h,   W1l,   DM,  DFF);
    wtrans<<<dim3(DM/32, DFF/32),     tb>>>(W2,    W2h,   W2l,   DFF, DM);

    // 1) LN1 -> xn pairs
    ln_kernel<<<MTOK, 256>>>(x, ln1_g, ln1_b, xnh, xnl);
    // 2) xg = xn @ W_in + b_in (fp32)
    launch_hgemm<0,false>(xnh, xnl, Winh, Winl, DM, 2*DI, b_in, nullptr, xg, nullptr, nullptr);
    // 3) conv -> xc pairs
    conv_kernel<<<(MTOK*DI)/256, 256>>>(xg, conv_w, conv_b, xch, xcl);
    // 4) delta = sigmoid(xc @ W_dt + b_dt)*0.099 + 0.001
    launch_hgemm<1,false>(xch, xcl, Wdth, Wdtl, DI, DI, b_dt, nullptr, delta, nullptr, nullptr);
    // 5) Bm, Cm
    launch_hgemm<0,false>(xch, xcl, WBh, WBl, DI, DI*DS, b_B, nullptr, Bm, nullptr, nullptr);
    launch_hgemm<0,false>(xch, xcl, WCh, WCl, DI, DI*DS, b_C, nullptr, Cm, nullptr, nullptr);
    // 6) scan -> y pairs
    scan_kernel<<<256, 256>>>(xg, delta, Bm, Cm, A_log, Dp, yh, yl);
    // 7) x2 = x + y @ W_out + b_out
    launch_hgemm<3,false>(yh, yl, Wouth, Woutl, DI, DM, b_out, x, x2, nullptr, nullptr);
    // 8) LN2 -> xn2 pairs
    ln_kernel<<<MTOK, 256>>>(x2, ln2_g, ln2_b, xn2h, xn2l);
    // 9) h1 = gelu(xn2 @ W1 + b1) -> bf16 pairs
    launch_hgemm<2,true>(xn2h, xn2l, W1h, W1l, DM, DFF, b1, nullptr, nullptr, h1h, h1l);
    // 10) out = x2 + h1 @ W2 + b2
    launch_hgemm<3,false>(h1h, h1l, W2h, W2l, DFF, DM, b2, x2, out, nullptr, nullptr);
}

// round 8
// speedup vs baseline: 2.9380x; 1.6945x over previous
#include <cuda_runtime.h>
#include <cuda_bf16.h>
#include <math.h>

#define B_SZ 2
#define SEQ  1024
#define DM   1024
#define DI   2048
#define DS   16
#define DFF  4096
#define MTOK (B_SZ*SEQ)

// ---- GEMM tiling: CTA 128x256, warp 64x64 (2x4 warps), BK=32, 3-stage cp.async ----
#define BM 128
#define BN 256
#define BK 32
#define NSTAGE 3
#define ROWB 80
#define A_SPLIT (BM*ROWB)
#define A_BOTH  (2*A_SPLIT)
#define B_SPLIT (BN*ROWB)
#define B_BOTH  (2*B_SPLIT)
#define STAGE_B (A_BOTH + B_BOTH)
#define SMEM_B  (NSTAGE*STAGE_B)

// ---- fp32 scratch ----
__device__ float g_xg   [MTOK*2*DI];
__device__ float g_delta[MTOK*DI];
__device__ float g_x2   [MTOK*DM];
// ---- bf16 Bm/Cm (single precision is enough for the scan path) ----
__device__ __nv_bfloat16 g_Bm[67108864];
__device__ __nv_bfloat16 g_Cm[67108864];
// ---- bf16 activation pairs ----
__device__ __nv_bfloat16 g_xn_h [MTOK*DM],  g_xn_l [MTOK*DM];
__device__ __nv_bfloat16 g_xc_h [MTOK*DI],  g_xc_l [MTOK*DI];
__device__ __nv_bfloat16 g_y_h  [MTOK*DI],  g_y_l  [MTOK*DI];
__device__ __nv_bfloat16 g_xn2_h[MTOK*DM],  g_xn2_l[MTOK*DM];
__device__ __nv_bfloat16 g_h1_h [MTOK*DFF], g_h1_l [MTOK*DFF];
// ---- bf16 transposed weight pairs [N,K] (WB/WC: hi only used) ----
__device__ __nv_bfloat16 g_Win_h [2*DI*DM],  g_Win_l [2*DI*DM];
__device__ __nv_bfloat16 g_Wdt_h [DI*DI],    g_Wdt_l [DI*DI];
__device__ __nv_bfloat16 g_WB_h  [DI*DI*DS];
__device__ __nv_bfloat16 g_WC_h  [DI*DI*DS];
__device__ __nv_bfloat16 g_Wout_h[DM*DI],    g_Wout_l[DM*DI];
__device__ __nv_bfloat16 g_W1_h  [DFF*DM],   g_W1_l  [DFF*DM];
__device__ __nv_bfloat16 g_W2_h  [DM*DFF],   g_W2_l  [DM*DFF];

// ---------------- helpers ----------------
__device__ __forceinline__ unsigned s2u(const void* p) {
    unsigned a;
    asm("{ .reg .u64 t; cvta.to.shared.u64 t, %1; cvt.u32.u64 %0, t; }" : "=r"(a) : "l"(p));
    return a;
}
__device__ __forceinline__ void cp16(unsigned d, const void* s) {
    asm volatile("cp.async.cg.shared.global [%0], [%1], 16;" :: "r"(d), "l"(s));
}
#define CP_COMMIT() asm volatile("cp.async.commit_group;" ::: "memory")
#define CP_WAIT1()  asm volatile("cp.async.wait_group 1;" ::: "memory")
#define LDSM4(r, addr) \
    asm volatile("ldmatrix.sync.aligned.m8n8.x4.shared.b16 {%0,%1,%2,%3}, [%4];" \
        : "=r"((r)[0]),"=r"((r)[1]),"=r"((r)[2]),"=r"((r)[3]) : "r"(addr))
#define MMA4(d, a, b0v, b1v) \
    asm volatile("mma.sync.aligned.m16n8k16.row.col.f32.bf16.bf16.f32 " \
        "{%0,%1,%2,%3},{%4,%5,%6,%7},{%8,%9},{%0,%1,%2,%3};" \
        : "+f"((d)[0]),"+f"((d)[1]),"+f"((d)[2]),"+f"((d)[3]) \
        : "r"((a)[0]),"r"((a)[1]),"r"((a)[2]),"r"((a)[3]),"r"(b0v),"r"(b1v))

__device__ __forceinline__ void split_bf16(float v, __nv_bfloat16& h, __nv_bfloat16& l) {
    h = __float2bfloat16(v);
    l = __float2bfloat16(v - __bfloat162float(h));
}

// ---------------- epilogue helper ----------------
// OMODE: 0 fp32 ; 1 bf16 hi/lo pair ; 2 bf16 single
template<int EPI, int OMODE>
__device__ __forceinline__ void epi2(int r, int c, float v0, float v1, int N,
    const float* __restrict__ bias, const float* __restrict__ add,
    float* __restrict__ outf, __nv_bfloat16* __restrict__ oh, __nv_bfloat16* __restrict__ ol)
{
    size_t go = (size_t)r*N + c;
    float2 bb = *(const float2*)&bias[c];
    v0 += bb.x; v1 += bb.y;
    if (EPI == 3) { float2 aa = *(const float2*)&add[go]; v0 += aa.x; v1 += aa.y; }
    if (EPI == 1) {
        v0 = 1.0f/(1.0f + expf(-v0))*0.099f + 0.001f;
        v1 = 1.0f/(1.0f + expf(-v1))*0.099f + 0.001f;
    }
    if (EPI == 2) {
        v0 = 0.5f*v0*(1.0f + erff(v0*0.70710678118654752f));
        v1 = 0.5f*v1*(1.0f + erff(v1*0.70710678118654752f));
    }
    if (OMODE == 1) {
        __nv_bfloat16 h0,l0,h1,l1;
        split_bf16(v0,h0,l0); split_bf16(v1,h1,l1);
        *(__nv_bfloat162*)&oh[go] = __nv_bfloat162{h0,h1};
        *(__nv_bfloat162*)&ol[go] = __nv_bfloat162{l0,l1};
    } else if (OMODE == 2) {
        *(__nv_bfloat162*)&oh[go] =
            __nv_bfloat162{__float2bfloat16(v0), __float2bfloat16(v1)};
    } else {
        float2 o; o.x = v0; o.y = v1;
        *(float2*)&outf[go] = o;
    }
}

// ---------------- split HMMA GEMM ----------------
// S3=true: 3-term split-bf16 (Ah·Bh + Ah·Bl + Al·Bh). S3=false: 1-term (Ah·Bh).
template<int EPI, int OMODE, bool S3>
__global__ __launch_bounds__(256, 1)
void hgemm(const __nv_bfloat16* __restrict__ Ah, const __nv_bfloat16* __restrict__ Al,
           const __nv_bfloat16* __restrict__ Bh, const __nv_bfloat16* __restrict__ Bl,
           int K, int N,
           const float* __restrict__ bias, const float* __restrict__ add,
           float* __restrict__ outf,
           __nv_bfloat16* __restrict__ oh, __nv_bfloat16* __restrict__ ol)
{
    extern __shared__ char sm[];
    unsigned sbase = s2u(sm);
    int tid = threadIdx.x, lane = tid & 31, wid = tid >> 5;
    int wm = wid & 1, wn = wid >> 1;
    int crow = blockIdx.x * BM, ccol = blockIdx.y * BN;

    int arow = tid & 127, asp = tid >> 7;
    bool aact = S3 || (asp == 0);
    const __nv_bfloat16* Asrc = (asp ? Al : Ah) + (size_t)(crow + arow)*K;
    unsigned adst = sbase + asp*A_SPLIT + arow*ROWB;
    int brow0 = tid, brow1 = tid + 256;
    bool bact1 = S3;                                  // brow1 always lo-split
    const __nv_bfloat16* Bsrc0 = ((brow0 >> 8) ? Bl : Bh) + (size_t)(ccol + (brow0 & 255))*K;
    const __nv_bfloat16* Bsrc1 = S3 ? Bl + (size_t)(ccol + (brow1 & 255))*K : Bh;
    unsigned bdst0 = sbase + A_BOTH + (brow0 >> 8)*B_SPLIT + (brow0 & 255)*ROWB;
    unsigned bdst1 = sbase + A_BOTH + B_SPLIT + (brow1 & 255)*ROWB;

    float acc[4][8][4];
    #pragma unroll
    for (int i = 0; i < 4; i++)
        #pragma unroll
        for (int j = 0; j < 8; j++)
            #pragma unroll
            for (int q = 0; q < 4; q++) acc[i][j][q] = 0.f;

    const int nk = K / BK;

    #pragma unroll
    for (int st = 0; st < NSTAGE-1; st++) {
        unsigned so = st*STAGE_B;
        #pragma unroll
        for (int c = 0; c < 4; c++) {
            if (aact)  cp16(adst + so + c*16,  Asrc  + st*BK + c*8);
            cp16(bdst0 + so + c*16, Bsrc0 + st*BK + c*8);
            if (bact1) cp16(bdst1 + so + c*16, Bsrc1 + st*BK + c*8);
        }
        CP_COMMIT();
    }

    int rrow = lane & 15, rhalf = lane >> 4;

    for (int i = 0; i < nk; i++) {
        CP_WAIT1();
        __syncthreads();

        int j = i + NSTAGE - 1;
        if (j < nk) {
            unsigned so = (j % NSTAGE)*STAGE_B;
            #pragma unroll
            for (int c = 0; c < 4; c++) {
                if (aact)  cp16(adst + so + c*16,  Asrc  + j*BK + c*8);
                cp16(bdst0 + so + c*16, Bsrc0 + j*BK + c*8);
                if (bact1) cp16(bdst1 + so + c*16, Bsrc1 + j*BK + c*8);
            }
        }
        CP_COMMIT();

        unsigned aST = sbase + (i % NSTAGE)*STAGE_B;
        unsigned bST = aST + A_BOTH;

        #pragma unroll
        for (int ks = 0; ks < 2; ks++) {
            int koff = ks*16;
            unsigned ah[4][4], al_[4][4];
            #pragma unroll
            for (int mt = 0; mt < 4; mt++) {
                unsigned base = aST + (unsigned)(wm*64 + mt*16 + rrow)*ROWB
                              + (unsigned)(koff + rhalf*8)*2;
                LDSM4(ah[mt], base);
                if (S3) LDSM4(al_[mt], base + A_SPLIT);
            }
            #pragma unroll
            for (int p = 0; p < 4; p++) {
                unsigned base = bST + (unsigned)(wn*64 + p*16 + rrow)*ROWB
                              + (unsigned)(koff + rhalf*8)*2;
                unsigned th[4], tl[4];
                LDSM4(th, base);
                if (S3) LDSM4(tl, base + B_SPLIT);
                #pragma unroll
                for (int mt = 0; mt < 4; mt++) {
                    MMA4(acc[mt][2*p],   ah[mt], th[0], th[2]);
                    MMA4(acc[mt][2*p+1], ah[mt], th[1], th[3]);
                    if (S3) {
                        MMA4(acc[mt][2*p],   ah[mt],  tl[0], tl[2]);
                        MMA4(acc[mt][2*p+1], ah[mt],  tl[1], tl[3]);
                        MMA4(acc[mt][2*p],   al_[mt], th[0], th[2]);
                        MMA4(acc[mt][2*p+1], al_[mt], th[1], th[3]);
                    }
                }
            }
        }
        __syncthreads();
    }

    #pragma unroll
    for (int mt = 0; mt < 4; mt++) {
        int r0 = crow + wm*64 + mt*16 + (lane >> 2);
        #pragma unroll
        for (int nt = 0; nt < 8; nt++) {
            int c = ccol + wn*64 + nt*8 + 2*(lane & 3);
            epi2<EPI,OMODE>(r0,     c, acc[mt][nt][0], acc[mt][nt][1], N, bias, add, outf, oh, ol);
            epi2<EPI,OMODE>(r0 + 8, c, acc[mt][nt][2], acc[mt][nt][3], N, bias, add, outf, oh, ol);
        }
    }
}

// ---------------- weight transpose + split (pair) ----------------
__global__ __launch_bounds__(256)
void wtrans(const float* __restrict__ W, __nv_bfloat16* __restrict__ hi,
            __nv_bfloat16* __restrict__ lo, int K, int N)
{
    __shared__ float t[32][33];
    int n0 = blockIdx.x*32, k0 = blockIdx.y*32;
    int tx = threadIdx.x, ty = threadIdx.y;
    #pragma unroll
    for (int i = 0; i < 4; i++)
        t[ty + i*8][tx] = W[(size_t)(k0 + ty + i*8)*N + n0 + tx];
    __syncthreads();
    #pragma unroll
    for (int i = 0; i < 4; i++) {
        int nl = ty + i*8;
        __nv_bfloat16 h, l; split_bf16(t[tx][nl], h, l);
        size_t o = (size_t)(n0 + nl)*K + k0 + tx;
        hi[o] = h; lo[o] = l;
    }
}
// hi-only variant (for WB/WC)
__global__ __launch_bounds__(256)
void wtrans1(const float* __restrict__ W, __nv_bfloat16* __restrict__ hi, int K, int N)
{
    __shared__ float t[32][33];
    int n0 = blockIdx.x*32, k0 = blockIdx.y*32;
    int tx = threadIdx.x, ty = threadIdx.y;
    #pragma unroll
    for (int i = 0; i < 4; i++)
        t[ty + i*8][tx] = W[(size_t)(k0 + ty + i*8)*N + n0 + tx];
    __syncthreads();
    #pragma unroll
    for (int i = 0; i < 4; i++) {
        int nl = ty + i*8;
        hi[(size_t)(n0 + nl)*K + k0 + tx] = __float2bfloat16(t[tx][nl]);
    }
}

// ---------------- LayerNorm -> bf16 pair ----------------
__global__ __launch_bounds__(256)
void ln_kernel(const float* __restrict__ in, const float* __restrict__ g,
               const float* __restrict__ bcoef,
               __nv_bfloat16* __restrict__ oh, __nv_bfloat16* __restrict__ ol)
{
    int row = blockIdx.x, tid = threadIdx.x;
    float4 v = ((const float4*)(in + (size_t)row*DM))[tid];
    __shared__ float red1[8], red2[8];
    float s = v.x + v.y + v.z + v.w;
    #pragma unroll
    for (int o = 16; o > 0; o >>= 1) s += __shfl_xor_sync(0xffffffffu, s, o);
    if ((tid & 31) == 0) red1[tid >> 5] = s;
    __syncthreads();
    float tot = 0.f;
    #pragma unroll
    for (int i = 0; i < 8; i++) tot += red1[i];
    float mean = tot * (1.0f/DM);
    float dx = v.x-mean, dy = v.y-mean, dz = v.z-mean, dw = v.w-mean;
    float sq = dx*dx + dy*dy + dz*dz + dw*dw;
    #pragma unroll
    for (int o = 16; o > 0; o >>= 1) sq += __shfl_xor_sync(0xffffffffu, sq, o);
    if ((tid & 31) == 0) red2[tid >> 5] = sq;
    __syncthreads();
    float tot2 = 0.f;
    #pragma unroll
    for (int i = 0; i < 8; i++) tot2 += red2[i];
    float rstd = rsqrtf(tot2*(1.0f/DM) + 1e-5f);
    float4 gg = ((const float4*)g)[tid];
    float4 bb = ((const float4*)bcoef)[tid];
    float o0 = dx*rstd*gg.x+bb.x, o1 = dy*rstd*gg.y+bb.y;
    float o2 = dz*rstd*gg.z+bb.z, o3 = dw*rstd*gg.w+bb.w;
    __nv_bfloat16 h0,l0,h1,l1,h2,l2,h3,l3;
    split_bf16(o0,h0,l0); split_bf16(o1,h1,l1); split_bf16(o2,h2,l2); split_bf16(o3,h3,l3);
    __nv_bfloat162* ph = (__nv_bfloat162*)(oh + (size_t)row*DM);
    __nv_bfloat162* pl = (__nv_bfloat162*)(ol + (size_t)row*DM);
    ph[tid*2] = __nv_bfloat162{h0,h1}; ph[tid*2+1] = __nv_bfloat162{h2,h3};
    pl[tid*2] = __nv_bfloat162{l0,l1}; pl[tid*2+1] = __nv_bfloat162{l2,l3};
}

// ---------------- causal depthwise conv -> bf16 pair ----------------
__global__ __launch_bounds__(256)
void conv_kernel(const float* __restrict__ xg, const float* __restrict__ cw,
                 const float* __restrict__ cb,
                 __nv_bfloat16* __restrict__ oh, __nv_bfloat16* __restrict__ ol)
{
    int idx = blockIdx.x*blockDim.x + threadIdx.x;
    int d = idx & (DI-1);
    int token = idx >> 11;
    int t = token & (SEQ-1);
    float acc = cb[d];
    #pragma unroll
    for (int k = 0; k < 4; k++) {
        int ts = t - 3 + k;
        if (ts >= 0) acc += xg[(size_t)(token-3+k)*(2*DI) + d] * cw[d*4+k];
    }
    __nv_bfloat16 h, l; split_bf16(acc, h, l);
    oh[idx] = h; ol[idx] = l;
}

// ---------------- selective scan (bf16 Bm/Cm) -> bf16 pair ----------------
__global__ __launch_bounds__(256)
void scan_kernel(const float* __restrict__ xg, const float* __restrict__ delta,
                 const __nv_bfloat16* __restrict__ Bm, const __nv_bfloat16* __restrict__ Cm,
                 const float* __restrict__ A_log, const float* __restrict__ Dp,
                 __nv_bfloat16* __restrict__ yh, __nv_bfloat16* __restrict__ yl)
{
    int tid = blockIdx.x*blockDim.x + threadIdx.x;
    int n = tid & (DS-1);
    int d = (tid >> 4) & (DI-1);
    int b = tid >> 15;
    float Aneg = -expf(A_log[d*DS + n]);
    float Dval = Dp[d];
    float h = 0.f;
    int base_tok = b*SEQ;
    for (int t = 0; t < SEQ; ++t) {
        int token = base_tok + t;
        float dv = delta[(size_t)token*DI + d];
        float xp = xg[(size_t)token*(2*DI) + d];
        float bm = __bfloat162float(Bm[(size_t)token*(DI*DS) + d*DS + n]);
        float cm = __bfloat162float(Cm[(size_t)token*(DI*DS) + d*DS + n]);
        float a = __expf(dv*Aneg);
        h = a*h + (dv*bm)*xp;
        float yv = cm*h;
        yv += __shfl_xor_sync(0xffffffffu, yv, 1);
        yv += __shfl_xor_sync(0xffffffffu, yv, 2);
        yv += __shfl_xor_sync(0xffffffffu, yv, 4);
        yv += __shfl_xor_sync(0xffffffffu, yv, 8);
        if (n == 0) {
            float g = xg[(size_t)token*(2*DI) + DI + d];
            float sg = g / (1.0f + __expf(-g));
            float val = (yv + Dval*xp)*sg;
            __nv_bfloat16 hh, ll; split_bf16(val, hh, ll);
            yh[(size_t)token*DI + d] = hh;
            yl[(size_t)token*DI + d] = ll;
        }
    }
}

// ---------------- host ----------------
template<int EPI, int OMODE, bool S3>
static void launch_hgemm(const __nv_bfloat16* Ah, const __nv_bfloat16* Al,
                         const __nv_bfloat16* Bh, const __nv_bfloat16* Bl,
                         int K, int N, const float* bias, const float* add,
                         float* outf, __nv_bfloat16* oh, __nv_bfloat16* ol)
{
    cudaFuncSetAttribute(hgemm<EPI,OMODE,S3>, cudaFuncAttributeMaxDynamicSharedMemorySize, SMEM_B);
    hgemm<EPI,OMODE,S3><<<dim3(MTOK/BM, N/BN), 256, SMEM_B>>>(Ah, Al, Bh, Bl, K, N,
                                                               bias, add, outf, oh, ol);
}

extern "C" void kernel_launch(void* const* d_in, const int* in_sizes, int n_in,
                              void* d_out, int out_size)
{
    const float* x      = (const float*)d_in[0];
    const float* ln1_g  = (const float*)d_in[1];
    const float* ln1_b  = (const float*)d_in[2];
    const float* W_in   = (const float*)d_in[3];
    const float* b_in   = (const float*)d_in[4];
    const float* conv_w = (const float*)d_in[5];
    const float* conv_b = (const float*)d_in[6];
    const float* A_log  = (const float*)d_in[7];
    const float* W_B    = (const float*)d_in[8];
    const float* b_B    = (const float*)d_in[9];
    const float* W_C    = (const float*)d_in[10];
    const float* b_C    = (const float*)d_in[11];
    const float* Dp     = (const float*)d_in[12];
    const float* W_dt   = (const float*)d_in[13];
    const float* b_dt   = (const float*)d_in[14];
    const float* W_out  = (const float*)d_in[15];
    const float* b_out  = (const float*)d_in[16];
    const float* ln2_g  = (const float*)d_in[17];
    const float* ln2_b  = (const float*)d_in[18];
    const float* W1     = (const float*)d_in[19];
    const float* b1     = (const float*)d_in[20];
    const float* W2     = (const float*)d_in[21];
    const float* b2     = (const float*)d_in[22];
    float* out = (float*)d_out;

    float *xg, *delta, *x2;
    cudaGetSymbolAddress((void**)&xg, g_xg);
    cudaGetSymbolAddress((void**)&delta, g_delta);
    cudaGetSymbolAddress((void**)&x2, g_x2);
    __nv_bfloat16 *Bm, *Cm;
    cudaGetSymbolAddress((void**)&Bm, g_Bm);
    cudaGetSymbolAddress((void**)&Cm, g_Cm);
    __nv_bfloat16 *xnh,*xnl,*xch,*xcl,*yh,*yl,*xn2h,*xn2l,*h1h,*h1l;
    cudaGetSymbolAddress((void**)&xnh, g_xn_h);   cudaGetSymbolAddress((void**)&xnl, g_xn_l);
    cudaGetSymbolAddress((void**)&xch, g_xc_h);   cudaGetSymbolAddress((void**)&xcl, g_xc_l);
    cudaGetSymbolAddress((void**)&yh,  g_y_h);    cudaGetSymbolAddress((void**)&yl,  g_y_l);
    cudaGetSymbolAddress((void**)&xn2h,g_xn2_h);  cudaGetSymbolAddress((void**)&xn2l,g_xn2_l);
    cudaGetSymbolAddress((void**)&h1h, g_h1_h);   cudaGetSymbolAddress((void**)&h1l, g_h1_l);
    __nv_bfloat16 *Winh,*Winl,*Wdth,*Wdtl,*WBh,*WCh,*Wouth,*Woutl,*W1h,*W1l,*W2h,*W2l;
    cudaGetSymbolAddress((void**)&Winh, g_Win_h); cudaGetSymbolAddress((void**)&Winl, g_Win_l);
    cudaGetSymbolAddress((void**)&Wdth, g_Wdt_h); cudaGetSymbolAddress((void**)&Wdtl, g_Wdt_l);
    cudaGetSymbolAddress((void**)&WBh,  g_WB_h);
    cudaGetSymbolAddress((void**)&WCh,  g_WC_h);
    cudaGetSymbolAddress((void**)&Wouth,g_Wout_h);cudaGetSymbolAddress((void**)&Woutl,g_Wout_l);
    cudaGetSymbolAddress((void**)&W1h,  g_W1_h);  cudaGetSymbolAddress((void**)&W1l,  g_W1_l);
    cudaGetSymbolAddress((void**)&W2h,  g_W2_h);  cudaGetSymbolAddress((void**)&W2l,  g_W2_l);

    dim3 tb(32, 8);
    wtrans <<<dim3((2*DI)/32, DM/32),  tb>>>(W_in,  Winh,  Winl,  DM,  2*DI);
    wtrans <<<dim3(DI/32, DI/32),      tb>>>(W_dt,  Wdth,  Wdtl,  DI,  DI);
    wtrans1<<<dim3((DI*DS)/32, DI/32), tb>>>(W_B,   WBh,   DI,  DI*DS);
    wtrans1<<<dim3((DI*DS)/32, DI/32), tb>>>(W_C,   WCh,   DI,  DI*DS);
    wtrans <<<dim3(DM/32, DI/32),      tb>>>(W_out, Wouth, Woutl, DI,  DM);
    wtrans <<<dim3(DFF/32, DM/32),     tb>>>(W1,    W1h,   W1l,   DM,  DFF);
    wtrans <<<dim3(DM/32, DFF/32),     tb>>>(W2,    W2h,   W2l,   DFF, DM);

    // 1) LN1 -> xn pairs
    ln_kernel<<<MTOK, 256>>>(x, ln1_g, ln1_b, xnh, xnl);
    // 2) xg = xn @ W_in + b_in (3-term, fp32)
    launch_hgemm<0,0,true>(xnh, xnl, Winh, Winl, DM, 2*DI, b_in, nullptr, xg, nullptr, nullptr);
    // 3) conv -> xc pairs
    conv_kernel<<<(MTOK*DI)/256, 256>>>(xg, conv_w, conv_b, xch, xcl);
    // 4) delta (3-term, fp32)
    launch_hgemm<1,0,true>(xch, xcl, Wdth, Wdtl, DI, DI, b_dt, nullptr, delta, nullptr, nullptr);
    // 5) Bm, Cm (1-term bf16, bf16 output)
    launch_hgemm<0,2,false>(xch, nullptr, WBh, nullptr, DI, DI*DS, b_B, nullptr, nullptr, Bm, nullptr);
    launch_hgemm<0,2,false>(xch, nullptr, WCh, nullptr, DI, DI*DS, b_C, nullptr, nullptr, Cm, nullptr);
    // 6) scan -> y pairs
    scan_kernel<<<256, 256>>>(xg, delta, Bm, Cm, A_log, Dp, yh, yl);
    // 7) x2 = x + y @ W_out + b_out (3-term, fp32)
    launch_hgemm<3,0,true>(yh, yl, Wouth, Woutl, DI, DM, b_out, x, x2, nullptr, nullptr);
    // 8) LN2 -> xn2 pairs
    ln_kernel<<<MTOK, 256>>>(x2, ln2_g, ln2_b, xn2h, xn2l);
    // 9) h1 = gelu(xn2 @ W1 + b1) (3-term) -> bf16 pairs
    launch_hgemm<2,1,true>(xn2h, xn2l, W1h, W1l, DM, DFF, b1, nullptr, nullptr, h1h, h1l);
    // 10) out = x2 + h1 @ W2 + b2 (3-term, fp32)
    launch_hgemm<3,0,true>(h1h, h1l, W2h, W2l, DFF, DM, b2, x2, out, nullptr, nullptr);
}

// round 9
// speedup vs baseline: 3.1811x; 1.0827x over previous
#include <cuda_runtime.h>
#include <cuda_bf16.h>
#include <cuda_fp8.h>
#include <math.h>

#define B_SZ 2
#define SEQ  1024
#define DM   1024
#define DI   2048
#define DS   16
#define DFF  4096
#define MTOK (B_SZ*SEQ)

// ---- bf16 GEMM tiling: CTA 128x256, warp 64x64 (2x4), BK=32, 3-stage ----
#define BM 128
#define BN 256
#define BK 32
#define NSTAGE 3
#define ROWB 80
#define A_SPLIT (BM*ROWB)
#define A_BOTH  (2*A_SPLIT)
#define B_SPLIT (BN*ROWB)
#define B_BOTH  (2*B_SPLIT)
#define STAGE_B (A_BOTH + B_BOTH)
#define SMEM_B  (NSTAGE*STAGE_B)

// ---- fp8 GEMM tiling: CTA 128x256, warp 64x64, FBK=64, 3-stage ----
#define FBK 64
#define FROWB 80
#define F_A (BM*FROWB)
#define F_B (BN*FROWB)
#define F_STAGE (F_A + F_B)
#define F_SMEM (NSTAGE*F_STAGE)

// ---- fp32 scratch ----
__device__ float g_xg   [MTOK*2*DI];
__device__ float g_delta[MTOK*DI];
__device__ float g_x2   [MTOK*DM];
// ---- bf16 Bm/Cm ----
__device__ __nv_bfloat16 g_Bm[67108864];
__device__ __nv_bfloat16 g_Cm[67108864];
// ---- bf16 activation pairs ----
__device__ __nv_bfloat16 g_xn_h [MTOK*DM],  g_xn_l [MTOK*DM];
__device__ __nv_bfloat16 g_xc_h [MTOK*DI],  g_xc_l [MTOK*DI];
__device__ __nv_bfloat16 g_y_h  [MTOK*DI],  g_y_l  [MTOK*DI];
__device__ __nv_bfloat16 g_xn2_h[MTOK*DM],  g_xn2_l[MTOK*DM];
__device__ __nv_bfloat16 g_h1_h [MTOK*DFF], g_h1_l [MTOK*DFF];
// ---- fp8 operands for WB/WC GEMMs ----
__device__ __nv_fp8_e4m3 g_xc8 [MTOK*DI];
__device__ __nv_fp8_e4m3 g_WB8 [DI*DI*DS];
__device__ __nv_fp8_e4m3 g_WC8 [DI*DI*DS];
// ---- bf16 transposed weight pairs [N,K] ----
__device__ __nv_bfloat16 g_Win_h [2*DI*DM],  g_Win_l [2*DI*DM];
__device__ __nv_bfloat16 g_Wdt_h [DI*DI],    g_Wdt_l [DI*DI];
__device__ __nv_bfloat16 g_Wout_h[DM*DI],    g_Wout_l[DM*DI];
__device__ __nv_bfloat16 g_W1_h  [DFF*DM],   g_W1_l  [DFF*DM];
__device__ __nv_bfloat16 g_W2_h  [DM*DFF],   g_W2_l  [DM*DFF];

// ---------------- helpers ----------------
__device__ __forceinline__ unsigned s2u(const void* p) {
    unsigned a;
    asm("{ .reg .u64 t; cvta.to.shared.u64 t, %1; cvt.u32.u64 %0, t; }" : "=r"(a) : "l"(p));
    return a;
}
__device__ __forceinline__ void cp16(unsigned d, const void* s) {
    asm volatile("cp.async.cg.shared.global [%0], [%1], 16;" :: "r"(d), "l"(s));
}
#define CP_COMMIT() asm volatile("cp.async.commit_group;" ::: "memory")
#define CP_WAIT1()  asm volatile("cp.async.wait_group 1;" ::: "memory")
#define LDSM4(r, addr) \
    asm volatile("ldmatrix.sync.aligned.m8n8.x4.shared.b16 {%0,%1,%2,%3}, [%4];" \
        : "=r"((r)[0]),"=r"((r)[1]),"=r"((r)[2]),"=r"((r)[3]) : "r"(addr))
#define MMA4(d, a, b0v, b1v) \
    asm volatile("mma.sync.aligned.m16n8k16.row.col.f32.bf16.bf16.f32 " \
        "{%0,%1,%2,%3},{%4,%5,%6,%7},{%8,%9},{%0,%1,%2,%3};" \
        : "+f"((d)[0]),"+f"((d)[1]),"+f"((d)[2]),"+f"((d)[3]) \
        : "r"((a)[0]),"r"((a)[1]),"r"((a)[2]),"r"((a)[3]),"r"(b0v),"r"(b1v))
#define MMA8(d, a, b0v, b1v) \
    asm volatile("mma.sync.aligned.m16n8k32.row.col.f32.e4m3.e4m3.f32 " \
        "{%0,%1,%2,%3},{%4,%5,%6,%7},{%8,%9},{%0,%1,%2,%3};" \
        : "+f"((d)[0]),"+f"((d)[1]),"+f"((d)[2]),"+f"((d)[3]) \
        : "r"((a)[0]),"r"((a)[1]),"r"((a)[2]),"r"((a)[3]),"r"(b0v),"r"(b1v))

__device__ __forceinline__ void split_bf16(float v, __nv_bfloat16& h, __nv_bfloat16& l) {
    h = __float2bfloat16(v);
    l = __float2bfloat16(v - __bfloat162float(h));
}

// ---------------- epilogue helper ----------------
template<int EPI, int OMODE>
__device__ __forceinline__ void epi2(int r, int c, float v0, float v1, int N,
    const float* __restrict__ bias, const float* __restrict__ add,
    float* __restrict__ outf, __nv_bfloat16* __restrict__ oh, __nv_bfloat16* __restrict__ ol)
{
    size_t go = (size_t)r*N + c;
    float2 bb = *(const float2*)&bias[c];
    v0 += bb.x; v1 += bb.y;
    if (EPI == 3) { float2 aa = *(const float2*)&add[go]; v0 += aa.x; v1 += aa.y; }
    if (EPI == 1) {
        v0 = 1.0f/(1.0f + expf(-v0))*0.099f + 0.001f;
        v1 = 1.0f/(1.0f + expf(-v1))*0.099f + 0.001f;
    }
    if (EPI == 2) {
        v0 = 0.5f*v0*(1.0f + erff(v0*0.70710678118654752f));
        v1 = 0.5f*v1*(1.0f + erff(v1*0.70710678118654752f));
    }
    if (OMODE == 1) {
        __nv_bfloat16 h0,l0,h1,l1;
        split_bf16(v0,h0,l0); split_bf16(v1,h1,l1);
        *(__nv_bfloat162*)&oh[go] = __nv_bfloat162{h0,h1};
        *(__nv_bfloat162*)&ol[go] = __nv_bfloat162{l0,l1};
    } else if (OMODE == 2) {
        *(__nv_bfloat162*)&oh[go] =
            __nv_bfloat162{__float2bfloat16(v0), __float2bfloat16(v1)};
    } else {
        float2 o; o.x = v0; o.y = v1;
        *(float2*)&outf[go] = o;
    }
}

// ---------------- bf16 split HMMA GEMM (3-term) ----------------
template<int EPI, int OMODE>
__global__ __launch_bounds__(256, 1)
void hgemm(const __nv_bfloat16* __restrict__ Ah, const __nv_bfloat16* __restrict__ Al,
           const __nv_bfloat16* __restrict__ Bh, const __nv_bfloat16* __restrict__ Bl,
           int K, int N,
           const float* __restrict__ bias, const float* __restrict__ add,
           float* __restrict__ outf,
           __nv_bfloat16* __restrict__ oh, __nv_bfloat16* __restrict__ ol)
{
    extern __shared__ char sm[];
    unsigned sbase = s2u(sm);
    int tid = threadIdx.x, lane = tid & 31, wid = tid >> 5;
    int wm = wid & 1, wn = wid >> 1;
    int crow = blockIdx.x * BM, ccol = blockIdx.y * BN;

    int arow = tid & 127, asp = tid >> 7;
    const __nv_bfloat16* Asrc = (asp ? Al : Ah) + (size_t)(crow + arow)*K;
    unsigned adst = sbase + asp*A_SPLIT + arow*ROWB;
    int brow0 = tid, brow1 = tid + 256;
    const __nv_bfloat16* Bsrc0 = ((brow0 >> 8) ? Bl : Bh) + (size_t)(ccol + (brow0 & 255))*K;
    const __nv_bfloat16* Bsrc1 = Bl + (size_t)(ccol + (brow1 & 255))*K;
    unsigned bdst0 = sbase + A_BOTH + (brow0 >> 8)*B_SPLIT + (brow0 & 255)*ROWB;
    unsigned bdst1 = sbase + A_BOTH + B_SPLIT + (brow1 & 255)*ROWB;

    float acc[4][8][4];
    #pragma unroll
    for (int i = 0; i < 4; i++)
        #pragma unroll
        for (int j = 0; j < 8; j++)
            #pragma unroll
            for (int q = 0; q < 4; q++) acc[i][j][q] = 0.f;

    const int nk = K / BK;

    #pragma unroll
    for (int st = 0; st < NSTAGE-1; st++) {
        unsigned so = st*STAGE_B;
        #pragma unroll
        for (int c = 0; c < 4; c++) {
            cp16(adst + so + c*16,  Asrc  + st*BK + c*8);
            cp16(bdst0 + so + c*16, Bsrc0 + st*BK + c*8);
            cp16(bdst1 + so + c*16, Bsrc1 + st*BK + c*8);
        }
        CP_COMMIT();
    }

    int rrow = lane & 15, rhalf = lane >> 4;

    for (int i = 0; i < nk; i++) {
        CP_WAIT1();
        __syncthreads();

        int j = i + NSTAGE - 1;
        if (j < nk) {
            unsigned so = (j % NSTAGE)*STAGE_B;
            #pragma unroll
            for (int c = 0; c < 4; c++) {
                cp16(adst + so + c*16,  Asrc  + j*BK + c*8);
                cp16(bdst0 + so + c*16, Bsrc0 + j*BK + c*8);
                cp16(bdst1 + so + c*16, Bsrc1 + j*BK + c*8);
            }
        }
        CP_COMMIT();

        unsigned aST = sbase + (i % NSTAGE)*STAGE_B;
        unsigned bST = aST + A_BOTH;

        #pragma unroll
        for (int ks = 0; ks < 2; ks++) {
            int koff = ks*16;
            unsigned ah[4][4], al_[4][4];
            #pragma unroll
            for (int mt = 0; mt < 4; mt++) {
                unsigned base = aST + (unsigned)(wm*64 + mt*16 + rrow)*ROWB
                              + (unsigned)(koff + rhalf*8)*2;
                LDSM4(ah[mt], base);
                LDSM4(al_[mt], base + A_SPLIT);
            }
            #pragma unroll
            for (int p = 0; p < 4; p++) {
                unsigned base = bST + (unsigned)(wn*64 + p*16 + rrow)*ROWB
                              + (unsigned)(koff + rhalf*8)*2;
                unsigned th[4], tl[4];
                LDSM4(th, base);
                LDSM4(tl, base + B_SPLIT);
                #pragma unroll
                for (int mt = 0; mt < 4; mt++) {
                    MMA4(acc[mt][2*p],   ah[mt],  th[0], th[2]);
                    MMA4(acc[mt][2*p+1], ah[mt],  th[1], th[3]);
                    MMA4(acc[mt][2*p],   ah[mt],  tl[0], tl[2]);
                    MMA4(acc[mt][2*p+1], ah[mt],  tl[1], tl[3]);
                    MMA4(acc[mt][2*p],   al_[mt], th[0], th[2]);
                    MMA4(acc[mt][2*p+1], al_[mt], th[1], th[3]);
                }
            }
        }
    }

    #pragma unroll
    for (int mt = 0; mt < 4; mt++) {
        int r0 = crow + wm*64 + mt*16 + (lane >> 2);
        #pragma unroll
        for (int nt = 0; nt < 8; nt++) {
            int c = ccol + wn*64 + nt*8 + 2*(lane & 3);
            epi2<EPI,OMODE>(r0,     c, acc[mt][nt][0], acc[mt][nt][1], N, bias, add, outf, oh, ol);
            epi2<EPI,OMODE>(r0 + 8, c, acc[mt][nt][2], acc[mt][nt][3], N, bias, add, outf, oh, ol);
        }
    }
}

// ---------------- fp8 e4m3 GEMM (1-term, k32 MMA) -> bf16 out ----------------
__global__ __launch_bounds__(256, 1)
void fgemm(const __nv_fp8_e4m3* __restrict__ A8, const __nv_fp8_e4m3* __restrict__ B8,
           int K, int N, const float* __restrict__ bias, __nv_bfloat16* __restrict__ oh)
{
    extern __shared__ char sm[];
    unsigned sbase = s2u(sm);
    int tid = threadIdx.x, lane = tid & 31, wid = tid >> 5;
    int wm = wid & 1, wn = wid >> 1;
    int crow = blockIdx.x * BM, ccol = blockIdx.y * BN;

    bool isA = tid < 128;
    int ar = tid & 127;
    const char* Asrc  = (const char*)(A8 + (size_t)(crow + ar)*K);
    const char* Bsrc0 = (const char*)(B8 + (size_t)(ccol + ar)*K);
    const char* Bsrc1 = (const char*)(B8 + (size_t)(ccol + ar + 128)*K);
    unsigned adst  = sbase + ar*FROWB;
    unsigned bdst0 = sbase + F_A + ar*FROWB;
    unsigned bdst1 = sbase + F_A + (ar + 128)*FROWB;

    float acc[4][8][4];
    #pragma unroll
    for (int i = 0; i < 4; i++)
        #pragma unroll
        for (int j = 0; j < 8; j++)
            #pragma unroll
            for (int q = 0; q < 4; q++) acc[i][j][q] = 0.f;

    const int nk = K / FBK;

    #pragma unroll
    for (int st = 0; st < NSTAGE-1; st++) {
        unsigned so = st*F_STAGE;
        #pragma unroll
        for (int c = 0; c < 4; c++) {
            if (isA) cp16(adst + so + c*16, Asrc + st*FBK + c*16);
            else {
                cp16(bdst0 + so + c*16, Bsrc0 + st*FBK + c*16);
                cp16(bdst1 + so + c*16, Bsrc1 + st*FBK + c*16);
            }
        }
        CP_COMMIT();
    }

    int rrow = lane & 15, rhalf = lane >> 4;

    for (int i = 0; i < nk; i++) {
        CP_WAIT1();
        __syncthreads();

        int j = i + NSTAGE - 1;
        if (j < nk) {
            unsigned so = (j % NSTAGE)*F_STAGE;
            #pragma unroll
            for (int c = 0; c < 4; c++) {
                if (isA) cp16(adst + so + c*16, Asrc + j*FBK + c*16);
                else {
                    cp16(bdst0 + so + c*16, Bsrc0 + j*FBK + c*16);
                    cp16(bdst1 + so + c*16, Bsrc1 + j*FBK + c*16);
                }
            }
        }
        CP_COMMIT();

        unsigned aST = sbase + (i % NSTAGE)*F_STAGE;
        unsigned bST = aST + F_A;

        #pragma unroll
        for (int ks = 0; ks < 2; ks++) {
            int koff = ks*32;
            unsigned ah[4][4];
            #pragma unroll
            for (int mt = 0; mt < 4; mt++) {
                unsigned base = aST + (unsigned)(wm*64 + mt*16 + rrow)*FROWB
                              + (unsigned)(koff + rhalf*16);
                LDSM4(ah[mt], base);
            }
            #pragma unroll
            for (int p = 0; p < 4; p++) {
                unsigned base = bST + (unsigned)(wn*64 + p*16 + rrow)*FROWB
                              + (unsigned)(koff + rhalf*16);
                unsigned th[4];
                LDSM4(th, base);
                #pragma unroll
                for (int mt = 0; mt < 4; mt++) {
                    MMA8(acc[mt][2*p],   ah[mt], th[0], th[2]);
                    MMA8(acc[mt][2*p+1], ah[mt], th[1], th[3]);
                }
            }
        }
    }

    #pragma unroll
    for (int mt = 0; mt < 4; mt++) {
        int r0 = crow + wm*64 + mt*16 + (lane >> 2);
        #pragma unroll
        for (int nt = 0; nt < 8; nt++) {
            int c = ccol + wn*64 + nt*8 + 2*(lane & 3);
            epi2<0,2>(r0,     c, acc[mt][nt][0], acc[mt][nt][1], N, bias, nullptr, nullptr, oh, nullptr);
            epi2<0,2>(r0 + 8, c, acc[mt][nt][2], acc[mt][nt][3], N, bias, nullptr, nullptr, oh, nullptr);
        }
    }
}

// ---------------- weight transpose kernels ----------------
__global__ __launch_bounds__(256)
void wtrans(const float* __restrict__ W, __nv_bfloat16* __restrict__ hi,
            __nv_bfloat16* __restrict__ lo, int K, int N)
{
    __shared__ float t[32][33];
    int n0 = blockIdx.x*32, k0 = blockIdx.y*32;
    int tx = threadIdx.x, ty = threadIdx.y;
    #pragma unroll
    for (int i = 0; i < 4; i++)
        t[ty + i*8][tx] = W[(size_t)(k0 + ty + i*8)*N + n0 + tx];
    __syncthreads();
    #pragma unroll
    for (int i = 0; i < 4; i++) {
        int nl = ty + i*8;
        __nv_bfloat16 h, l; split_bf16(t[tx][nl], h, l);
        size_t o = (size_t)(n0 + nl)*K + k0 + tx;
        hi[o] = h; lo[o] = l;
    }
}
__global__ __launch_bounds__(256)
void wtrans8(const float* __restrict__ W, __nv_fp8_e4m3* __restrict__ o8, int K, int N)
{
    __shared__ float t[32][33];
    int n0 = blockIdx.x*32, k0 = blockIdx.y*32;
    int tx = threadIdx.x, ty = threadIdx.y;
    #pragma unroll
    for (int i = 0; i < 4; i++)
        t[ty + i*8][tx] = W[(size_t)(k0 + ty + i*8)*N + n0 + tx];
    __syncthreads();
    #pragma unroll
    for (int i = 0; i < 4; i++) {
        int nl = ty + i*8;
        o8[(size_t)(n0 + nl)*K + k0 + tx] = __nv_fp8_e4m3(t[tx][nl]);
    }
}

// ---------------- LayerNorm -> bf16 pair ----------------
__global__ __launch_bounds__(256)
void ln_kernel(const float* __restrict__ in, const float* __restrict__ g,
               const float* __restrict__ bcoef,
               __nv_bfloat16* __restrict__ oh, __nv_bfloat16* __restrict__ ol)
{
    int row = blockIdx.x, tid = threadIdx.x;
    float4 v = ((const float4*)(in + (size_t)row*DM))[tid];
    __shared__ float red1[8], red2[8];
    float s = v.x + v.y + v.z + v.w;
    #pragma unroll
    for (int o = 16; o > 0; o >>= 1) s += __shfl_xor_sync(0xffffffffu, s, o);
    if ((tid & 31) == 0) red1[tid >> 5] = s;
    __syncthreads();
    float tot = 0.f;
    #pragma unroll
    for (int i = 0; i < 8; i++) tot += red1[i];
    float mean = tot * (1.0f/DM);
    float dx = v.x-mean, dy = v.y-mean, dz = v.z-mean, dw = v.w-mean;
    float sq = dx*dx + dy*dy + dz*dz + dw*dw;
    #pragma unroll
    for (int o = 16; o > 0; o >>= 1) sq += __shfl_xor_sync(0xffffffffu, sq, o);
    if ((tid & 31) == 0) red2[tid >> 5] = sq;
    __syncthreads();
    float tot2 = 0.f;
    #pragma unroll
    for (int i = 0; i < 8; i++) tot2 += red2[i];
    float rstd = rsqrtf(tot2*(1.0f/DM) + 1e-5f);
    float4 gg = ((const float4*)g)[tid];
    float4 bb = ((const float4*)bcoef)[tid];
    float o0 = dx*rstd*gg.x+bb.x, o1 = dy*rstd*gg.y+bb.y;
    float o2 = dz*rstd*gg.z+bb.z, o3 = dw*rstd*gg.w+bb.w;
    __nv_bfloat16 h0,l0,h1,l1,h2,l2,h3,l3;
    split_bf16(o0,h0,l0); split_bf16(o1,h1,l1); split_bf16(o2,h2,l2); split_bf16(o3,h3,l3);
    __nv_bfloat162* ph = (__nv_bfloat162*)(oh + (size_t)row*DM);
    __nv_bfloat162* pl = (__nv_bfloat162*)(ol + (size_t)row*DM);
    ph[tid*2] = __nv_bfloat162{h0,h1}; ph[tid*2+1] = __nv_bfloat162{h2,h3};
    pl[tid*2] = __nv_bfloat162{l0,l1}; pl[tid*2+1] = __nv_bfloat162{l2,l3};
}

// ---------------- conv -> bf16 pair + fp8 ----------------
__global__ __launch_bounds__(256)
void conv_kernel(const float* __restrict__ xg, const float* __restrict__ cw,
                 const float* __restrict__ cb,
                 __nv_bfloat16* __restrict__ oh, __nv_bfloat16* __restrict__ ol,
                 __nv_fp8_e4m3* __restrict__ o8)
{
    int idx = blockIdx.x*blockDim.x + threadIdx.x;
    int d = idx & (DI-1);
    int token = idx >> 11;
    int t = token & (SEQ-1);
    float acc = cb[d];
    #pragma unroll
    for (int k = 0; k < 4; k++) {
        int ts = t - 3 + k;
        if (ts >= 0) acc += xg[(size_t)(token-3+k)*(2*DI) + d] * cw[d*4+k];
    }
    __nv_bfloat16 h, l; split_bf16(acc, h, l);
    oh[idx] = h; ol[idx] = l;
    o8[idx] = __nv_fp8_e4m3(acc);
}

// ---------------- selective scan -> bf16 pair ----------------
__global__ __launch_bounds__(256)
void scan_kernel(const float* __restrict__ xg, const float* __restrict__ delta,
                 const __nv_bfloat16* __restrict__ Bm, const __nv_bfloat16* __restrict__ Cm,
                 const float* __restrict__ A_log, const float* __restrict__ Dp,
                 __nv_bfloat16* __restrict__ yh, __nv_bfloat16* __restrict__ yl)
{
    int tid = blockIdx.x*blockDim.x + threadIdx.x;
    int n = tid & (DS-1);
    int d = (tid >> 4) & (DI-1);
    int b = tid >> 15;
    float Aneg = -expf(A_log[d*DS + n]);
    float Dval = Dp[d];
    float h = 0.f;
    int base_tok = b*SEQ;
    for (int t = 0; t < SEQ; ++t) {
        int token = base_tok + t;
        float dv = delta[(size_t)token*DI + d];
        float xp = xg[(size_t)token*(2*DI) + d];
        float bm = __bfloat162float(Bm[(size_t)token*(DI*DS) + d*DS + n]);
        float cm = __bfloat162float(Cm[(size_t)token*(DI*DS) + d*DS + n]);
        float a = __expf(dv*Aneg);
        h = a*h + (dv*bm)*xp;
        float yv = cm*h;
        yv += __shfl_xor_sync(0xffffffffu, yv, 1);
        yv += __shfl_xor_sync(0xffffffffu, yv, 2);
        yv += __shfl_xor_sync(0xffffffffu, yv, 4);
        yv += __shfl_xor_sync(0xffffffffu, yv, 8);
        if (n == 0) {
            float g = xg[(size_t)token*(2*DI) + DI + d];
            float sg = g / (1.0f + __expf(-g));
            float val = (yv + Dval*xp)*sg;
            __nv_bfloat16 hh, ll; split_bf16(val, hh, ll);
            yh[(size_t)token*DI + d] = hh;
            yl[(size_t)token*DI + d] = ll;
        }
    }
}

// ---------------- host ----------------
template<int EPI, int OMODE>
static void launch_hgemm(const __nv_bfloat16* Ah, const __nv_bfloat16* Al,
                         const __nv_bfloat16* Bh, const __nv_bfloat16* Bl,
                         int K, int N, const float* bias, const float* add,
                         float* outf, __nv_bfloat16* oh, __nv_bfloat16* ol)
{
    cudaFuncSetAttribute(hgemm<EPI,OMODE>, cudaFuncAttributeMaxDynamicSharedMemorySize, SMEM_B);
    hgemm<EPI,OMODE><<<dim3(MTOK/BM, N/BN), 256, SMEM_B>>>(Ah, Al, Bh, Bl, K, N,
                                                            bias, add, outf, oh, ol);
}
static void launch_fgemm(const __nv_fp8_e4m3* A8, const __nv_fp8_e4m3* B8,
                         int K, int N, const float* bias, __nv_bfloat16* oh)
{
    cudaFuncSetAttribute(fgemm, cudaFuncAttributeMaxDynamicSharedMemorySize, F_SMEM);
    fgemm<<<dim3(MTOK/BM, N/BN), 256, F_SMEM>>>(A8, B8, K, N, bias, oh);
}

extern "C" void kernel_launch(void* const* d_in, const int* in_sizes, int n_in,
                              void* d_out, int out_size)
{
    const float* x      = (const float*)d_in[0];
    const float* ln1_g  = (const float*)d_in[1];
    const float* ln1_b  = (const float*)d_in[2];
    const float* W_in   = (const float*)d_in[3];
    const float* b_in   = (const float*)d_in[4];
    const float* conv_w = (const float*)d_in[5];
    const float* conv_b = (const float*)d_in[6];
    const float* A_log  = (const float*)d_in[7];
    const float* W_B    = (const float*)d_in[8];
    const float* b_B    = (const float*)d_in[9];
    const float* W_C    = (const float*)d_in[10];
    const float* b_C    = (const float*)d_in[11];
    const float* Dp     = (const float*)d_in[12];
    const float* W_dt   = (const float*)d_in[13];
    const float* b_dt   = (const float*)d_in[14];
    const float* W_out  = (const float*)d_in[15];
    const float* b_out  = (const float*)d_in[16];
    const float* ln2_g  = (const float*)d_in[17];
    const float* ln2_b  = (const float*)d_in[18];
    const float* W1     = (const float*)d_in[19];
    const float* b1     = (const float*)d_in[20];
    const float* W2     = (const float*)d_in[21];
    const float* b2     = (const float*)d_in[22];
    float* out = (float*)d_out;

    float *xg, *delta, *x2;
    cudaGetSymbolAddress((void**)&xg, g_xg);
    cudaGetSymbolAddress((void**)&delta, g_delta);
    cudaGetSymbolAddress((void**)&x2, g_x2);
    __nv_bfloat16 *Bm, *Cm;
    cudaGetSymbolAddress((void**)&Bm, g_Bm);
    cudaGetSymbolAddress((void**)&Cm, g_Cm);
    __nv_bfloat16 *xnh,*xnl,*xch,*xcl,*yh,*yl,*xn2h,*xn2l,*h1h,*h1l;
    cudaGetSymbolAddress((void**)&xnh, g_xn_h);   cudaGetSymbolAddress((void**)&xnl, g_xn_l);
    cudaGetSymbolAddress((void**)&xch, g_xc_h);   cudaGetSymbolAddress((void**)&xcl, g_xc_l);
    cudaGetSymbolAddress((void**)&yh,  g_y_h);    cudaGetSymbolAddress((void**)&yl,  g_y_l);
    cudaGetSymbolAddress((void**)&xn2h,g_xn2_h);  cudaGetSymbolAddress((void**)&xn2l,g_xn2_l);
    cudaGetSymbolAddress((void**)&h1h, g_h1_h);   cudaGetSymbolAddress((void**)&h1l, g_h1_l);
    __nv_fp8_e4m3 *xc8, *WB8, *WC8;
    cudaGetSymbolAddress((void**)&xc8, g_xc8);
    cudaGetSymbolAddress((void**)&WB8, g_WB8);
    cudaGetSymbolAddress((void**)&WC8, g_WC8);
    __nv_bfloat16 *Winh,*Winl,*Wdth,*Wdtl,*Wouth,*Woutl,*W1h,*W1l,*W2h,*W2l;
    cudaGetSymbolAddress((void**)&Winh, g_Win_h); cudaGetSymbolAddress((void**)&Winl, g_Win_l);
    cudaGetSymbolAddress((void**)&Wdth, g_Wdt_h); cudaGetSymbolAddress((void**)&Wdtl, g_Wdt_l);
    cudaGetSymbolAddress((void**)&Wouth,g_Wout_h);cudaGetSymbolAddress((void**)&Woutl,g_Wout_l);
    cudaGetSymbolAddress((void**)&W1h,  g_W1_h);  cudaGetSymbolAddress((void**)&W1l,  g_W1_l);
    cudaGetSymbolAddress((void**)&W2h,  g_W2_h);  cudaGetSymbolAddress((void**)&W2l,  g_W2_l);

    dim3 tb(32, 8);
    // launch order chosen so launch #5 (ncu -s 5 -c 1) is the big fp8 GEMM
    wtrans <<<dim3((2*DI)/32, DM/32),  tb>>>(W_in, Winh, Winl, DM, 2*DI);            // 0
    ln_kernel<<<MTOK, 256>>>(x, ln1_g, ln1_b, xnh, xnl);                             // 1
    launch_hgemm<0,0>(xnh, xnl, Winh, Winl, DM, 2*DI, b_in, nullptr, xg, nullptr, nullptr); // 2
    conv_kernel<<<(MTOK*DI)/256, 256>>>(xg, conv_w, conv_b, xch, xcl, xc8);          // 3
    wtrans8<<<dim3((DI*DS)/32, DI/32), tb>>>(W_B, WB8, DI, DI*DS);                   // 4
    launch_fgemm(xc8, WB8, DI, DI*DS, b_B, Bm);                                      // 5 <- profiled
    wtrans8<<<dim3((DI*DS)/32, DI/32), tb>>>(W_C, WC8, DI, DI*DS);                   // 6
    launch_fgemm(xc8, WC8, DI, DI*DS, b_C, Cm);                                      // 7
    wtrans <<<dim3(DI/32, DI/32),      tb>>>(W_dt, Wdth, Wdtl, DI, DI);              // 8
    launch_hgemm<1,0>(xch, xcl, Wdth, Wdtl, DI, DI, b_dt, nullptr, delta, nullptr, nullptr); // 9
    scan_kernel<<<256, 256>>>(xg, delta, Bm, Cm, A_log, Dp, yh, yl);                 // 10
    wtrans <<<dim3(DM/32, DI/32),      tb>>>(W_out, Wouth, Woutl, DI, DM);           // 11
    launch_hgemm<3,0>(yh, yl, Wouth, Woutl, DI, DM, b_out, x, x2, nullptr, nullptr); // 12
    ln_kernel<<<MTOK, 256>>>(x2, ln2_g, ln2_b, xn2h, xn2l);                          // 13
    wtrans <<<dim3(DFF/32, DM/32),     tb>>>(W1, W1h, W1l, DM, DFF);                 // 14
    launch_hgemm<2,1>(xn2h, xn2l, W1h, W1l, DM, DFF, b1, nullptr, nullptr, h1h, h1l);// 15
    wtrans <<<dim3(DM/32, DFF/32),     tb>>>(W2, W2h, W2l, DFF, DM);                 // 16
    launch_hgemm<3,0>(h1h, h1l, W2h, W2l, DFF, DM, b2, x2, out, nullptr, nullptr);   // 17
}

// round 10
// speedup vs baseline: 3.4328x; 1.0791x over previous
#include <cuda_runtime.h>
#include <cuda_bf16.h>
#include <cuda_fp8.h>
#include <math.h>

#define B_SZ 2
#define SEQ  1024
#define DM   1024
#define DI   2048
#define DS   16
#define DFF  4096
#define MTOK (B_SZ*SEQ)

// ---- bf16 GEMM tiling: CTA 128x256, warp 64x64 (2x4), BK=32, 3-stage ----
#define BM 128
#define BN 256
#define BK 32
#define NSTAGE 3
#define ROWB 80
#define A_SPLIT (BM*ROWB)
#define A_BOTH  (2*A_SPLIT)
#define B_SPLIT (BN*ROWB)
#define B_BOTH  (2*B_SPLIT)
#define STAGE_B (A_BOTH + B_BOTH)
#define SMEM_B  (NSTAGE*STAGE_B)

// ---- fp8 GEMM tiling: CTA 128x256, warp 64x64, FBK=128, 3-stage ----
#define FBK 128
#define FROWB 144                       // 128B data + 16B pad (conflict-free ldmatrix)
#define F_A (BM*FROWB)                  // 18432
#define F_B (BN*FROWB)                  // 36864
#define F_STAGE (F_A + F_B)             // 55296
#define F_SMEM (NSTAGE*F_STAGE)         // 165888

// ---- fp32 scratch ----
__device__ float g_xg   [MTOK*2*DI];
__device__ float g_delta[MTOK*DI];
__device__ float g_x2   [MTOK*DM];
// ---- bf16 Bm/Cm ----
__device__ __nv_bfloat16 g_Bm[67108864];
__device__ __nv_bfloat16 g_Cm[67108864];
// ---- bf16 activation pairs ----
__device__ __nv_bfloat16 g_xn_h [MTOK*DM],  g_xn_l [MTOK*DM];
__device__ __nv_bfloat16 g_y_h  [MTOK*DI],  g_y_l  [MTOK*DI];
__device__ __nv_bfloat16 g_xn2_h[MTOK*DM],  g_xn2_l[MTOK*DM];
__device__ __nv_bfloat16 g_h1_h [MTOK*DFF], g_h1_l [MTOK*DFF];
// ---- fp8 operands ----
__device__ __nv_fp8_e4m3 g_xc8  [MTOK*DI];
__device__ __nv_fp8_e4m3 g_WB8  [DI*DI*DS];
__device__ __nv_fp8_e4m3 g_WC8  [DI*DI*DS];
__device__ __nv_fp8_e4m3 g_Wdt8 [DI*DI];
// ---- bf16 transposed weight pairs [N,K] ----
__device__ __nv_bfloat16 g_Win_h [2*DI*DM],  g_Win_l [2*DI*DM];
__device__ __nv_bfloat16 g_Wout_h[DM*DI],    g_Wout_l[DM*DI];
__device__ __nv_bfloat16 g_W1_h  [DFF*DM],   g_W1_l  [DFF*DM];
__device__ __nv_bfloat16 g_W2_h  [DM*DFF],   g_W2_l  [DM*DFF];

// ---------------- helpers ----------------
__device__ __forceinline__ unsigned s2u(const void* p) {
    unsigned a;
    asm("{ .reg .u64 t; cvta.to.shared.u64 t, %1; cvt.u32.u64 %0, t; }" : "=r"(a) : "l"(p));
    return a;
}
__device__ __forceinline__ void cp16(unsigned d, const void* s) {
    asm volatile("cp.async.cg.shared.global [%0], [%1], 16;" :: "r"(d), "l"(s));
}
#define CP_COMMIT() asm volatile("cp.async.commit_group;" ::: "memory")
#define CP_WAIT1()  asm volatile("cp.async.wait_group 1;" ::: "memory")
#define LDSM4(r, addr) \
    asm volatile("ldmatrix.sync.aligned.m8n8.x4.shared.b16 {%0,%1,%2,%3}, [%4];" \
        : "=r"((r)[0]),"=r"((r)[1]),"=r"((r)[2]),"=r"((r)[3]) : "r"(addr))
#define MMA4(d, a, b0v, b1v) \
    asm volatile("mma.sync.aligned.m16n8k16.row.col.f32.bf16.bf16.f32 " \
        "{%0,%1,%2,%3},{%4,%5,%6,%7},{%8,%9},{%0,%1,%2,%3};" \
        : "+f"((d)[0]),"+f"((d)[1]),"+f"((d)[2]),"+f"((d)[3]) \
        : "r"((a)[0]),"r"((a)[1]),"r"((a)[2]),"r"((a)[3]),"r"(b0v),"r"(b1v))
#define MMA8(d, a, b0v, b1v) \
    asm volatile("mma.sync.aligned.m16n8k32.row.col.f32.e4m3.e4m3.f32 " \
        "{%0,%1,%2,%3},{%4,%5,%6,%7},{%8,%9},{%0,%1,%2,%3};" \
        : "+f"((d)[0]),"+f"((d)[1]),"+f"((d)[2]),"+f"((d)[3]) \
        : "r"((a)[0]),"r"((a)[1]),"r"((a)[2]),"r"((a)[3]),"r"(b0v),"r"(b1v))

__device__ __forceinline__ void split_bf16(float v, __nv_bfloat16& h, __nv_bfloat16& l) {
    h = __float2bfloat16(v);
    l = __float2bfloat16(v - __bfloat162float(h));
}

// ---------------- epilogue helper ----------------
// OMODE: 0 fp32 ; 1 bf16 hi/lo pair ; 2 bf16 single
template<int EPI, int OMODE>
__device__ __forceinline__ void epi2(int r, int c, float v0, float v1, int N,
    const float* __restrict__ bias, const float* __restrict__ add,
    float* __restrict__ outf, __nv_bfloat16* __restrict__ oh, __nv_bfloat16* __restrict__ ol)
{
    size_t go = (size_t)r*N + c;
    float2 bb = *(const float2*)&bias[c];
    v0 += bb.x; v1 += bb.y;
    if (EPI == 3) { float2 aa = *(const float2*)&add[go]; v0 += aa.x; v1 += aa.y; }
    if (EPI == 1) {
        v0 = 1.0f/(1.0f + expf(-v0))*0.099f + 0.001f;
        v1 = 1.0f/(1.0f + expf(-v1))*0.099f + 0.001f;
    }
    if (EPI == 2) {
        v0 = 0.5f*v0*(1.0f + erff(v0*0.70710678118654752f));
        v1 = 0.5f*v1*(1.0f + erff(v1*0.70710678118654752f));
    }
    if (OMODE == 1) {
        __nv_bfloat16 h0,l0,h1,l1;
        split_bf16(v0,h0,l0); split_bf16(v1,h1,l1);
        *(__nv_bfloat162*)&oh[go] = __nv_bfloat162{h0,h1};
        *(__nv_bfloat162*)&ol[go] = __nv_bfloat162{l0,l1};
    } else if (OMODE == 2) {
        *(__nv_bfloat162*)&oh[go] =
            __nv_bfloat162{__float2bfloat16(v0), __float2bfloat16(v1)};
    } else {
        float2 o; o.x = v0; o.y = v1;
        *(float2*)&outf[go] = o;
    }
}

// ---------------- bf16 split HMMA GEMM (3-term) ----------------
template<int EPI, int OMODE>
__global__ __launch_bounds__(256, 1)
void hgemm(const __nv_bfloat16* __restrict__ Ah, const __nv_bfloat16* __restrict__ Al,
           const __nv_bfloat16* __restrict__ Bh, const __nv_bfloat16* __restrict__ Bl,
           int K, int N,
           const float* __restrict__ bias, const float* __restrict__ add,
           float* __restrict__ outf,
           __nv_bfloat16* __restrict__ oh, __nv_bfloat16* __restrict__ ol)
{
    extern __shared__ char sm[];
    unsigned sbase = s2u(sm);
    int tid = threadIdx.x, lane = tid & 31, wid = tid >> 5;
    int wm = wid & 1, wn = wid >> 1;
    int crow = blockIdx.x * BM, ccol = blockIdx.y * BN;

    int arow = tid & 127, asp = tid >> 7;
    const __nv_bfloat16* Asrc = (asp ? Al : Ah) + (size_t)(crow + arow)*K;
    unsigned adst = sbase + asp*A_SPLIT + arow*ROWB;
    int brow0 = tid, brow1 = tid + 256;
    const __nv_bfloat16* Bsrc0 = ((brow0 >> 8) ? Bl : Bh) + (size_t)(ccol + (brow0 & 255))*K;
    const __nv_bfloat16* Bsrc1 = Bl + (size_t)(ccol + (brow1 & 255))*K;
    unsigned bdst0 = sbase + A_BOTH + (brow0 >> 8)*B_SPLIT + (brow0 & 255)*ROWB;
    unsigned bdst1 = sbase + A_BOTH + B_SPLIT + (brow1 & 255)*ROWB;

    float acc[4][8][4];
    #pragma unroll
    for (int i = 0; i < 4; i++)
        #pragma unroll
        for (int j = 0; j < 8; j++)
            #pragma unroll
            for (int q = 0; q < 4; q++) acc[i][j][q] = 0.f;

    const int nk = K / BK;

    #pragma unroll
    for (int st = 0; st < NSTAGE-1; st++) {
        unsigned so = st*STAGE_B;
        #pragma unroll
        for (int c = 0; c < 4; c++) {
            cp16(adst + so + c*16,  Asrc  + st*BK + c*8);
            cp16(bdst0 + so + c*16, Bsrc0 + st*BK + c*8);
            cp16(bdst1 + so + c*16, Bsrc1 + st*BK + c*8);
        }
        CP_COMMIT();
    }

    int rrow = lane & 15, rhalf = lane >> 4;

    for (int i = 0; i < nk; i++) {
        CP_WAIT1();
        __syncthreads();

        int j = i + NSTAGE - 1;
        if (j < nk) {
            unsigned so = (j % NSTAGE)*STAGE_B;
            #pragma unroll
            for (int c = 0; c < 4; c++) {
                cp16(adst + so + c*16,  Asrc  + j*BK + c*8);
                cp16(bdst0 + so + c*16, Bsrc0 + j*BK + c*8);
                cp16(bdst1 + so + c*16, Bsrc1 + j*BK + c*8);
            }
        }
        CP_COMMIT();

        unsigned aST = sbase + (i % NSTAGE)*STAGE_B;
        unsigned bST = aST + A_BOTH;

        #pragma unroll
        for (int ks = 0; ks < 2; ks++) {
            int koff = ks*16;
            unsigned ah[4][4], al_[4][4];
            #pragma unroll
            for (int mt = 0; mt < 4; mt++) {
                unsigned base = aST + (unsigned)(wm*64 + mt*16 + rrow)*ROWB
                              + (unsigned)(koff + rhalf*8)*2;
                LDSM4(ah[mt], base);
                LDSM4(al_[mt], base + A_SPLIT);
            }
            #pragma unroll
            for (int p = 0; p < 4; p++) {
                unsigned base = bST + (unsigned)(wn*64 + p*16 + rrow)*ROWB
                              + (unsigned)(koff + rhalf*8)*2;
                unsigned th[4], tl[4];
                LDSM4(th, base);
                LDSM4(tl, base + B_SPLIT);
                #pragma unroll
                for (int mt = 0; mt < 4; mt++) {
                    MMA4(acc[mt][2*p],   ah[mt],  th[0], th[2]);
                    MMA4(acc[mt][2*p+1], ah[mt],  th[1], th[3]);
                    MMA4(acc[mt][2*p],   ah[mt],  tl[0], tl[2]);
                    MMA4(acc[mt][2*p+1], ah[mt],  tl[1], tl[3]);
                    MMA4(acc[mt][2*p],   al_[mt], th[0], th[2]);
                    MMA4(acc[mt][2*p+1], al_[mt], th[1], th[3]);
                }
            }
        }
    }

    #pragma unroll
    for (int mt = 0; mt < 4; mt++) {
        int r0 = crow + wm*64 + mt*16 + (lane >> 2);
        #pragma unroll
        for (int nt = 0; nt < 8; nt++) {
            int c = ccol + wn*64 + nt*8 + 2*(lane & 3);
            epi2<EPI,OMODE>(r0,     c, acc[mt][nt][0], acc[mt][nt][1], N, bias, add, outf, oh, ol);
            epi2<EPI,OMODE>(r0 + 8, c, acc[mt][nt][2], acc[mt][nt][3], N, bias, add, outf, oh, ol);
        }
    }
}

// ---------------- fp8 e4m3 GEMM, FBK=128 ----------------
// EPI: 0 bias ; 1 sigmoid-delta.  OMODE: 0 fp32 ; 2 bf16 single.
template<int EPI, int OMODE>
__global__ __launch_bounds__(256, 1)
void fgemm(const __nv_fp8_e4m3* __restrict__ A8, const __nv_fp8_e4m3* __restrict__ B8,
           int K, int N, const float* __restrict__ bias,
           float* __restrict__ outf, __nv_bfloat16* __restrict__ oh)
{
    extern __shared__ char sm[];
    unsigned sbase = s2u(sm);
    int tid = threadIdx.x, lane = tid & 31, wid = tid >> 5;
    int wm = wid & 1, wn = wid >> 1;
    int crow = blockIdx.x * BM, ccol = blockIdx.y * BN;

    // loaders: A row tid>>1 (half tid&1, 4 chunks), B row tid (8 chunks)
    int ar = tid >> 1, ah_ = tid & 1;
    const char* Asrc = (const char*)(A8 + (size_t)(crow + ar)*K) + ah_*64;
    const char* Bsrc = (const char*)(B8 + (size_t)(ccol + tid)*K);
    unsigned adst = sbase + ar*FROWB + ah_*64;
    unsigned bdst = sbase + F_A + tid*FROWB;

    float acc[4][8][4];
    #pragma unroll
    for (int i = 0; i < 4; i++)
        #pragma unroll
        for (int j = 0; j < 8; j++)
            #pragma unroll
            for (int q = 0; q < 4; q++) acc[i][j][q] = 0.f;

    const int nk = K / FBK;

    #pragma unroll
    for (int st = 0; st < NSTAGE-1; st++) {
        unsigned so = st*F_STAGE;
        #pragma unroll
        for (int c = 0; c < 4; c++) cp16(adst + so + c*16, Asrc + st*FBK + c*16);
        #pragma unroll
        for (int c = 0; c < 8; c++) cp16(bdst + so + c*16, Bsrc + st*FBK + c*16);
        CP_COMMIT();
    }

    int rrow = lane & 15, rhalf = lane >> 4;

    for (int i = 0; i < nk; i++) {
        CP_WAIT1();
        __syncthreads();

        int j = i + NSTAGE - 1;
        if (j < nk) {
            unsigned so = (j % NSTAGE)*F_STAGE;
            #pragma unroll
            for (int c = 0; c < 4; c++) cp16(adst + so + c*16, Asrc + j*FBK + c*16);
            #pragma unroll
            for (int c = 0; c < 8; c++) cp16(bdst + so + c*16, Bsrc + j*FBK + c*16);
        }
        CP_COMMIT();

        unsigned aST = sbase + (i % NSTAGE)*F_STAGE;
        unsigned bST = aST + F_A;

        #pragma unroll
        for (int ks = 0; ks < 4; ks++) {            // four k32 chunks per FBK=128
            int koff = ks*32;                       // bytes
            unsigned av[4][4];
            #pragma unroll
            for (int mt = 0; mt < 4; mt++) {
                unsigned base = aST + (unsigned)(wm*64 + mt*16 + rrow)*FROWB
                              + (unsigned)(koff + rhalf*16);
                LDSM4(av[mt], base);
            }
            #pragma unroll
            for (int p = 0; p < 4; p++) {
                unsigned base = bST + (unsigned)(wn*64 + p*16 + rrow)*FROWB
                              + (unsigned)(koff + rhalf*16);
                unsigned tb[4];
                LDSM4(tb, base);
                #pragma unroll
                for (int mt = 0; mt < 4; mt++) {
                    MMA8(acc[mt][2*p],   av[mt], tb[0], tb[2]);
                    MMA8(acc[mt][2*p+1], av[mt], tb[1], tb[3]);
                }
            }
        }
    }

    #pragma unroll
    for (int mt = 0; mt < 4; mt++) {
        int r0 = crow + wm*64 + mt*16 + (lane >> 2);
        #pragma unroll
        for (int nt = 0; nt < 8; nt++) {
            int c = ccol + wn*64 + nt*8 + 2*(lane & 3);
            epi2<EPI,OMODE>(r0,     c, acc[mt][nt][0], acc[mt][nt][1], N, bias, nullptr, outf, oh, nullptr);
            epi2<EPI,OMODE>(r0 + 8, c, acc[mt][nt][2], acc[mt][nt][3], N, bias, nullptr, outf, oh, nullptr);
        }
    }
}

// ---------------- weight transpose kernels (vectorized stores) ----------------
__global__ __launch_bounds__(256)
void wtrans(const float* __restrict__ W, __nv_bfloat16* __restrict__ hi,
            __nv_bfloat16* __restrict__ lo, int K, int N)
{
    __shared__ float t[32][33];
    int n0 = blockIdx.x*32, k0 = blockIdx.y*32;
    int tx = threadIdx.x, ty = threadIdx.y;
    #pragma unroll
    for (int i = 0; i < 4; i++)
        t[ty + i*8][tx] = W[(size_t)(k0 + ty + i*8)*N + n0 + tx];
    __syncthreads();
    int flat = ty*32 + tx;
    int nl = flat >> 3, k4 = (flat & 7)*4;
    __nv_bfloat16 h[4], l[4];
    #pragma unroll
    for (int j = 0; j < 4; j++) split_bf16(t[k4+j][nl], h[j], l[j]);
    size_t o = (size_t)(n0 + nl)*K + k0 + k4;
    uint2 ph, pl;
    ph.x = ((unsigned)__bfloat16_as_ushort(h[1]) << 16) | __bfloat16_as_ushort(h[0]);
    ph.y = ((unsigned)__bfloat16_as_ushort(h[3]) << 16) | __bfloat16_as_ushort(h[2]);
    pl.x = ((unsigned)__bfloat16_as_ushort(l[1]) << 16) | __bfloat16_as_ushort(l[0]);
    pl.y = ((unsigned)__bfloat16_as_ushort(l[3]) << 16) | __bfloat16_as_ushort(l[2]);
    *(uint2*)&hi[o] = ph;
    *(uint2*)&lo[o] = pl;
}
__global__ __launch_bounds__(256)
void wtrans8(const float* __restrict__ W, __nv_fp8_e4m3* __restrict__ o8, int K, int N)
{
    __shared__ float t[32][33];
    int n0 = blockIdx.x*32, k0 = blockIdx.y*32;
    int tx = threadIdx.x, ty = threadIdx.y;
    #pragma unroll
    for (int i = 0; i < 4; i++)
        t[ty + i*8][tx] = W[(size_t)(k0 + ty + i*8)*N + n0 + tx];
    __syncthreads();
    int flat = ty*32 + tx;
    int nl = flat >> 3, k4 = (flat & 7)*4;
    unsigned pk = 0;
    #pragma unroll
    for (int j = 0; j < 4; j++) {
        __nv_fp8_e4m3 v(t[k4+j][nl]);
        pk |= (unsigned)(*(unsigned char*)&v) << (j*8);
    }
    *(unsigned*)&o8[(size_t)(n0 + nl)*K + k0 + k4] = pk;
}

// ---------------- LayerNorm -> bf16 pair ----------------
__global__ __launch_bounds__(256)
void ln_kernel(const float* __restrict__ in, const float* __restrict__ g,
               const float* __restrict__ bcoef,
               __nv_bfloat16* __restrict__ oh, __nv_bfloat16* __restrict__ ol)
{
    int row = blockIdx.x, tid = threadIdx.x;
    float4 v = ((const float4*)(in + (size_t)row*DM))[tid];
    __shared__ float red1[8], red2[8];
    float s = v.x + v.y + v.z + v.w;
    #pragma unroll
    for (int o = 16; o > 0; o >>= 1) s += __shfl_xor_sync(0xffffffffu, s, o);
    if ((tid & 31) == 0) red1[tid >> 5] = s;
    __syncthreads();
    float tot = 0.f;
    #pragma unroll
    for (int i = 0; i < 8; i++) tot += red1[i];
    float mean = tot * (1.0f/DM);
    float dx = v.x-mean, dy = v.y-mean, dz = v.z-mean, dw = v.w-mean;
    float sq = dx*dx + dy*dy + dz*dz + dw*dw;
    #pragma unroll
    for (int o = 16; o > 0; o >>= 1) sq += __shfl_xor_sync(0xffffffffu, sq, o);
    if ((tid & 31) == 0) red2[tid >> 5] = sq;
    __syncthreads();
    float tot2 = 0.f;
    #pragma unroll
    for (int i = 0; i < 8; i++) tot2 += red2[i];
    float rstd = rsqrtf(tot2*(1.0f/DM) + 1e-5f);
    float4 gg = ((const float4*)g)[tid];
    float4 bb = ((const float4*)bcoef)[tid];
    float o0 = dx*rstd*gg.x+bb.x, o1 = dy*rstd*gg.y+bb.y;
    float o2 = dz*rstd*gg.z+bb.z, o3 = dw*rstd*gg.w+bb.w;
    __nv_bfloat16 h0,l0,h1,l1,h2,l2,h3,l3;
    split_bf16(o0,h0,l0); split_bf16(o1,h1,l1); split_bf16(o2,h2,l2); split_bf16(o3,h3,l3);
    __nv_bfloat162* ph = (__nv_bfloat162*)(oh + (size_t)row*DM);
    __nv_bfloat162* pl = (__nv_bfloat162*)(ol + (size_t)row*DM);
    ph[tid*2] = __nv_bfloat162{h0,h1}; ph[tid*2+1] = __nv_bfloat162{h2,h3};
    pl[tid*2] = __nv_bfloat162{l0,l1}; pl[tid*2+1] = __nv_bfloat162{l2,l3};
}

// ---------------- conv -> fp8 only ----------------
__global__ __launch_bounds__(256)
void conv_kernel(const float* __restrict__ xg, const float* __restrict__ cw,
                 const float* __restrict__ cb, __nv_fp8_e4m3* __restrict__ o8)
{
    int idx = blockIdx.x*blockDim.x + threadIdx.x;
    int d = idx & (DI-1);
    int token = idx >> 11;
    int t = token & (SEQ-1);
    float acc = cb[d];
    #pragma unroll
    for (int k = 0; k < 4; k++) {
        int ts = t - 3 + k;
        if (ts >= 0) acc += xg[(size_t)(token-3+k)*(2*DI) + d] * cw[d*4+k];
    }
    o8[idx] = __nv_fp8_e4m3(acc);
}

// ---------------- selective scan -> bf16 pair ----------------
__global__ __launch_bounds__(256)
void scan_kernel(const float* __restrict__ xg, const float* __restrict__ delta,
                 const __nv_bfloat16* __restrict__ Bm, const __nv_bfloat16* __restrict__ Cm,
                 const float* __restrict__ A_log, const float* __restrict__ Dp,
                 __nv_bfloat16* __restrict__ yh, __nv_bfloat16* __restrict__ yl)
{
    int tid = blockIdx.x*blockDim.x + threadIdx.x;
    int n = tid & (DS-1);
    int d = (tid >> 4) & (DI-1);
    int b = tid >> 15;
    float Aneg = -expf(A_log[d*DS + n]);
    float Dval = Dp[d];
    float h = 0.f;
    int base_tok = b*SEQ;
    for (int t = 0; t < SEQ; ++t) {
        int token = base_tok + t;
        float dv = delta[(size_t)token*DI + d];
        float xp = xg[(size_t)token*(2*DI) + d];
        float bm = __bfloat162float(Bm[(size_t)token*(DI*DS) + d*DS + n]);
        float cm = __bfloat162float(Cm[(size_t)token*(DI*DS) + d*DS + n]);
        float a = __expf(dv*Aneg);
        h = a*h + (dv*bm)*xp;
        float yv = cm*h;
        yv += __shfl_xor_sync(0xffffffffu, yv, 1);
        yv += __shfl_xor_sync(0xffffffffu, yv, 2);
        yv += __shfl_xor_sync(0xffffffffu, yv, 4);
        yv += __shfl_xor_sync(0xffffffffu, yv, 8);
        if (n == 0) {
            float g = xg[(size_t)token*(2*DI) + DI + d];
            float sg = g / (1.0f + __expf(-g));
            float val = (yv + Dval*xp)*sg;
            __nv_bfloat16 hh, ll; split_bf16(val, hh, ll);
            yh[(size_t)token*DI + d] = hh;
            yl[(size_t)token*DI + d] = ll;
        }
    }
}

// ---------------- host ----------------
template<int EPI, int OMODE>
static void launch_hgemm(const __nv_bfloat16* Ah, const __nv_bfloat16* Al,
                         const __nv_bfloat16* Bh, const __nv_bfloat16* Bl,
                         int K, int N, const float* bias, const float* add,
                         float* outf, __nv_bfloat16* oh, __nv_bfloat16* ol)
{
    cudaFuncSetAttribute(hgemm<EPI,OMODE>, cudaFuncAttributeMaxDynamicSharedMemorySize, SMEM_B);
    hgemm<EPI,OMODE><<<dim3(MTOK/BM, N/BN), 256, SMEM_B>>>(Ah, Al, Bh, Bl, K, N,
                                                            bias, add, outf, oh, ol);
}
template<int EPI, int OMODE>
static void launch_fgemm(const __nv_fp8_e4m3* A8, const __nv_fp8_e4m3* B8,
                         int K, int N, const float* bias,
                         float* outf, __nv_bfloat16* oh)
{
    cudaFuncSetAttribute(fgemm<EPI,OMODE>, cudaFuncAttributeMaxDynamicSharedMemorySize, F_SMEM);
    fgemm<EPI,OMODE><<<dim3(MTOK/BM, N/BN), 256, F_SMEM>>>(A8, B8, K, N, bias, outf, oh);
}

extern "C" void kernel_launch(void* const* d_in, const int* in_sizes, int n_in,
                              void* d_out, int out_size)
{
    const float* x      = (const float*)d_in[0];
    const float* ln1_g  = (const float*)d_in[1];
    const float* ln1_b  = (const float*)d_in[2];
    const float* W_in   = (const float*)d_in[3];
    const float* b_in   = (const float*)d_in[4];
    const float* conv_w = (const float*)d_in[5];
    const float* conv_b = (const float*)d_in[6];
    const float* A_log  = (const float*)d_in[7];
    const float* W_B    = (const float*)d_in[8];
    const float* b_B    = (const float*)d_in[9];
    const float* W_C    = (const float*)d_in[10];
    const float* b_C    = (const float*)d_in[11];
    const float* Dp     = (const float*)d_in[12];
    const float* W_dt   = (const float*)d_in[13];
    const float* b_dt   = (const float*)d_in[14];
    const float* W_out  = (const float*)d_in[15];
    const float* b_out  = (const float*)d_in[16];
    const float* ln2_g  = (const float*)d_in[17];
    const float* ln2_b  = (const float*)d_in[18];
    const float* W1     = (const float*)d_in[19];
    const float* b1     = (const float*)d_in[20];
    const float* W2     = (const float*)d_in[21];
    const float* b2     = (const float*)d_in[22];
    float* out = (float*)d_out;

    float *xg, *delta, *x2;
    cudaGetSymbolAddress((void**)&xg, g_xg);
    cudaGetSymbolAddress((void**)&delta, g_delta);
    cudaGetSymbolAddress((void**)&x2, g_x2);
    __nv_bfloat16 *Bm, *Cm;
    cudaGetSymbolAddress((void**)&Bm, g_Bm);
    cudaGetSymbolAddress((void**)&Cm, g_Cm);
    __nv_bfloat16 *xnh,*xnl,*yh,*yl,*xn2h,*xn2l,*h1h,*h1l;
    cudaGetSymbolAddress((void**)&xnh, g_xn_h);   cudaGetSymbolAddress((void**)&xnl, g_xn_l);
    cudaGetSymbolAddress((void**)&yh,  g_y_h);    cudaGetSymbolAddress((void**)&yl,  g_y_l);
    cudaGetSymbolAddress((void**)&xn2h,g_xn2_h);  cudaGetSymbolAddress((void**)&xn2l,g_xn2_l);
    cudaGetSymbolAddress((void**)&h1h, g_h1_h);   cudaGetSymbolAddress((void**)&h1l, g_h1_l);
    __nv_fp8_e4m3 *xc8, *WB8, *WC8, *Wdt8;
    cudaGetSymbolAddress((void**)&xc8, g_xc8);
    cudaGetSymbolAddress((void**)&WB8, g_WB8);
    cudaGetSymbolAddress((void**)&WC8, g_WC8);
    cudaGetSymbolAddress((void**)&Wdt8, g_Wdt8);
    __nv_bfloat16 *Winh,*Winl,*Wouth,*Woutl,*W1h,*W1l,*W2h,*W2l;
    cudaGetSymbolAddress((void**)&Winh, g_Win_h); cudaGetSymbolAddress((void**)&Winl, g_Win_l);
    cudaGetSymbolAddress((void**)&Wouth,g_Wout_h);cudaGetSymbolAddress((void**)&Woutl,g_Wout_l);
    cudaGetSymbolAddress((void**)&W1h,  g_W1_h);  cudaGetSymbolAddress((void**)&W1l,  g_W1_l);
    cudaGetSymbolAddress((void**)&W2h,  g_W2_h);  cudaGetSymbolAddress((void**)&W2l,  g_W2_l);

    dim3 tb(32, 8);
    // launch order keeps #5 = big fp8 GEMM for ncu (-s 5 -c 1)
    wtrans <<<dim3((2*DI)/32, DM/32),  tb>>>(W_in, Winh, Winl, DM, 2*DI);            // 0
    ln_kernel<<<MTOK, 256>>>(x, ln1_g, ln1_b, xnh, xnl);                             // 1
    launch_hgemm<0,0>(xnh, xnl, Winh, Winl, DM, 2*DI, b_in, nullptr, xg, nullptr, nullptr); // 2
    conv_kernel<<<(MTOK*DI)/256, 256>>>(xg, conv_w, conv_b, xc8);                    // 3
    wtrans8<<<dim3((DI*DS)/32, DI/32), tb>>>(W_B, WB8, DI, DI*DS);                   // 4
    launch_fgemm<0,2>(xc8, WB8, DI, DI*DS, b_B, nullptr, Bm);                        // 5 <- profiled
    wtrans8<<<dim3((DI*DS)/32, DI/32), tb>>>(W_C, WC8, DI, DI*DS);                   // 6
    launch_fgemm<0,2>(xc8, WC8, DI, DI*DS, b_C, nullptr, Cm);                        // 7
    wtrans8<<<dim3(DI/32, DI/32),      tb>>>(W_dt, Wdt8, DI, DI);                    // 8
    launch_fgemm<1,0>(xc8, Wdt8, DI, DI, b_dt, delta, nullptr);                      // 9
    scan_kernel<<<256, 256>>>(xg, delta, Bm, Cm, A_log, Dp, yh, yl);                 // 10
    wtrans <<<dim3(DM/32, DI/32),      tb>>>(W_out, Wouth, Woutl, DI, DM);           // 11
    launch_hgemm<3,0>(yh, yl, Wouth, Woutl, DI, DM, b_out, x, x2, nullptr, nullptr); // 12
    ln_kernel<<<MTOK, 256>>>(x2, ln2_g, ln2_b, xn2h, xn2l);                          // 13
    wtrans <<<dim3(DFF/32, DM/32),     tb>>>(W1, W1h, W1l, DM, DFF);                 // 14
    launch_hgemm<2,1>(xn2h, xn2l, W1h, W1l, DM, DFF, b1, nullptr, nullptr, h1h, h1l);// 15
    wtrans <<<dim3(DM/32, DFF/32),     tb>>>(W2, W2h, W2l, DFF, DM);                 // 16
    launch_hgemm<3,0>(h1h, h1l, W2h, W2l, DFF, DM, b2, x2, out, nullptr, nullptr);   // 17
}

// round 11
// speedup vs baseline: 3.6347x; 1.0588x over previous
#include <cuda_runtime.h>
#include <cuda_bf16.h>
#include <cuda_fp8.h>
#include <math.h>

#define B_SZ 2
#define SEQ  1024
#define DM   1024
#define DI   2048
#define DS   16
#define DFF  4096
#define MTOK (B_SZ*SEQ)

// ---- bf16 GEMM tiling: CTA 128x256, warp 64x64 (2x4), BK=32, 3-stage ----
#define BM 128
#define BN 256
#define BK 32
#define NSTAGE 3
#define ROWB 80
#define A_SPLIT (BM*ROWB)
#define A_BOTH  (2*A_SPLIT)
#define B_SPLIT (BN*ROWB)
#define B_BOTH  (2*B_SPLIT)
#define STAGE_B (A_BOTH + B_BOTH)
#define SMEM_B  (NSTAGE*STAGE_B)

// ---- fp8 GEMM tiling: CTA 128x128, warp 64x32 (2x4), FBK=128, 3-stage, 2 CTA/SM ----
#define FN 128
#define FBK 128
#define FROWB 144                       // 128B data + 16B pad (conflict-free ldmatrix)
#define F_A (BM*FROWB)                  // 18432
#define F_B (FN*FROWB)                  // 18432
#define F_STAGE (F_A + F_B)             // 36864
#define F_SMEM (NSTAGE*F_STAGE)         // 110592 -> 2 CTAs/SM

// ---- fp32 scratch ----
__device__ float g_xg   [MTOK*2*DI];
__device__ float g_delta[MTOK*DI];
__device__ float g_x2   [MTOK*DM];
// ---- bf16 Bm/Cm ----
__device__ __nv_bfloat16 g_Bm[67108864];
__device__ __nv_bfloat16 g_Cm[67108864];
// ---- bf16 activation pairs ----
__device__ __nv_bfloat16 g_xn_h [MTOK*DM],  g_xn_l [MTOK*DM];
__device__ __nv_bfloat16 g_y_h  [MTOK*DI],  g_y_l  [MTOK*DI];
__device__ __nv_bfloat16 g_xn2_h[MTOK*DM],  g_xn2_l[MTOK*DM];
__device__ __nv_bfloat16 g_h1_h [MTOK*DFF], g_h1_l [MTOK*DFF];
// ---- fp8 operands ----
__device__ __nv_fp8_e4m3 g_xc8  [MTOK*DI];
__device__ __nv_fp8_e4m3 g_WB8  [DI*DI*DS];
__device__ __nv_fp8_e4m3 g_WC8  [DI*DI*DS];
__device__ __nv_fp8_e4m3 g_Wdt8 [DI*DI];
// ---- bf16 transposed weight pairs [N,K] ----
__device__ __nv_bfloat16 g_Win_h [2*DI*DM],  g_Win_l [2*DI*DM];
__device__ __nv_bfloat16 g_Wout_h[DM*DI],    g_Wout_l[DM*DI];
__device__ __nv_bfloat16 g_W1_h  [DFF*DM],   g_W1_l  [DFF*DM];
__device__ __nv_bfloat16 g_W2_h  [DM*DFF],   g_W2_l  [DM*DFF];

// ---------------- helpers ----------------
__device__ __forceinline__ unsigned s2u(const void* p) {
    unsigned a;
    asm("{ .reg .u64 t; cvta.to.shared.u64 t, %1; cvt.u32.u64 %0, t; }" : "=r"(a) : "l"(p));
    return a;
}
__device__ __forceinline__ void cp16(unsigned d, const void* s) {
    asm volatile("cp.async.cg.shared.global [%0], [%1], 16;" :: "r"(d), "l"(s));
}
#define CP_COMMIT() asm volatile("cp.async.commit_group;" ::: "memory")
#define CP_WAIT1()  asm volatile("cp.async.wait_group 1;" ::: "memory")
#define LDSM4(r, addr) \
    asm volatile("ldmatrix.sync.aligned.m8n8.x4.shared.b16 {%0,%1,%2,%3}, [%4];" \
        : "=r"((r)[0]),"=r"((r)[1]),"=r"((r)[2]),"=r"((r)[3]) : "r"(addr))
#define MMA4(d, a, b0v, b1v) \
    asm volatile("mma.sync.aligned.m16n8k16.row.col.f32.bf16.bf16.f32 " \
        "{%0,%1,%2,%3},{%4,%5,%6,%7},{%8,%9},{%0,%1,%2,%3};" \
        : "+f"((d)[0]),"+f"((d)[1]),"+f"((d)[2]),"+f"((d)[3]) \
        : "r"((a)[0]),"r"((a)[1]),"r"((a)[2]),"r"((a)[3]),"r"(b0v),"r"(b1v))
#define MMA8(d, a, b0v, b1v) \
    asm volatile("mma.sync.aligned.m16n8k32.row.col.f32.e4m3.e4m3.f32 " \
        "{%0,%1,%2,%3},{%4,%5,%6,%7},{%8,%9},{%0,%1,%2,%3};" \
        : "+f"((d)[0]),"+f"((d)[1]),"+f"((d)[2]),"+f"((d)[3]) \
        : "r"((a)[0]),"r"((a)[1]),"r"((a)[2]),"r"((a)[3]),"r"(b0v),"r"(b1v))

__device__ __forceinline__ void split_bf16(float v, __nv_bfloat16& h, __nv_bfloat16& l) {
    h = __float2bfloat16(v);
    l = __float2bfloat16(v - __bfloat162float(h));
}

// ---------------- epilogue helper ----------------
// OMODE: 0 fp32 ; 1 bf16 hi/lo pair ; 2 bf16 single
template<int EPI, int OMODE>
__device__ __forceinline__ void epi2(int r, int c, float v0, float v1, int N,
    const float* __restrict__ bias, const float* __restrict__ add,
    float* __restrict__ outf, __nv_bfloat16* __restrict__ oh, __nv_bfloat16* __restrict__ ol)
{
    size_t go = (size_t)r*N + c;
    float2 bb = *(const float2*)&bias[c];
    v0 += bb.x; v1 += bb.y;
    if (EPI == 3) { float2 aa = *(const float2*)&add[go]; v0 += aa.x; v1 += aa.y; }
    if (EPI == 1) {
        v0 = 1.0f/(1.0f + expf(-v0))*0.099f + 0.001f;
        v1 = 1.0f/(1.0f + expf(-v1))*0.099f + 0.001f;
    }
    if (EPI == 2) {
        v0 = 0.5f*v0*(1.0f + erff(v0*0.70710678118654752f));
        v1 = 0.5f*v1*(1.0f + erff(v1*0.70710678118654752f));
    }
    if (OMODE == 1) {
        __nv_bfloat16 h0,l0,h1,l1;
        split_bf16(v0,h0,l0); split_bf16(v1,h1,l1);
        *(__nv_bfloat162*)&oh[go] = __nv_bfloat162{h0,h1};
        *(__nv_bfloat162*)&ol[go] = __nv_bfloat162{l0,l1};
    } else if (OMODE == 2) {
        *(__nv_bfloat162*)&oh[go] =
            __nv_bfloat162{__float2bfloat16(v0), __float2bfloat16(v1)};
    } else {
        float2 o; o.x = v0; o.y = v1;
        *(float2*)&outf[go] = o;
    }
}

// ---------------- bf16 split HMMA GEMM (3-term) ----------------
template<int EPI, int OMODE>
__global__ __launch_bounds__(256, 1)
void hgemm(const __nv_bfloat16* __restrict__ Ah, const __nv_bfloat16* __restrict__ Al,
           const __nv_bfloat16* __restrict__ Bh, const __nv_bfloat16* __restrict__ Bl,
           int K, int N,
           const float* __restrict__ bias, const float* __restrict__ add,
           float* __restrict__ outf,
           __nv_bfloat16* __restrict__ oh, __nv_bfloat16* __restrict__ ol)
{
    extern __shared__ char sm[];
    unsigned sbase = s2u(sm);
    int tid = threadIdx.x, lane = tid & 31, wid = tid >> 5;
    int wm = wid & 1, wn = wid >> 1;
    int crow = blockIdx.x * BM, ccol = blockIdx.y * BN;

    int arow = tid & 127, asp = tid >> 7;
    const __nv_bfloat16* Asrc = (asp ? Al : Ah) + (size_t)(crow + arow)*K;
    unsigned adst = sbase + asp*A_SPLIT + arow*ROWB;
    int brow0 = tid, brow1 = tid + 256;
    const __nv_bfloat16* Bsrc0 = ((brow0 >> 8) ? Bl : Bh) + (size_t)(ccol + (brow0 & 255))*K;
    const __nv_bfloat16* Bsrc1 = Bl + (size_t)(ccol + (brow1 & 255))*K;
    unsigned bdst0 = sbase + A_BOTH + (brow0 >> 8)*B_SPLIT + (brow0 & 255)*ROWB;
    unsigned bdst1 = sbase + A_BOTH + B_SPLIT + (brow1 & 255)*ROWB;

    float acc[4][8][4];
    #pragma unroll
    for (int i = 0; i < 4; i++)
        #pragma unroll
        for (int j = 0; j < 8; j++)
            #pragma unroll
            for (int q = 0; q < 4; q++) acc[i][j][q] = 0.f;

    const int nk = K / BK;

    #pragma unroll
    for (int st = 0; st < NSTAGE-1; st++) {
        unsigned so = st*STAGE_B;
        #pragma unroll
        for (int c = 0; c < 4; c++) {
            cp16(adst + so + c*16,  Asrc  + st*BK + c*8);
            cp16(bdst0 + so + c*16, Bsrc0 + st*BK + c*8);
            cp16(bdst1 + so + c*16, Bsrc1 + st*BK + c*8);
        }
        CP_COMMIT();
    }

    int rrow = lane & 15, rhalf = lane >> 4;

    for (int i = 0; i < nk; i++) {
        CP_WAIT1();
        __syncthreads();

        int j = i + NSTAGE - 1;
        if (j < nk) {
            unsigned so = (j % NSTAGE)*STAGE_B;
            #pragma unroll
            for (int c = 0; c < 4; c++) {
                cp16(adst + so + c*16,  Asrc  + j*BK + c*8);
                cp16(bdst0 + so + c*16, Bsrc0 + j*BK + c*8);
                cp16(bdst1 + so + c*16, Bsrc1 + j*BK + c*8);
            }
        }
        CP_COMMIT();

        unsigned aST = sbase + (i % NSTAGE)*STAGE_B;
        unsigned bST = aST + A_BOTH;

        #pragma unroll
        for (int ks = 0; ks < 2; ks++) {
            int koff = ks*16;
            unsigned ah[4][4], al_[4][4];
            #pragma unroll
            for (int mt = 0; mt < 4; mt++) {
                unsigned base = aST + (unsigned)(wm*64 + mt*16 + rrow)*ROWB
                              + (unsigned)(koff + rhalf*8)*2;
                LDSM4(ah[mt], base);
                LDSM4(al_[mt], base + A_SPLIT);
            }
            #pragma unroll
            for (int p = 0; p < 4; p++) {
                unsigned base = bST + (unsigned)(wn*64 + p*16 + rrow)*ROWB
                              + (unsigned)(koff + rhalf*8)*2;
                unsigned th[4], tl[4];
                LDSM4(th, base);
                LDSM4(tl, base + B_SPLIT);
                #pragma unroll
                for (int mt = 0; mt < 4; mt++) {
                    MMA4(acc[mt][2*p],   ah[mt],  th[0], th[2]);
                    MMA4(acc[mt][2*p+1], ah[mt],  th[1], th[3]);
                    MMA4(acc[mt][2*p],   ah[mt],  tl[0], tl[2]);
                    MMA4(acc[mt][2*p+1], ah[mt],  tl[1], tl[3]);
                    MMA4(acc[mt][2*p],   al_[mt], th[0], th[2]);
                    MMA4(acc[mt][2*p+1], al_[mt], th[1], th[3]);
                }
            }
        }
    }

    #pragma unroll
    for (int mt = 0; mt < 4; mt++) {
        int r0 = crow + wm*64 + mt*16 + (lane >> 2);
        #pragma unroll
        for (int nt = 0; nt < 8; nt++) {
            int c = ccol + wn*64 + nt*8 + 2*(lane & 3);
            epi2<EPI,OMODE>(r0,     c, acc[mt][nt][0], acc[mt][nt][1], N, bias, add, outf, oh, ol);
            epi2<EPI,OMODE>(r0 + 8, c, acc[mt][nt][2], acc[mt][nt][3], N, bias, add, outf, oh, ol);
        }
    }
}

// ---------------- fp8 e4m3 GEMM: CTA 128x128, 2 CTA/SM ----------------
// EPI: 0 bias ; 1 sigmoid-delta.  OMODE: 0 fp32 ; 2 bf16 single.
template<int EPI, int OMODE>
__global__ __launch_bounds__(256, 2)
void fgemm(const __nv_fp8_e4m3* __restrict__ A8, const __nv_fp8_e4m3* __restrict__ B8,
           int K, int N, const float* __restrict__ bias,
           float* __restrict__ outf, __nv_bfloat16* __restrict__ oh)
{
    extern __shared__ char sm[];
    unsigned sbase = s2u(sm);
    int tid = threadIdx.x, lane = tid & 31, wid = tid >> 5;
    int wm = wid & 1, wn = wid >> 1;            // 2 x 4 warps; warp tile 64 x 32
    int crow = blockIdx.x * BM, ccol = blockIdx.y * FN;

    // loaders: A row tid>>1 (half tid&1), B row tid>>1 (half tid&1); 4 chunks each
    int r2 = tid >> 1, hf = tid & 1;
    const char* Asrc = (const char*)(A8 + (size_t)(crow + r2)*K) + hf*64;
    const char* Bsrc = (const char*)(B8 + (size_t)(ccol + r2)*K) + hf*64;
    unsigned adst = sbase + r2*FROWB + hf*64;
    unsigned bdst = sbase + F_A + r2*FROWB + hf*64;

    float acc[4][4][4];
    #pragma unroll
    for (int i = 0; i < 4; i++)
        #pragma unroll
        for (int j = 0; j < 4; j++)
            #pragma unroll
            for (int q = 0; q < 4; q++) acc[i][j][q] = 0.f;

    const int nk = K / FBK;

    #pragma unroll
    for (int st = 0; st < NSTAGE-1; st++) {
        unsigned so = st*F_STAGE;
        #pragma unroll
        for (int c = 0; c < 4; c++) {
            cp16(adst + so + c*16, Asrc + st*FBK + c*16);
            cp16(bdst + so + c*16, Bsrc + st*FBK + c*16);
        }
        CP_COMMIT();
    }

    int rrow = lane & 15, rhalf = lane >> 4;

    for (int i = 0; i < nk; i++) {
        CP_WAIT1();
        __syncthreads();

        int j = i + NSTAGE - 1;
        if (j < nk) {
            unsigned so = (j % NSTAGE)*F_STAGE;
            #pragma unroll
            for (int c = 0; c < 4; c++) {
                cp16(adst + so + c*16, Asrc + j*FBK + c*16);
                cp16(bdst + so + c*16, Bsrc + j*FBK + c*16);
            }
        }
        CP_COMMIT();

        unsigned aST = sbase + (i % NSTAGE)*F_STAGE;
        unsigned bST = aST + F_A;

        #pragma unroll
        for (int ks = 0; ks < 4; ks++) {            // four k32 chunks per FBK=128
            int koff = ks*32;                       // bytes
            unsigned av[4][4];
            #pragma unroll
            for (int mt = 0; mt < 4; mt++) {
                unsigned base = aST + (unsigned)(wm*64 + mt*16 + rrow)*FROWB
                              + (unsigned)(koff + rhalf*16);
                LDSM4(av[mt], base);
            }
            #pragma unroll
            for (int p = 0; p < 2; p++) {
                unsigned base = bST + (unsigned)(wn*32 + p*16 + rrow)*FROWB
                              + (unsigned)(koff + rhalf*16);
                unsigned tb[4];
                LDSM4(tb, base);
                #pragma unroll
                for (int mt = 0; mt < 4; mt++) {
                    MMA8(acc[mt][2*p],   av[mt], tb[0], tb[2]);
                    MMA8(acc[mt][2*p+1], av[mt], tb[1], tb[3]);
                }
            }
        }
    }

    #pragma unroll
    for (int mt = 0; mt < 4; mt++) {
        int r0 = crow + wm*64 + mt*16 + (lane >> 2);
        #pragma unroll
        for (int nt = 0; nt < 4; nt++) {
            int c = ccol + wn*32 + nt*8 + 2*(lane & 3);
            epi2<EPI,OMODE>(r0,     c, acc[mt][nt][0], acc[mt][nt][1], N, bias, nullptr, outf, oh, nullptr);
            epi2<EPI,OMODE>(r0 + 8, c, acc[mt][nt][2], acc[mt][nt][3], N, bias, nullptr, outf, oh, nullptr);
        }
    }
}

// ---------------- weight transpose kernels (vectorized stores) ----------------
__global__ __launch_bounds__(256)
void wtrans(const float* __restrict__ W, __nv_bfloat16* __restrict__ hi,
            __nv_bfloat16* __restrict__ lo, int K, int N)
{
    __shared__ float t[32][33];
    int n0 = blockIdx.x*32, k0 = blockIdx.y*32;
    int tx = threadIdx.x, ty = threadIdx.y;
    #pragma unroll
    for (int i = 0; i < 4; i++)
        t[ty + i*8][tx] = W[(size_t)(k0 + ty + i*8)*N + n0 + tx];
    __syncthreads();
    int flat = ty*32 + tx;
    int nl = flat >> 3, k4 = (flat & 7)*4;
    __nv_bfloat16 h[4], l[4];
    #pragma unroll
    for (int j = 0; j < 4; j++) split_bf16(t[k4+j][nl], h[j], l[j]);
    size_t o = (size_t)(n0 + nl)*K + k0 + k4;
    uint2 ph, pl;
    ph.x = ((unsigned)__bfloat16_as_ushort(h[1]) << 16) | __bfloat16_as_ushort(h[0]);
    ph.y = ((unsigned)__bfloat16_as_ushort(h[3]) << 16) | __bfloat16_as_ushort(h[2]);
    pl.x = ((unsigned)__bfloat16_as_ushort(l[1]) << 16) | __bfloat16_as_ushort(l[0]);
    pl.y = ((unsigned)__bfloat16_as_ushort(l[3]) << 16) | __bfloat16_as_ushort(l[2]);
    *(uint2*)&hi[o] = ph;
    *(uint2*)&lo[o] = pl;
}
__global__ __launch_bounds__(256)
void wtrans8(const float* __restrict__ W, __nv_fp8_e4m3* __restrict__ o8, int K, int N)
{
    __shared__ float t[32][33];
    int n0 = blockIdx.x*32, k0 = blockIdx.y*32;
    int tx = threadIdx.x, ty = threadIdx.y;
    #pragma unroll
    for (int i = 0; i < 4; i++)
        t[ty + i*8][tx] = W[(size_t)(k0 + ty + i*8)*N + n0 + tx];
    __syncthreads();
    int flat = ty*32 + tx;
    int nl = flat >> 3, k4 = (flat & 7)*4;
    unsigned pk = 0;
    #pragma unroll
    for (int j = 0; j < 4; j++) {
        __nv_fp8_e4m3 v(t[k4+j][nl]);
        pk |= (unsigned)(*(unsigned char*)&v) << (j*8);
    }
    *(unsigned*)&o8[(size_t)(n0 + nl)*K + k0 + k4] = pk;
}

// ---------------- LayerNorm -> bf16 pair ----------------
__global__ __launch_bounds__(256)
void ln_kernel(const float* __restrict__ in, const float* __restrict__ g,
               const float* __restrict__ bcoef,
               __nv_bfloat16* __restrict__ oh, __nv_bfloat16* __restrict__ ol)
{
    int row = blockIdx.x, tid = threadIdx.x;
    float4 v = ((const float4*)(in + (size_t)row*DM))[tid];
    __shared__ float red1[8], red2[8];
    float s = v.x + v.y + v.z + v.w;
    #pragma unroll
    for (int o = 16; o > 0; o >>= 1) s += __shfl_xor_sync(0xffffffffu, s, o);
    if ((tid & 31) == 0) red1[tid >> 5] = s;
    __syncthreads();
    float tot = 0.f;
    #pragma unroll
    for (int i = 0; i < 8; i++) tot += red1[i];
    float mean = tot * (1.0f/DM);
    float dx = v.x-mean, dy = v.y-mean, dz = v.z-mean, dw = v.w-mean;
    float sq = dx*dx + dy*dy + dz*dz + dw*dw;
    #pragma unroll
    for (int o = 16; o > 0; o >>= 1) sq += __shfl_xor_sync(0xffffffffu, sq, o);
    if ((tid & 31) == 0) red2[tid >> 5] = sq;
    __syncthreads();
    float tot2 = 0.f;
    #pragma unroll
    for (int i = 0; i < 8; i++) tot2 += red2[i];
    float rstd = rsqrtf(tot2*(1.0f/DM) + 1e-5f);
    float4 gg = ((const float4*)g)[tid];
    float4 bb = ((const float4*)bcoef)[tid];
    float o0 = dx*rstd*gg.x+bb.x, o1 = dy*rstd*gg.y+bb.y;
    float o2 = dz*rstd*gg.z+bb.z, o3 = dw*rstd*gg.w+bb.w;
    __nv_bfloat16 h0,l0,h1,l1,h2,l2,h3,l3;
    split_bf16(o0,h0,l0); split_bf16(o1,h1,l1); split_bf16(o2,h2,l2); split_bf16(o3,h3,l3);
    __nv_bfloat162* ph = (__nv_bfloat162*)(oh + (size_t)row*DM);
    __nv_bfloat162* pl = (__nv_bfloat162*)(ol + (size_t)row*DM);
    ph[tid*2] = __nv_bfloat162{h0,h1}; ph[tid*2+1] = __nv_bfloat162{h2,h3};
    pl[tid*2] = __nv_bfloat162{l0,l1}; pl[tid*2+1] = __nv_bfloat162{l2,l3};
}

// ---------------- conv -> fp8 only ----------------
__global__ __launch_bounds__(256)
void conv_kernel(const float* __restrict__ xg, const float* __restrict__ cw,
                 const float* __restrict__ cb, __nv_fp8_e4m3* __restrict__ o8)
{
    int idx = blockIdx.x*blockDim.x + threadIdx.x;
    int d = idx & (DI-1);
    int token = idx >> 11;
    int t = token & (SEQ-1);
    float acc = cb[d];
    #pragma unroll
    for (int k = 0; k < 4; k++) {
        int ts = t - 3 + k;
        if (ts >= 0) acc += xg[(size_t)(token-3+k)*(2*DI) + d] * cw[d*4+k];
    }
    o8[idx] = __nv_fp8_e4m3(acc);
}

// ---------------- selective scan -> bf16 pair ----------------
__global__ __launch_bounds__(256)
void scan_kernel(const float* __restrict__ xg, const float* __restrict__ delta,
                 const __nv_bfloat16* __restrict__ Bm, const __nv_bfloat16* __restrict__ Cm,
                 const float* __restrict__ A_log, const float* __restrict__ Dp,
                 __nv_bfloat16* __restrict__ yh, __nv_bfloat16* __restrict__ yl)
{
    int tid = blockIdx.x*blockDim.x + threadIdx.x;
    int n = tid & (DS-1);
    int d = (tid >> 4) & (DI-1);
    int b = tid >> 15;
    float Aneg = -expf(A_log[d*DS + n]);
    float Dval = Dp[d];
    float h = 0.f;
    int base_tok = b*SEQ;
    for (int t = 0; t < SEQ; ++t) {
        int token = base_tok + t;
        float dv = delta[(size_t)token*DI + d];
        float xp = xg[(size_t)token*(2*DI) + d];
        float bm = __bfloat162float(Bm[(size_t)token*(DI*DS) + d*DS + n]);
        float cm = __bfloat162float(Cm[(size_t)token*(DI*DS) + d*DS + n]);
        float a = __expf(dv*Aneg);
        h = a*h + (dv*bm)*xp;
        float yv = cm*h;
        yv += __shfl_xor_sync(0xffffffffu, yv, 1);
        yv += __shfl_xor_sync(0xffffffffu, yv, 2);
        yv += __shfl_xor_sync(0xffffffffu, yv, 4);
        yv += __shfl_xor_sync(0xffffffffu, yv, 8);
        if (n == 0) {
            float g = xg[(size_t)token*(2*DI) + DI + d];
            float sg = g / (1.0f + __expf(-g));
            float val = (yv + Dval*xp)*sg;
            __nv_bfloat16 hh, ll; split_bf16(val, hh, ll);
            yh[(size_t)token*DI + d] = hh;
            yl[(size_t)token*DI + d] = ll;
        }
    }
}

// ---------------- host ----------------
template<int EPI, int OMODE>
static void launch_hgemm(const __nv_bfloat16* Ah, const __nv_bfloat16* Al,
                         const __nv_bfloat16* Bh, const __nv_bfloat16* Bl,
                         int K, int N, const float* bias, const float* add,
                         float* outf, __nv_bfloat16* oh, __nv_bfloat16* ol)
{
    cudaFuncSetAttribute(hgemm<EPI,OMODE>, cudaFuncAttributeMaxDynamicSharedMemorySize, SMEM_B);
    hgemm<EPI,OMODE><<<dim3(MTOK/BM, N/BN), 256, SMEM_B>>>(Ah, Al, Bh, Bl, K, N,
                                                            bias, add, outf, oh, ol);
}
template<int EPI, int OMODE>
static void launch_fgemm(const __nv_fp8_e4m3* A8, const __nv_fp8_e4m3* B8,
                         int K, int N, const float* bias,
                         float* outf, __nv_bfloat16* oh)
{
    cudaFuncSetAttribute(fgemm<EPI,OMODE>, cudaFuncAttributeMaxDynamicSharedMemorySize, F_SMEM);
    fgemm<EPI,OMODE><<<dim3(MTOK/BM, N/FN), 256, F_SMEM>>>(A8, B8, K, N, bias, outf, oh);
}

extern "C" void kernel_launch(void* const* d_in, const int* in_sizes, int n_in,
                              void* d_out, int out_size)
{
    const float* x      = (const float*)d_in[0];
    const float* ln1_g  = (const float*)d_in[1];
    const float* ln1_b  = (const float*)d_in[2];
    const float* W_in   = (const float*)d_in[3];
    const float* b_in   = (const float*)d_in[4];
    const float* conv_w = (const float*)d_in[5];
    const float* conv_b = (const float*)d_in[6];
    const float* A_log  = (const float*)d_in[7];
    const float* W_B    = (const float*)d_in[8];
    const float* b_B    = (const float*)d_in[9];
    const float* W_C    = (const float*)d_in[10];
    const float* b_C    = (const float*)d_in[11];
    const float* Dp     = (const float*)d_in[12];
    const float* W_dt   = (const float*)d_in[13];
    const float* b_dt   = (const float*)d_in[14];
    const float* W_out  = (const float*)d_in[15];
    const float* b_out  = (const float*)d_in[16];
    const float* ln2_g  = (const float*)d_in[17];
    const float* ln2_b  = (const float*)d_in[18];
    const float* W1     = (const float*)d_in[19];
    const float* b1     = (const float*)d_in[20];
    const float* W2     = (const float*)d_in[21];
    const float* b2     = (const float*)d_in[22];
    float* out = (float*)d_out;

    float *xg, *delta, *x2;
    cudaGetSymbolAddress((void**)&xg, g_xg);
    cudaGetSymbolAddress((void**)&delta, g_delta);
    cudaGetSymbolAddress((void**)&x2, g_x2);
    __nv_bfloat16 *Bm, *Cm;
    cudaGetSymbolAddress((void**)&Bm, g_Bm);
    cudaGetSymbolAddress((void**)&Cm, g_Cm);
    __nv_bfloat16 *xnh,*xnl,*yh,*yl,*xn2h,*xn2l,*h1h,*h1l;
    cudaGetSymbolAddress((void**)&xnh, g_xn_h);   cudaGetSymbolAddress((void**)&xnl, g_xn_l);
    cudaGetSymbolAddress((void**)&yh,  g_y_h);    cudaGetSymbolAddress((void**)&yl,  g_y_l);
    cudaGetSymbolAddress((void**)&xn2h,g_xn2_h);  cudaGetSymbolAddress((void**)&xn2l,g_xn2_l);
    cudaGetSymbolAddress((void**)&h1h, g_h1_h);   cudaGetSymbolAddress((void**)&h1l, g_h1_l);
    __nv_fp8_e4m3 *xc8, *WB8, *WC8, *Wdt8;
    cudaGetSymbolAddress((void**)&xc8, g_xc8);
    cudaGetSymbolAddress((void**)&WB8, g_WB8);
    cudaGetSymbolAddress((void**)&WC8, g_WC8);
    cudaGetSymbolAddress((void**)&Wdt8, g_Wdt8);
    __nv_bfloat16 *Winh,*Winl,*Wouth,*Woutl,*W1h,*W1l,*W2h,*W2l;
    cudaGetSymbolAddress((void**)&Winh, g_Win_h); cudaGetSymbolAddress((void**)&Winl, g_Win_l);
    cudaGetSymbolAddress((void**)&Wouth,g_Wout_h);cudaGetSymbolAddress((void**)&Woutl,g_Wout_l);
    cudaGetSymbolAddress((void**)&W1h,  g_W1_h);  cudaGetSymbolAddress((void**)&W1l,  g_W1_l);
    cudaGetSymbolAddress((void**)&W2h,  g_W2_h);  cudaGetSymbolAddress((void**)&W2l,  g_W2_l);

    dim3 tb(32, 8);
    // observed: ncu captures my launch index 3 -> place the 3-term hgemm there
    wtrans <<<dim3((2*DI)/32, DM/32),  tb>>>(W_in, Winh, Winl, DM, 2*DI);            // 0
    ln_kernel<<<MTOK, 256>>>(x, ln1_g, ln1_b, xnh, xnl);                             // 1
    wtrans8<<<dim3((DI*DS)/32, DI/32), tb>>>(W_B, WB8, DI, DI*DS);                   // 2 (independent)
    launch_hgemm<0,0>(xnh, xnl, Winh, Winl, DM, 2*DI, b_in, nullptr, xg, nullptr, nullptr); // 3 <- profiled
    conv_kernel<<<(MTOK*DI)/256, 256>>>(xg, conv_w, conv_b, xc8);                    // 4
    launch_fgemm<0,2>(xc8, WB8, DI, DI*DS, b_B, nullptr, Bm);                        // 5
    wtrans8<<<dim3((DI*DS)/32, DI/32), tb>>>(W_C, WC8, DI, DI*DS);                   // 6
    launch_fgemm<0,2>(xc8, WC8, DI, DI*DS, b_C, nullptr, Cm);                        // 7
    wtrans8<<<dim3(DI/32, DI/32),      tb>>>(W_dt, Wdt8, DI, DI);                    // 8
    launch_fgemm<1,0>(xc8, Wdt8, DI, DI, b_dt, delta, nullptr);                      // 9
    scan_kernel<<<256, 256>>>(xg, delta, Bm, Cm, A_log, Dp, yh, yl);                 // 10
    wtrans <<<dim3(DM/32, DI/32),      tb>>>(W_out, Wouth, Woutl, DI, DM);           // 11
    launch_hgemm<3,0>(yh, yl, Wouth, Woutl, DI, DM, b_out, x, x2, nullptr, nullptr); // 12
    ln_kernel<<<MTOK, 256>>>(x2, ln2_g, ln2_b, xn2h, xn2l);                          // 13
    wtrans <<<dim3(DFF/32, DM/32),     tb>>>(W1, W1h, W1l, DM, DFF);                 // 14
    launch_hgemm<2,1>(xn2h, xn2l, W1h, W1l, DM, DFF, b1, nullptr, nullptr, h1h, h1l);// 15
    wtrans <<<dim3(DM/32, DFF/32),     tb>>>(W2, W2h, W2l, DFF, DM);                 // 16
    launch_hgemm<3,0>(h1h, h1l, W2h, W2l, DFF, DM, b2, x2, out, nullptr, nullptr);   // 17
}

// round 12
// speedup vs baseline: 3.6497x; 1.0041x over previous
#include <cuda_runtime.h>
#include <cuda_bf16.h>
#include <cuda_fp8.h>
#include <math.h>

#define B_SZ 2
#define SEQ  1024
#define DM   1024
#define DI   2048
#define DS   16
#define DFF  4096
#define MTOK (B_SZ*SEQ)

// ---- bf16 GEMM tiling: CTA 128x256, warp 32x64 (4x4, 512 thr), BK=32, 3-stage ----
#define BM 128
#define BN 256
#define BK 32
#define NSTAGE 3
#define ROWB 80
#define A_SPLIT (BM*ROWB)
#define A_BOTH  (2*A_SPLIT)
#define B_SPLIT (BN*ROWB)
#define B_BOTH  (2*B_SPLIT)
#define STAGE_B (A_BOTH + B_BOTH)
#define SMEM_B  (NSTAGE*STAGE_B)

// ---- fp8 GEMM tiling: CTA 128x128, warp 64x32 (2x4), FBK=128, 3-stage, 2 CTA/SM ----
#define FN 128
#define FBK 128
#define FROWB 144
#define F_A (BM*FROWB)
#define F_B (FN*FROWB)
#define F_STAGE (F_A + F_B)
#define F_SMEM (NSTAGE*F_STAGE)

// ---- fp32 scratch ----
__device__ float g_xg   [MTOK*2*DI];
__device__ float g_delta[MTOK*DI];
__device__ float g_x2   [MTOK*DM];
// ---- bf16 Bm/Cm ----
__device__ __nv_bfloat16 g_Bm[67108864];
__device__ __nv_bfloat16 g_Cm[67108864];
// ---- bf16 activation pairs ----
__device__ __nv_bfloat16 g_xn_h [MTOK*DM],  g_xn_l [MTOK*DM];
__device__ __nv_bfloat16 g_y_h  [MTOK*DI],  g_y_l  [MTOK*DI];
__device__ __nv_bfloat16 g_xn2_h[MTOK*DM],  g_xn2_l[MTOK*DM];
__device__ __nv_bfloat16 g_h1_h [MTOK*DFF], g_h1_l [MTOK*DFF];
// ---- fp8 operands ----
__device__ __nv_fp8_e4m3 g_xc8  [MTOK*DI];
__device__ __nv_fp8_e4m3 g_WB8  [DI*DI*DS];
__device__ __nv_fp8_e4m3 g_WC8  [DI*DI*DS];
__device__ __nv_fp8_e4m3 g_Wdt8 [DI*DI];
// ---- bf16 transposed weight pairs [N,K] ----
__device__ __nv_bfloat16 g_Win_h [2*DI*DM],  g_Win_l [2*DI*DM];
__device__ __nv_bfloat16 g_Wout_h[DM*DI],    g_Wout_l[DM*DI];
__device__ __nv_bfloat16 g_W1_h  [DFF*DM],   g_W1_l  [DFF*DM];
__device__ __nv_bfloat16 g_W2_h  [DM*DFF],   g_W2_l  [DM*DFF];

// ---------------- helpers ----------------
__device__ __forceinline__ unsigned s2u(const void* p) {
    unsigned a;
    asm("{ .reg .u64 t; cvta.to.shared.u64 t, %1; cvt.u32.u64 %0, t; }" : "=r"(a) : "l"(p));
    return a;
}
__device__ __forceinline__ void cp16(unsigned d, const void* s) {
    asm volatile("cp.async.cg.shared.global [%0], [%1], 16;" :: "r"(d), "l"(s));
}
#define CP_COMMIT() asm volatile("cp.async.commit_group;" ::: "memory")
#define CP_WAIT1()  asm volatile("cp.async.wait_group 1;" ::: "memory")
#define LDSM4(r, addr) \
    asm volatile("ldmatrix.sync.aligned.m8n8.x4.shared.b16 {%0,%1,%2,%3}, [%4];" \
        : "=r"((r)[0]),"=r"((r)[1]),"=r"((r)[2]),"=r"((r)[3]) : "r"(addr))
#define MMA4(d, a, b0v, b1v) \
    asm volatile("mma.sync.aligned.m16n8k16.row.col.f32.bf16.bf16.f32 " \
        "{%0,%1,%2,%3},{%4,%5,%6,%7},{%8,%9},{%0,%1,%2,%3};" \
        : "+f"((d)[0]),"+f"((d)[1]),"+f"((d)[2]),"+f"((d)[3]) \
        : "r"((a)[0]),"r"((a)[1]),"r"((a)[2]),"r"((a)[3]),"r"(b0v),"r"(b1v))
#define MMA8(d, a, b0v, b1v) \
    asm volatile("mma.sync.aligned.m16n8k32.row.col.f32.e4m3.e4m3.f32 " \
        "{%0,%1,%2,%3},{%4,%5,%6,%7},{%8,%9},{%0,%1,%2,%3};" \
        : "+f"((d)[0]),"+f"((d)[1]),"+f"((d)[2]),"+f"((d)[3]) \
        : "r"((a)[0]),"r"((a)[1]),"r"((a)[2]),"r"((a)[3]),"r"(b0v),"r"(b1v))

__device__ __forceinline__ void split_bf16(float v, __nv_bfloat16& h, __nv_bfloat16& l) {
    h = __float2bfloat16(v);
    l = __float2bfloat16(v - __bfloat162float(h));
}

// ---------------- epilogue helper ----------------
// OMODE: 0 fp32 ; 1 bf16 hi/lo pair ; 2 bf16 single
template<int EPI, int OMODE>
__device__ __forceinline__ void epi2(int r, int c, float v0, float v1, int N,
    const float* __restrict__ bias, const float* __restrict__ add,
    float* __restrict__ outf, __nv_bfloat16* __restrict__ oh, __nv_bfloat16* __restrict__ ol)
{
    size_t go = (size_t)r*N + c;
    float2 bb = *(const float2*)&bias[c];
    v0 += bb.x; v1 += bb.y;
    if (EPI == 3) { float2 aa = *(const float2*)&add[go]; v0 += aa.x; v1 += aa.y; }
    if (EPI == 1) {
        v0 = 1.0f/(1.0f + expf(-v0))*0.099f + 0.001f;
        v1 = 1.0f/(1.0f + expf(-v1))*0.099f + 0.001f;
    }
    if (EPI == 2) {
        v0 = 0.5f*v0*(1.0f + erff(v0*0.70710678118654752f));
        v1 = 0.5f*v1*(1.0f + erff(v1*0.70710678118654752f));
    }
    if (OMODE == 1) {
        __nv_bfloat16 h0,l0,h1,l1;
        split_bf16(v0,h0,l0); split_bf16(v1,h1,l1);
        *(__nv_bfloat162*)&oh[go] = __nv_bfloat162{h0,h1};
        *(__nv_bfloat162*)&ol[go] = __nv_bfloat162{l0,l1};
    } else if (OMODE == 2) {
        *(__nv_bfloat162*)&oh[go] =
            __nv_bfloat162{__float2bfloat16(v0), __float2bfloat16(v1)};
    } else {
        float2 o; o.x = v0; o.y = v1;
        *(float2*)&outf[go] = o;
    }
}

// ---------------- bf16 split HMMA GEMM (3-term), 512 threads ----------------
template<int EPI, int OMODE>
__global__ __launch_bounds__(512, 1)
void hgemm(const __nv_bfloat16* __restrict__ Ah, const __nv_bfloat16* __restrict__ Al,
           const __nv_bfloat16* __restrict__ Bh, const __nv_bfloat16* __restrict__ Bl,
           int K, int N,
           const float* __restrict__ bias, const float* __restrict__ add,
           float* __restrict__ outf,
           __nv_bfloat16* __restrict__ oh, __nv_bfloat16* __restrict__ ol)
{
    extern __shared__ char sm[];
    unsigned sbase = s2u(sm);
    int tid = threadIdx.x, lane = tid & 31, wid = tid >> 5;
    int wm = wid & 3, wn = wid >> 2;             // 4 x 4 warps; warp tile 32 x 64
    int crow = blockIdx.x * BM, ccol = blockIdx.y * BN;

    // loaders: A (256 row-splits) by tid<256 ; B (512 row-splits) by all
    bool aact = tid < 256;
    int arow = tid & 127, asp = (tid >> 7) & 1;
    const __nv_bfloat16* Asrc = (asp ? Al : Ah) + (size_t)(crow + arow)*K;
    unsigned adst = sbase + asp*A_SPLIT + arow*ROWB;
    int brow = tid & 255, bsp = tid >> 8;
    const __nv_bfloat16* Bsrc = (bsp ? Bl : Bh) + (size_t)(ccol + brow)*K;
    unsigned bdst = sbase + A_BOTH + bsp*B_SPLIT + brow*ROWB;

    float acc[2][8][4];
    #pragma unroll
    for (int i = 0; i < 2; i++)
        #pragma unroll
        for (int j = 0; j < 8; j++)
            #pragma unroll
            for (int q = 0; q < 4; q++) acc[i][j][q] = 0.f;

    const int nk = K / BK;

    #pragma unroll
    for (int st = 0; st < NSTAGE-1; st++) {
        unsigned so = st*STAGE_B;
        #pragma unroll
        for (int c = 0; c < 4; c++) {
            if (aact) cp16(adst + so + c*16, Asrc + st*BK + c*8);
            cp16(bdst + so + c*16, Bsrc + st*BK + c*8);
        }
        CP_COMMIT();
    }

    int rrow = lane & 15, rhalf = lane >> 4;

    for (int i = 0; i < nk; i++) {
        CP_WAIT1();
        __syncthreads();

        int j = i + NSTAGE - 1;
        if (j < nk) {
            unsigned so = (j % NSTAGE)*STAGE_B;
            #pragma unroll
            for (int c = 0; c < 4; c++) {
                if (aact) cp16(adst + so + c*16, Asrc + j*BK + c*8);
                cp16(bdst + so + c*16, Bsrc + j*BK + c*8);
            }
        }
        CP_COMMIT();

        unsigned aST = sbase + (i % NSTAGE)*STAGE_B;
        unsigned bST = aST + A_BOTH;

        #pragma unroll
        for (int ks = 0; ks < 2; ks++) {
            int koff = ks*16;
            unsigned ah[2][4], al_[2][4];
            #pragma unroll
            for (int mt = 0; mt < 2; mt++) {
                unsigned base = aST + (unsigned)(wm*32 + mt*16 + rrow)*ROWB
                              + (unsigned)(koff + rhalf*8)*2;
                LDSM4(ah[mt], base);
                LDSM4(al_[mt], base + A_SPLIT);
            }
            #pragma unroll
            for (int p = 0; p < 4; p++) {
                unsigned base = bST + (unsigned)(wn*64 + p*16 + rrow)*ROWB
                              + (unsigned)(koff + rhalf*8)*2;
                unsigned th[4], tl[4];
                LDSM4(th, base);
                LDSM4(tl, base + B_SPLIT);
                #pragma unroll
                for (int mt = 0; mt < 2; mt++) {
                    MMA4(acc[mt][2*p],   ah[mt],  th[0], th[2]);
                    MMA4(acc[mt][2*p+1], ah[mt],  th[1], th[3]);
                    MMA4(acc[mt][2*p],   ah[mt],  tl[0], tl[2]);
                    MMA4(acc[mt][2*p+1], ah[mt],  tl[1], tl[3]);
                    MMA4(acc[mt][2*p],   al_[mt], th[0], th[2]);
                    MMA4(acc[mt][2*p+1], al_[mt], th[1], th[3]);
                }
            }
        }
    }

    #pragma unroll
    for (int mt = 0; mt < 2; mt++) {
        int r0 = crow + wm*32 + mt*16 + (lane >> 2);
        #pragma unroll
        for (int nt = 0; nt < 8; nt++) {
            int c = ccol + wn*64 + nt*8 + 2*(lane & 3);
            epi2<EPI,OMODE>(r0,     c, acc[mt][nt][0], acc[mt][nt][1], N, bias, add, outf, oh, ol);
            epi2<EPI,OMODE>(r0 + 8, c, acc[mt][nt][2], acc[mt][nt][3], N, bias, add, outf, oh, ol);
        }
    }
}

// ---------------- fp8 e4m3 GEMM: CTA 128x128, 2 CTA/SM ----------------
template<int EPI, int OMODE>
__global__ __launch_bounds__(256, 2)
void fgemm(const __nv_fp8_e4m3* __restrict__ A8, const __nv_fp8_e4m3* __restrict__ B8,
           int K, int N, const float* __restrict__ bias,
           float* __restrict__ outf, __nv_bfloat16* __restrict__ oh)
{
    extern __shared__ char sm[];
    unsigned sbase = s2u(sm);
    int tid = threadIdx.x, lane = tid & 31, wid = tid >> 5;
    int wm = wid & 1, wn = wid >> 1;
    int crow = blockIdx.x * BM, ccol = blockIdx.y * FN;

    int r2 = tid >> 1, hf = tid & 1;
    const char* Asrc = (const char*)(A8 + (size_t)(crow + r2)*K) + hf*64;
    const char* Bsrc = (const char*)(B8 + (size_t)(ccol + r2)*K) + hf*64;
    unsigned adst = sbase + r2*FROWB + hf*64;
    unsigned bdst = sbase + F_A + r2*FROWB + hf*64;

    float acc[4][4][4];
    #pragma unroll
    for (int i = 0; i < 4; i++)
        #pragma unroll
        for (int j = 0; j < 4; j++)
            #pragma unroll
            for (int q = 0; q < 4; q++) acc[i][j][q] = 0.f;

    const int nk = K / FBK;

    #pragma unroll
    for (int st = 0; st < NSTAGE-1; st++) {
        unsigned so = st*F_STAGE;
        #pragma unroll
        for (int c = 0; c < 4; c++) {
            cp16(adst + so + c*16, Asrc + st*FBK + c*16);
            cp16(bdst + so + c*16, Bsrc + st*FBK + c*16);
        }
        CP_COMMIT();
    }

    int rrow = lane & 15, rhalf = lane >> 4;

    for (int i = 0; i < nk; i++) {
        CP_WAIT1();
        __syncthreads();

        int j = i + NSTAGE - 1;
        if (j < nk) {
            unsigned so = (j % NSTAGE)*F_STAGE;
            #pragma unroll
            for (int c = 0; c < 4; c++) {
                cp16(adst + so + c*16, Asrc + j*FBK + c*16);
                cp16(bdst + so + c*16, Bsrc + j*FBK + c*16);
            }
        }
        CP_COMMIT();

        unsigned aST = sbase + (i % NSTAGE)*F_STAGE;
        unsigned bST = aST + F_A;

        #pragma unroll
        for (int ks = 0; ks < 4; ks++) {
            int koff = ks*32;
            unsigned av[4][4];
            #pragma unroll
            for (int mt = 0; mt < 4; mt++) {
                unsigned base = aST + (unsigned)(wm*64 + mt*16 + rrow)*FROWB
                              + (unsigned)(koff + rhalf*16);
                LDSM4(av[mt], base);
            }
            #pragma unroll
            for (int p = 0; p < 2; p++) {
                unsigned base = bST + (unsigned)(wn*32 + p*16 + rrow)*FROWB
                              + (unsigned)(koff + rhalf*16);
                unsigned tb[4];
                LDSM4(tb, base);
                #pragma unroll
                for (int mt = 0; mt < 4; mt++) {
                    MMA8(acc[mt][2*p],   av[mt], tb[0], tb[2]);
                    MMA8(acc[mt][2*p+1], av[mt], tb[1], tb[3]);
                }
            }
        }
    }

    #pragma unroll
    for (int mt = 0; mt < 4; mt++) {
        int r0 = crow + wm*64 + mt*16 + (lane >> 2);
        #pragma unroll
        for (int nt = 0; nt < 4; nt++) {
            int c = ccol + wn*32 + nt*8 + 2*(lane & 3);
            epi2<EPI,OMODE>(r0,     c, acc[mt][nt][0], acc[mt][nt][1], N, bias, nullptr, outf, oh, nullptr);
            epi2<EPI,OMODE>(r0 + 8, c, acc[mt][nt][2], acc[mt][nt][3], N, bias, nullptr, outf, oh, nullptr);
        }
    }
}

// ---------------- weight transpose kernels (vectorized stores) ----------------
__global__ __launch_bounds__(256)
void wtrans(const float* __restrict__ W, __nv_bfloat16* __restrict__ hi,
            __nv_bfloat16* __restrict__ lo, int K, int N)
{
    __shared__ float t[32][33];
    int n0 = blockIdx.x*32, k0 = blockIdx.y*32;
    int tx = threadIdx.x, ty = threadIdx.y;
    #pragma unroll
    for (int i = 0; i < 4; i++)
        t[ty + i*8][tx] = W[(size_t)(k0 + ty + i*8)*N + n0 + tx];
    __syncthreads();
    int flat = ty*32 + tx;
    int nl = flat >> 3, k4 = (flat & 7)*4;
    __nv_bfloat16 h[4], l[4];
    #pragma unroll
    for (int j = 0; j < 4; j++) split_bf16(t[k4+j][nl], h[j], l[j]);
    size_t o = (size_t)(n0 + nl)*K + k0 + k4;
    uint2 ph, pl;
    ph.x = ((unsigned)__bfloat16_as_ushort(h[1]) << 16) | __bfloat16_as_ushort(h[0]);
    ph.y = ((unsigned)__bfloat16_as_ushort(h[3]) << 16) | __bfloat16_as_ushort(h[2]);
    pl.x = ((unsigned)__bfloat16_as_ushort(l[1]) << 16) | __bfloat16_as_ushort(l[0]);
    pl.y = ((unsigned)__bfloat16_as_ushort(l[3]) << 16) | __bfloat16_as_ushort(l[2]);
    *(uint2*)&hi[o] = ph;
    *(uint2*)&lo[o] = pl;
}
__global__ __launch_bounds__(256)
void wtrans8(const float* __restrict__ W, __nv_fp8_e4m3* __restrict__ o8, int K, int N)
{
    __shared__ float t[32][33];
    int n0 = blockIdx.x*32, k0 = blockIdx.y*32;
    int tx = threadIdx.x, ty = threadIdx.y;
    #pragma unroll
    for (int i = 0; i < 4; i++)
        t[ty + i*8][tx] = W[(size_t)(k0 + ty + i*8)*N + n0 + tx];
    __syncthreads();
    int flat = ty*32 + tx;
    int nl = flat >> 3, k4 = (flat & 7)*4;
    unsigned pk = 0;
    #pragma unroll
    for (int j = 0; j < 4; j++) {
        __nv_fp8_e4m3 v(t[k4+j][nl]);
        pk |= (unsigned)(*(unsigned char*)&v) << (j*8);
    }
    *(unsigned*)&o8[(size_t)(n0 + nl)*K + k0 + k4] = pk;
}

// ---------------- LayerNorm -> bf16 pair ----------------
__global__ __launch_bounds__(256)
void ln_kernel(const float* __restrict__ in, const float* __restrict__ g,
               const float* __restrict__ bcoef,
               __nv_bfloat16* __restrict__ oh, __nv_bfloat16* __restrict__ ol)
{
    int row = blockIdx.x, tid = threadIdx.x;
    float4 v = ((const float4*)(in + (size_t)row*DM))[tid];
    __shared__ float red1[8], red2[8];
    float s = v.x + v.y + v.z + v.w;
    #pragma unroll
    for (int o = 16; o > 0; o >>= 1) s += __shfl_xor_sync(0xffffffffu, s, o);
    if ((tid & 31) == 0) red1[tid >> 5] = s;
    __syncthreads();
    float tot = 0.f;
    #pragma unroll
    for (int i = 0; i < 8; i++) tot += red1[i];
    float mean = tot * (1.0f/DM);
    float dx = v.x-mean, dy = v.y-mean, dz = v.z-mean, dw = v.w-mean;
    float sq = dx*dx + dy*dy + dz*dz + dw*dw;
    #pragma unroll
    for (int o = 16; o > 0; o >>= 1) sq += __shfl_xor_sync(0xffffffffu, sq, o);
    if ((tid & 31) == 0) red2[tid >> 5] = sq;
    __syncthreads();
    float tot2 = 0.f;
    #pragma unroll
    for (int i = 0; i < 8; i++) tot2 += red2[i];
    float rstd = rsqrtf(tot2*(1.0f/DM) + 1e-5f);
    float4 gg = ((const float4*)g)[tid];
    float4 bb = ((const float4*)bcoef)[tid];
    float o0 = dx*rstd*gg.x+bb.x, o1 = dy*rstd*gg.y+bb.y;
    float o2 = dz*rstd*gg.z+bb.z, o3 = dw*rstd*gg.w+bb.w;
    __nv_bfloat16 h0,l0,h1,l1,h2,l2,h3,l3;
    split_bf16(o0,h0,l0); split_bf16(o1,h1,l1); split_bf16(o2,h2,l2); split_bf16(o3,h3,l3);
    __nv_bfloat162* ph = (__nv_bfloat162*)(oh + (size_t)row*DM);
    __nv_bfloat162* pl = (__nv_bfloat162*)(ol + (size_t)row*DM);
    ph[tid*2] = __nv_bfloat162{h0,h1}; ph[tid*2+1] = __nv_bfloat162{h2,h3};
    pl[tid*2] = __nv_bfloat162{l0,l1}; pl[tid*2+1] = __nv_bfloat162{l2,l3};
}

// ---------------- conv -> fp8 only ----------------
__global__ __launch_bounds__(256)
void conv_kernel(const float* __restrict__ xg, const float* __restrict__ cw,
                 const float* __restrict__ cb, __nv_fp8_e4m3* __restrict__ o8)
{
    int idx = blockIdx.x*blockDim.x + threadIdx.x;
    int d = idx & (DI-1);
    int token = idx >> 11;
    int t = token & (SEQ-1);
    float acc = cb[d];
    #pragma unroll
    for (int k = 0; k < 4; k++) {
        int ts = t - 3 + k;
        if (ts >= 0) acc += xg[(size_t)(token-3+k)*(2*DI) + d] * cw[d*4+k];
    }
    o8[idx] = __nv_fp8_e4m3(acc);
}

// ---------------- selective scan -> bf16 pair ----------------
__global__ __launch_bounds__(256)
void scan_kernel(const float* __restrict__ xg, const float* __restrict__ delta,
                 const __nv_bfloat16* __restrict__ Bm, const __nv_bfloat16* __restrict__ Cm,
                 const float* __restrict__ A_log, const float* __restrict__ Dp,
                 __nv_bfloat16* __restrict__ yh, __nv_bfloat16* __restrict__ yl)
{
    int tid = blockIdx.x*blockDim.x + threadIdx.x;
    int n = tid & (DS-1);
    int d = (tid >> 4) & (DI-1);
    int b = tid >> 15;
    float Aneg = -expf(A_log[d*DS + n]);
    float Dval = Dp[d];
    float h = 0.f;
    int base_tok = b*SEQ;
    for (int t = 0; t < SEQ; ++t) {
        int token = base_tok + t;
        float dv = delta[(size_t)token*DI + d];
        float xp = xg[(size_t)token*(2*DI) + d];
        float bm = __bfloat162float(Bm[(size_t)token*(DI*DS) + d*DS + n]);
        float cm = __bfloat162float(Cm[(size_t)token*(DI*DS) + d*DS + n]);
        float a = __expf(dv*Aneg);
        h = a*h + (dv*bm)*xp;
        float yv = cm*h;
        yv += __shfl_xor_sync(0xffffffffu, yv, 1);
        yv += __shfl_xor_sync(0xffffffffu, yv, 2);
        yv += __shfl_xor_sync(0xffffffffu, yv, 4);
        yv += __shfl_xor_sync(0xffffffffu, yv, 8);
        if (n == 0) {
            float g = xg[(size_t)token*(2*DI) + DI + d];
            float sg = g / (1.0f + __expf(-g));
            float val = (yv + Dval*xp)*sg;
            __nv_bfloat16 hh, ll; split_bf16(val, hh, ll);
            yh[(size_t)token*DI + d] = hh;
            yl[(size_t)token*DI + d] = ll;
        }
    }
}

// ---------------- host ----------------
template<int EPI, int OMODE>
static void launch_hgemm(const __nv_bfloat16* Ah, const __nv_bfloat16* Al,
                         const __nv_bfloat16* Bh, const __nv_bfloat16* Bl,
                         int K, int N, const float* bias, const float* add,
                         float* outf, __nv_bfloat16* oh, __nv_bfloat16* ol)
{
    cudaFuncSetAttribute(hgemm<EPI,OMODE>, cudaFuncAttributeMaxDynamicSharedMemorySize, SMEM_B);
    hgemm<EPI,OMODE><<<dim3(MTOK/BM, N/BN), 512, SMEM_B>>>(Ah, Al, Bh, Bl, K, N,
                                                            bias, add, outf, oh, ol);
}
template<int EPI, int OMODE>
static void launch_fgemm(const __nv_fp8_e4m3* A8, const __nv_fp8_e4m3* B8,
                         int K, int N, const float* bias,
                         float* outf, __nv_bfloat16* oh)
{
    cudaFuncSetAttribute(fgemm<EPI,OMODE>, cudaFuncAttributeMaxDynamicSharedMemorySize, F_SMEM);
    fgemm<EPI,OMODE><<<dim3(MTOK/BM, N/FN), 256, F_SMEM>>>(A8, B8, K, N, bias, outf, oh);
}

extern "C" void kernel_launch(void* const* d_in, const int* in_sizes, int n_in,
                              void* d_out, int out_size)
{
    const float* x      = (const float*)d_in[0];
    const float* ln1_g  = (const float*)d_in[1];
    const float* ln1_b  = (const float*)d_in[2];
    const float* W_in   = (const float*)d_in[3];
    const float* b_in   = (const float*)d_in[4];
    const float* conv_w = (const float*)d_in[5];
    const float* conv_b = (const float*)d_in[6];
    const float* A_log  = (const float*)d_in[7];
    const float* W_B    = (const float*)d_in[8];
    const float* b_B    = (const float*)d_in[9];
    const float* W_C    = (const float*)d_in[10];
    const float* b_C    = (const float*)d_in[11];
    const float* Dp     = (const float*)d_in[12];
    const float* W_dt   = (const float*)d_in[13];
    const float* b_dt   = (const float*)d_in[14];
    const float* W_out  = (const float*)d_in[15];
    const float* b_out  = (const float*)d_in[16];
    const float* ln2_g  = (const float*)d_in[17];
    const float* ln2_b  = (const float*)d_in[18];
    const float* W1     = (const float*)d_in[19];
    const float* b1     = (const float*)d_in[20];
    const float* W2     = (const float*)d_in[21];
    const float* b2     = (const float*)d_in[22];
    float* out = (float*)d_out;

    float *xg, *delta, *x2;
    cudaGetSymbolAddress((void**)&xg, g_xg);
    cudaGetSymbolAddress((void**)&delta, g_delta);
    cudaGetSymbolAddress((void**)&x2, g_x2);
    __nv_bfloat16 *Bm, *Cm;
    cudaGetSymbolAddress((void**)&Bm, g_Bm);
    cudaGetSymbolAddress((void**)&Cm, g_Cm);
    __nv_bfloat16 *xnh,*xnl,*yh,*yl,*xn2h,*xn2l,*h1h,*h1l;
    cudaGetSymbolAddress((void**)&xnh, g_xn_h);   cudaGetSymbolAddress((void**)&xnl, g_xn_l);
    cudaGetSymbolAddress((void**)&yh,  g_y_h);    cudaGetSymbolAddress((void**)&yl,  g_y_l);
    cudaGetSymbolAddress((void**)&xn2h,g_xn2_h);  cudaGetSymbolAddress((void**)&xn2l,g_xn2_l);
    cudaGetSymbolAddress((void**)&h1h, g_h1_h);   cudaGetSymbolAddress((void**)&h1l, g_h1_l);
    __nv_fp8_e4m3 *xc8, *WB8, *WC8, *Wdt8;
    cudaGetSymbolAddress((void**)&xc8, g_xc8);
    cudaGetSymbolAddress((void**)&WB8, g_WB8);
    cudaGetSymbolAddress((void**)&WC8, g_WC8);
    cudaGetSymbolAddress((void**)&Wdt8, g_Wdt8);
    __nv_bfloat16 *Winh,*Winl,*Wouth,*Woutl,*W1h,*W1l,*W2h,*W2l;
    cudaGetSymbolAddress((void**)&Winh, g_Win_h); cudaGetSymbolAddress((void**)&Winl, g_Win_l);
    cudaGetSymbolAddress((void**)&Wouth,g_Wout_h);cudaGetSymbolAddress((void**)&Woutl,g_Wout_l);
    cudaGetSymbolAddress((void**)&W1h,  g_W1_h);  cudaGetSymbolAddress((void**)&W1l,  g_W1_l);
    cudaGetSymbolAddress((void**)&W2h,  g_W2_h);  cudaGetSymbolAddress((void**)&W2l,  g_W2_l);

    dim3 tb(32, 8);
    // keep my launch index 3 = hgemm<0,0> (ncu captures it)
    wtrans <<<dim3((2*DI)/32, DM/32),  tb>>>(W_in, Winh, Winl, DM, 2*DI);            // 0
    ln_kernel<<<MTOK, 256>>>(x, ln1_g, ln1_b, xnh, xnl);                             // 1
    wtrans8<<<dim3((DI*DS)/32, DI/32), tb>>>(W_B, WB8, DI, DI*DS);                   // 2
    launch_hgemm<0,0>(xnh, xnl, Winh, Winl, DM, 2*DI, b_in, nullptr, xg, nullptr, nullptr); // 3 <- profiled
    conv_kernel<<<(MTOK*DI)/256, 256>>>(xg, conv_w, conv_b, xc8);                    // 4
    launch_fgemm<0,2>(xc8, WB8, DI, DI*DS, b_B, nullptr, Bm);                        // 5
    wtrans8<<<dim3((DI*DS)/32, DI/32), tb>>>(W_C, WC8, DI, DI*DS);                   // 6
    launch_fgemm<0,2>(xc8, WC8, DI, DI*DS, b_C, nullptr, Cm);                        // 7
    wtrans8<<<dim3(DI/32, DI/32),      tb>>>(W_dt, Wdt8, DI, DI);                    // 8
    launch_fgemm<1,0>(xc8, Wdt8, DI, DI, b_dt, delta, nullptr);                      // 9
    scan_kernel<<<256, 256>>>(xg, delta, Bm, Cm, A_log, Dp, yh, yl);                 // 10
    wtrans <<<dim3(DM/32, DI/32),      tb>>>(W_out, Wouth, Woutl, DI, DM);           // 11
    launch_hgemm<3,0>(yh, yl, Wouth, Woutl, DI, DM, b_out, x, x2, nullptr, nullptr); // 12
    ln_kernel<<<MTOK, 256>>>(x2, ln2_g, ln2_b, xn2h, xn2l);                          // 13
    wtrans <<<dim3(DFF/32, DM/32),     tb>>>(W1, W1h, W1l, DM, DFF);                 // 14
    launch_hgemm<2,1>(xn2h, xn2l, W1h, W1l, DM, DFF, b1, nullptr, nullptr, h1h, h1l);// 15
    wtrans <<<dim3(DM/32, DFF/32),     tb>>>(W2, W2h, W2l, DFF, DM);                 // 16
    launch_hgemm<3,0>(h1h, h1l, W2h, W2l, DFF, DM, b2, x2, out, nullptr, nullptr);   // 17
}